// round 6
// baseline (speedup 1.0000x reference)
#include <cuda_runtime.h>
#include <math.h>

#define NCLS 21

// ---------------- f32x2 packed helpers (Blackwell; ptxas never auto-emits) ----
__device__ __forceinline__ unsigned long long f2_fma(unsigned long long a,
                                                     unsigned long long b,
                                                     unsigned long long c) {
  unsigned long long d;
  asm("fma.rn.f32x2 %0, %1, %2, %3;" : "=l"(d) : "l"(a), "l"(b), "l"(c));
  return d;
}
__device__ __forceinline__ unsigned long long f2_add(unsigned long long a,
                                                     unsigned long long b) {
  unsigned long long d;
  asm("add.rn.f32x2 %0, %1, %2;" : "=l"(d) : "l"(a), "l"(b));
  return d;
}
__device__ __forceinline__ unsigned long long f2_bcast(float x) {
  unsigned long long d;
  asm("mov.b64 %0, {%1, %1};" : "=l"(d) : "f"(x));
  return d;
}
__device__ __forceinline__ void f2_unpack(unsigned long long v, float& lo,
                                          float& hi) {
  asm("mov.b64 {%0, %1}, %2;" : "=f"(lo), "=f"(hi) : "l"(v));
}
#define F2_NEG1 0xBF800000BF800000ULL  // (-1.0f, -1.0f)

// ---------------- scratch (static device globals; no allocation) ----------------
__device__ float g_h1[64 * 256 * 256];    // conv1 out
__device__ float g_h2[128 * 128 * 128];   // conv2 out
__device__ float g_h3[256 * 64 * 64];     // conv3 out
__device__ float g_h4[256 * 32 * 32];     // ex out
__device__ float g_c3part[2 * 256 * 64 * 64];  // conv3 split-C partials
__device__ float g_expart[4 * 256 * 32 * 32];  // ex split-C partials
__device__ float g_part[8 * 25 * 1024];   // head conv split-K partials
__device__ float g_locs[1024 * 4];
__device__ float g_confs[1024 * NCLS];
__device__ float g_scores[1024];
__device__ int g_labels[1024];
__device__ int g_order[1024];
__device__ float4 g_sbox[1024];
__device__ float g_sscore[1024];
__device__ unsigned g_validmask[32];
__device__ unsigned g_sup[1024 * 32];
__device__ unsigned g_keepmask[32];

// ---------------- 3x3 conv, stride 2, SAME padding ----------------
// JAX SAME, even input, stride 2: pad_lo=0, pad_hi=1 (out = in/2).
// 16x16 output tile, COUTS output channels per block, 256 threads.
// NCH input channels staged per sync-pair; next group's loads prefetched into
// registers while current group computes.
// Numerics: per input channel, 9-term FMA chain (wsum), Kahan fold into acc.
// Implemented in packed f32x2 (2 couts per register) — per-lane arithmetic is
// bit-identical to the proven scalar version (SIMD lanes, subtract realized as
// fma(x, -1, y): exact scale, single rounding).
template <int CIN, int WCH, int NCH, int STRIDE, int COUTS, int NCHUNK,
          bool FINAL>
__device__ __forceinline__ void conv_body(const float* __restrict__ in,
                                          const float* __restrict__ wgt,
                                          const float* __restrict__ bias,
                                          float* __restrict__ out, int Hin,
                                          int Win, int Hout, int Wout,
                                          int c_begin, int co0) {
  constexpr int TILE = 16;
  constexpr int IN_T = TILE * STRIDE + 2;
  constexpr int ROWP = IN_T + 2;
  constexpr int ELEMS = NCH * IN_T * IN_T;
  constexpr int LD = (ELEMS + 255) / 256;
  constexpr int G = WCH / NCH;
  constexpr int NW = WCH * 9 * COUTS;
  constexpr int WLD = (NW + 255) / 256;
  constexpr int NP = COUTS / 2;  // packed f32x2 accumulators

  __shared__ float s_in[NCH * IN_T * ROWP];
  __shared__ __align__(16) float s_w[NW];

  const int t = threadIdx.x;
  const int tx = t & 15, ty = t >> 4;
  const int ow0 = blockIdx.x * TILE, oh0 = blockIdx.y * TILE;
  const int HW = Hin * Win;

  // per-thread load descriptors (same for every channel group)
  int goff[LD], soff[LD];
#pragma unroll
  for (int i = 0; i < LD; ++i) {
    int idx = t + i * 256;
    int ch = idx / (IN_T * IN_T);
    int rem = idx - ch * (IN_T * IN_T);
    int r = rem / IN_T, c = rem - r * IN_T;
    int ih = oh0 * STRIDE + r, iw = ow0 * STRIDE + c;
    bool ok = (idx < ELEMS) && ((unsigned)ih < (unsigned)Hin) &&
              ((unsigned)iw < (unsigned)Win);
    goff[i] = ok ? (ch * HW + ih * Win + iw) : -1;
    soff[i] = (ch * IN_T + r) * ROWP + c;
  }

  unsigned long long acc2[NP], cmp2[NP];
#pragma unroll
  for (int i = 0; i < NP; i++) { acc2[i] = 0ull; cmp2[i] = 0ull; }

  for (int c0 = c_begin; c0 < c_begin + NCHUNK * WCH; c0 += WCH) {
    __syncthreads();  // previous chunk compute done; smem reusable
    // stage weight chunk: s_w[(ccg*9+k)*COUTS + co]
#pragma unroll
    for (int i = 0; i < WLD; ++i) {
      int idx = t + i * 256;
      if (idx < NW) {
        int co = idx / (WCH * 9);
        int rem = idx - co * (WCH * 9);
        int ccg = rem / 9, k = rem - ccg * 9;
        s_w[(ccg * 9 + k) * COUTS + co] =
            wgt[(size_t)(co0 + co) * CIN * 9 + (size_t)(c0 + ccg) * 9 + k];
      }
    }
    // prefetch group 0
    float rbuf[LD];
    {
      const float* inb = in + (size_t)c0 * HW;
#pragma unroll
      for (int i = 0; i < LD; ++i)
        rbuf[i] = (goff[i] >= 0) ? inb[goff[i]] : 0.f;
    }
    for (int g = 0; g < G; ++g) {
      __syncthreads();  // compute(g-1) done before overwriting s_in
#pragma unroll
      for (int i = 0; i < LD; ++i)
        if (t + i * 256 < ELEMS) s_in[soff[i]] = rbuf[i];
      if (g + 1 < G) {  // prefetch next group (overlaps with compute below)
        const float* inb = in + (size_t)(c0 + (g + 1) * NCH) * HW;
#pragma unroll
        for (int i = 0; i < LD; ++i)
          rbuf[i] = (goff[i] >= 0) ? inb[goff[i]] : 0.f;
      }
      __syncthreads();  // staging (weights + input) visible

#pragma unroll
      for (int cc = 0; cc < NCH; ++cc) {
        unsigned long long wsum2[NP];
#pragma unroll
        for (int i = 0; i < NP; ++i) wsum2[i] = 0ull;
#pragma unroll
        for (int kh = 0; kh < 3; ++kh)
#pragma unroll
          for (int kw = 0; kw < 3; ++kw) {
            float xv = s_in[(cc * IN_T + ty * STRIDE + kh) * ROWP +
                            tx * STRIDE + kw];
            unsigned long long xv2 = f2_bcast(xv);
            const ulonglong2* wp = (const ulonglong2*)&s_w[((g * NCH + cc) * 9 +
                                                            kh * 3 + kw) *
                                                           COUTS];
#pragma unroll
            for (int q = 0; q < COUTS / 4; ++q) {
              ulonglong2 w2 = wp[q];
              wsum2[q * 2 + 0] = f2_fma(xv2, w2.x, wsum2[q * 2 + 0]);
              wsum2[q * 2 + 1] = f2_fma(xv2, w2.y, wsum2[q * 2 + 1]);
            }
          }
        // Kahan fold per channel (per-lane identical to scalar version)
#pragma unroll
        for (int i = 0; i < NP; ++i) {
          unsigned long long y = f2_fma(cmp2[i], F2_NEG1, wsum2[i]);
          unsigned long long tt = f2_add(acc2[i], y);
          unsigned long long t2 = f2_fma(acc2[i], F2_NEG1, tt);
          cmp2[i] = f2_fma(y, F2_NEG1, t2);
          acc2[i] = tt;
        }
      }
    }
  }

  const int oh = oh0 + ty, ow = ow0 + tx;
#pragma unroll
  for (int i = 0; i < NP; i++) {
    float lo, hi;
    f2_unpack(acc2[i], lo, hi);
    if (FINAL) {
      lo = fmaxf(lo + bias[co0 + 2 * i], 0.f);
      hi = fmaxf(hi + bias[co0 + 2 * i + 1], 0.f);
    }
    out[(size_t)(co0 + 2 * i) * Hout * Wout + (size_t)oh * Wout + ow] = lo;
    out[(size_t)(co0 + 2 * i + 1) * Hout * Wout + (size_t)oh * Wout + ow] = hi;
  }
}

__global__ void __launch_bounds__(256) k_conv1(const float* x, const float* w,
                                               const float* b) {
  conv_body<3, 3, 3, 2, 4, 1, true>(x, w, b, g_h1, 512, 512, 256, 256, 0,
                                    blockIdx.z * 4);
}
__global__ void __launch_bounds__(256) k_conv2(const float* w, const float* b) {
  conv_body<64, 64, 4, 2, 8, 1, true>(g_h1, w, b, g_h2, 256, 256, 128, 128, 0,
                                      blockIdx.z * 8);
}
// conv3: split-C x2. z = split*32 + co_blk.
__global__ void __launch_bounds__(256) k_conv3(const float* w) {
  const int split = blockIdx.z >> 5;
  const int co0 = (blockIdx.z & 31) * 8;
  conv_body<128, 64, 4, 2, 8, 1, false>(
      g_h2, w, nullptr, g_c3part + (size_t)split * 256 * 64 * 64, 128, 128, 64,
      64, split * 64, co0);
}
__global__ void k_comb3(const float* __restrict__ b) {
  const int i = blockIdx.x * 256 + threadIdx.x;  // 0 .. 256*64*64-1
  const int co = i >> 12;
  double s = (double)g_c3part[i] + (double)g_c3part[256 * 64 * 64 + i];
  float v = (float)(s + (double)b[co]);
  g_h3[i] = fmaxf(v, 0.f);
}
// ex: split-C x4. z = split*32 + co_blk.
__global__ void __launch_bounds__(256) k_ex(const float* w) {
  const int split = blockIdx.z >> 5;
  const int co0 = (blockIdx.z & 31) * 8;
  conv_body<256, 64, 4, 2, 8, 1, false>(
      g_h3, w, nullptr, g_expart + (size_t)split * 256 * 32 * 32, 64, 64, 32,
      32, split * 64, co0);
}
__global__ void k_combex(const float* __restrict__ b) {
  const int i = blockIdx.x * 256 + threadIdx.x;  // 0 .. 256*32*32-1
  const int co = i >> 10;
  double s = 0.0;
#pragma unroll
  for (int sp = 0; sp < 4; ++sp)
    s += (double)g_expart[(size_t)sp * 256 * 32 * 32 + i];
  float v = (float)(s + (double)b[co]);
  g_h4[i] = fmaxf(v, 0.f);
}

// ---------------- head convs (reg 4ch + cls 21ch), stride1 pad1, split-K -------
// grid: (split 0..7, cout 0..24). Block: 32 input channels, all 1024 px.
__global__ void __launch_bounds__(256) k_head(const float* __restrict__ reg_w,
                                              const float* __restrict__ cls_w) {
  constexpr int IN_T = 34, ROWP = 35, NCH = 4;
  constexpr int ELEMS = NCH * IN_T * IN_T;
  constexpr int LD = (ELEMS + 255) / 256;
  const int split = blockIdx.x, co = blockIdx.y;
  const float* w = (co < 4) ? (reg_w + (size_t)co * 256 * 9)
                            : (cls_w + (size_t)(co - 4) * 256 * 9);
  __shared__ float s_in[NCH * IN_T * ROWP];
  __shared__ float s_w[32 * 9];
  const int t = threadIdx.x;

  int goff[LD], soff[LD];
#pragma unroll
  for (int i = 0; i < LD; ++i) {
    int idx = t + i * 256;
    int ch = idx / (IN_T * IN_T);
    int rem = idx - ch * (IN_T * IN_T);
    int r = rem / IN_T, c = rem - r * IN_T;
    int ih = r - 1, iw = c - 1;
    bool ok = (idx < ELEMS) && ((unsigned)ih < 32u) && ((unsigned)iw < 32u);
    goff[i] = ok ? (ch * 1024 + ih * 32 + iw) : -1;
    soff[i] = (ch * IN_T + r) * ROWP + c;
  }
  for (int idx = t; idx < 32 * 9; idx += 256)
    s_w[idx] = w[(size_t)(split * 32 + idx / 9) * 9 + (idx % 9)];

  float acc[4] = {0.f, 0.f, 0.f, 0.f};
  float cmp[4] = {0.f, 0.f, 0.f, 0.f};

  float rbuf[LD];
  {
    const float* inb = g_h4 + (size_t)split * 32 * 1024;
#pragma unroll
    for (int i = 0; i < LD; ++i) rbuf[i] = (goff[i] >= 0) ? inb[goff[i]] : 0.f;
  }
  for (int g = 0; g < 8; ++g) {
    __syncthreads();
#pragma unroll
    for (int i = 0; i < LD; ++i)
      if (t + i * 256 < ELEMS) s_in[soff[i]] = rbuf[i];
    if (g + 1 < 8) {
      const float* inb = g_h4 + (size_t)(split * 32 + (g + 1) * NCH) * 1024;
#pragma unroll
      for (int i = 0; i < LD; ++i)
        rbuf[i] = (goff[i] >= 0) ? inb[goff[i]] : 0.f;
    }
    __syncthreads();

#pragma unroll
    for (int cc = 0; cc < NCH; ++cc) {
      float wr[9];
#pragma unroll
      for (int k = 0; k < 9; ++k) wr[k] = s_w[(g * NCH + cc) * 9 + k];
#pragma unroll
      for (int px = 0; px < 4; ++px) {
        int p = t + px * 256;
        int oh = p >> 5, ow = p & 31;
        float a = 0.f;
#pragma unroll
        for (int kh = 0; kh < 3; ++kh)
#pragma unroll
          for (int kw = 0; kw < 3; ++kw)
            a = fmaf(s_in[(cc * IN_T + oh + kh) * ROWP + ow + kw],
                     wr[kh * 3 + kw], a);
        float y = a - cmp[px];
        float tt = acc[px] + y;
        cmp[px] = (tt - acc[px]) - y;
        acc[px] = tt;
      }
    }
  }
#pragma unroll
  for (int px = 0; px < 4; ++px)
    g_part[(size_t)(split * 25 + co) * 1024 + t + px * 256] = acc[px];
}

// ---------------- reduce partials (double) + transpose + softmax (double) ------
__global__ void k_prep(const float* __restrict__ reg_b,
                       const float* __restrict__ cls_b) {
  const int a = blockIdx.x * 256 + threadIdx.x;  // anchor 0..1023
#pragma unroll
  for (int j = 0; j < 4; ++j) {
    double s = 0.0;
    for (int sp = 0; sp < 8; ++sp)
      s += (double)g_part[(size_t)(sp * 25 + j) * 1024 + a];
    g_locs[a * 4 + j] = (float)(s + (double)reg_b[j]);
  }
  float conf[NCLS];
  for (int c = 0; c < NCLS; ++c) {
    double s = 0.0;
    for (int sp = 0; sp < 8; ++sp)
      s += (double)g_part[(size_t)(sp * 25 + 4 + c) * 1024 + a];
    conf[c] = (float)(s + (double)cls_b[c]);
    g_confs[a * NCLS + c] = conf[c];
  }
  float m = conf[0];
  int lab = 0;
  for (int c = 1; c < NCLS; ++c)
    if (conf[c] > m) { m = conf[c]; lab = c; }
  double sum = 0.0;
  for (int c = 0; c < NCLS; ++c) sum += exp((double)conf[c] - (double)m);
  g_scores[a] = (float)(1.0 / sum);  // max softmax prob
  g_labels[a] = lab;
}

// ---------------- stable bitonic sort by descending score ----------------
__global__ void k_sort() {
  __shared__ float s[1024];
  __shared__ int si[1024];
  const int t = threadIdx.x;
  s[t] = g_scores[t];
  si[t] = t;
  __syncthreads();
  for (int k = 2; k <= 1024; k <<= 1) {
    for (int j = k >> 1; j > 0; j >>= 1) {
      int ixj = t ^ j;
      if (ixj > t) {
        float sa = s[t], sb = s[ixj];
        int ia = si[t], ib = si[ixj];
        bool aFirst = (sa > sb) || (sa == sb && ia < ib);  // stable desc
        bool dirUp = ((t & k) == 0);
        if (dirUp ? !aFirst : aFirst) {
          s[t] = sb; s[ixj] = sa;
          si[t] = ib; si[ixj] = ia;
        }
      }
      __syncthreads();
    }
  }
  const int idx = si[t];
  g_order[t] = idx;
  g_sscore[t] = s[t];
  g_sbox[t] = make_float4(g_locs[idx * 4 + 0], g_locs[idx * 4 + 1],
                          g_locs[idx * 4 + 2], g_locs[idx * 4 + 3]);
  unsigned vb = __ballot_sync(0xffffffffu, s[t] > 0.04f);
  if ((t & 31) == 0) g_validmask[t >> 5] = vb;
}

// ---------------- pairwise IoU suppression bitmask (double precision) ----------
__global__ void k_iou() {
  const int i = blockIdx.x, j = threadIdx.x;
  float4 bi = g_sbox[i];
  float4 bj = g_sbox[j];
  double ai = ((double)bi.z - (double)bi.x) * ((double)bi.w - (double)bi.y);
  double aj = ((double)bj.z - (double)bj.x) * ((double)bj.w - (double)bj.y);
  double ltx = fmax((double)bi.x, (double)bj.x);
  double lty = fmax((double)bi.y, (double)bj.y);
  double rbx = fmin((double)bi.z, (double)bj.z);
  double rby = fmin((double)bi.w, (double)bj.w);
  double inter = fmax(rbx - ltx, 0.0) * fmax(rby - lty, 0.0);
  double uni = ai + aj - inter;
  double iou = inter / (uni + 1e-9);
  unsigned m = __ballot_sync(0xffffffffu, iou > 0.5);
  if ((j & 31) == 0) g_sup[i * 32 + (j >> 5)] = m;
}

// ---------------- sequential greedy NMS on bitmask, single warp ----------------
__global__ void k_nms() {
  const int lane = threadIdx.x;  // 32 threads
  unsigned kw = 0;
  const unsigned validw = g_validmask[lane];
  const int CH = 8;
  unsigned buf[CH], nbuf[CH];
#pragma unroll
  for (int q = 0; q < CH; ++q) buf[q] = g_sup[q * 32 + lane];
  for (int c = 0; c < 1024 / CH; ++c) {
    if (c + 1 < 1024 / CH) {
#pragma unroll
      for (int q = 0; q < CH; ++q)
        nbuf[q] = g_sup[((c + 1) * CH + q) * 32 + lane];
    }
#pragma unroll
    for (int q = 0; q < CH; ++q) {
      int i = c * CH + q;
      bool sup = __any_sync(0xffffffffu, (buf[q] & kw) != 0u);
      unsigned vbit =
          (__shfl_sync(0xffffffffu, validw, i >> 5) >> (i & 31)) & 1u;
      if (!sup && vbit && lane == (i >> 5)) kw |= (1u << (i & 31));
    }
#pragma unroll
    for (int q = 0; q < CH; ++q) buf[q] = nbuf[q];
  }
  g_keepmask[lane] = kw;
}

// ---------------- masked gather to output ----------------
// layout (float32): boxes[1024*4] | labels[1024] | scores[1024] | confs[1024*21]
__global__ void k_out(float* __restrict__ out) {
  const int p = blockIdx.x * 256 + threadIdx.x;  // 0..1023
  const bool keep = (g_keepmask[p >> 5] >> (p & 31)) & 1u;
  const int idx = g_order[p];
  float4 b = g_sbox[p];
  out[p * 4 + 0] = keep ? b.x : -1.0f;
  out[p * 4 + 1] = keep ? b.y : -1.0f;
  out[p * 4 + 2] = keep ? b.z : -1.0f;
  out[p * 4 + 3] = keep ? b.w : -1.0f;
  out[4096 + p] = keep ? (float)g_labels[idx] : 0.0f;
  out[5120 + p] = keep ? g_sscore[p] : -1.0f;
  for (int c = 0; c < NCLS; ++c)
    out[6144 + p * NCLS + c] = keep ? g_confs[idx * NCLS + c] : -1.0f;
}

// ---------------- launch ----------------
extern "C" void kernel_launch(void* const* d_in, const int* in_sizes, int n_in,
                              void* d_out, int out_size) {
  const float* x = (const float*)d_in[0];
  const float* bb_w1 = (const float*)d_in[1];
  const float* bb_b1 = (const float*)d_in[2];
  const float* bb_w2 = (const float*)d_in[3];
  const float* bb_b2 = (const float*)d_in[4];
  const float* bb_w3 = (const float*)d_in[5];
  const float* bb_b3 = (const float*)d_in[6];
  const float* ex_w = (const float*)d_in[7];
  const float* ex_b = (const float*)d_in[8];
  const float* reg_w = (const float*)d_in[9];
  const float* reg_b = (const float*)d_in[10];
  const float* cls_w = (const float*)d_in[11];
  const float* cls_b = (const float*)d_in[12];

  // only batch element 7 affects the output
  const float* x7 = x + (size_t)7 * 3 * 512 * 512;

  k_conv1<<<dim3(16, 16, 16), 256>>>(x7, bb_w1, bb_b1);
  k_conv2<<<dim3(8, 8, 16), 256>>>(bb_w2, bb_b2);
  k_conv3<<<dim3(4, 4, 64), 256>>>(bb_w3);
  k_comb3<<<4096, 256>>>(bb_b3);
  k_ex<<<dim3(2, 2, 128), 256>>>(ex_w);
  k_combex<<<1024, 256>>>(ex_b);
  k_head<<<dim3(8, 25), 256>>>(reg_w, cls_w);
  k_prep<<<4, 256>>>(reg_b, cls_b);
  k_sort<<<1, 1024>>>();
  k_iou<<<1024, 1024>>>();
  k_nms<<<1, 32>>>();
  k_out<<<4, 256>>>((float*)d_out);
}

// round 7
// speedup vs baseline: 1.1071x; 1.1071x over previous
#include <cuda_runtime.h>
#include <math.h>

#define NCLS 21

// ---------------- f32x2 packed helpers (Blackwell; ptxas never auto-emits) ----
__device__ __forceinline__ unsigned long long f2_fma(unsigned long long a,
                                                     unsigned long long b,
                                                     unsigned long long c) {
  unsigned long long d;
  asm("fma.rn.f32x2 %0, %1, %2, %3;" : "=l"(d) : "l"(a), "l"(b), "l"(c));
  return d;
}
__device__ __forceinline__ unsigned long long f2_add(unsigned long long a,
                                                     unsigned long long b) {
  unsigned long long d;
  asm("add.rn.f32x2 %0, %1, %2;" : "=l"(d) : "l"(a), "l"(b));
  return d;
}
__device__ __forceinline__ unsigned long long f2_bcast(float x) {
  unsigned long long d;
  asm("mov.b64 %0, {%1, %1};" : "=l"(d) : "f"(x));
  return d;
}
__device__ __forceinline__ void f2_unpack(unsigned long long v, float& lo,
                                          float& hi) {
  asm("mov.b64 {%0, %1}, %2;" : "=f"(lo), "=f"(hi) : "l"(v));
}
#define F2_NEG1 0xBF800000BF800000ULL  // (-1.0f, -1.0f)

// ---------------- scratch (static device globals; no allocation) ----------------
__device__ float g_h1[64 * 256 * 256];    // conv1 out
__device__ float g_h2[128 * 128 * 128];   // conv2 out
__device__ float g_h3[256 * 64 * 64];     // conv3 out
__device__ float g_h4[256 * 32 * 32];     // ex out
__device__ float g_c3part[2 * 256 * 64 * 64];  // conv3 split-C partials
__device__ float g_expart[4 * 256 * 32 * 32];  // ex split-C partials
__device__ float g_part[8 * 25 * 1024];   // head conv split-K partials
__device__ float g_locs[1024 * 4];
__device__ float g_confs[1024 * NCLS];
__device__ float g_scores[1024];
__device__ int g_labels[1024];
__device__ int g_order[1024];
__device__ float4 g_sbox[1024];
__device__ float g_sscore[1024];
__device__ unsigned g_validmask[32];
__device__ unsigned g_sup[1024 * 32];
__device__ unsigned g_keepmask[32];

// ================= conv1 (kept exactly as the R6-proven version) =============
template <int CIN, int WCH, int NCH, int STRIDE, int COUTS, int NCHUNK,
          bool FINAL>
__device__ __forceinline__ void conv_body(const float* __restrict__ in,
                                          const float* __restrict__ wgt,
                                          const float* __restrict__ bias,
                                          float* __restrict__ out, int Hin,
                                          int Win, int Hout, int Wout,
                                          int c_begin, int co0) {
  constexpr int TILE = 16;
  constexpr int IN_T = TILE * STRIDE + 2;
  constexpr int ROWP = IN_T + 2;
  constexpr int ELEMS = NCH * IN_T * IN_T;
  constexpr int LD = (ELEMS + 255) / 256;
  constexpr int G = WCH / NCH;
  constexpr int NW = WCH * 9 * COUTS;
  constexpr int WLD = (NW + 255) / 256;
  constexpr int NP = COUTS / 2;

  __shared__ float s_in[NCH * IN_T * ROWP];
  __shared__ __align__(16) float s_w[NW];

  const int t = threadIdx.x;
  const int tx = t & 15, ty = t >> 4;
  const int ow0 = blockIdx.x * TILE, oh0 = blockIdx.y * TILE;
  const int HW = Hin * Win;

  int goff[LD], soff[LD];
#pragma unroll
  for (int i = 0; i < LD; ++i) {
    int idx = t + i * 256;
    int ch = idx / (IN_T * IN_T);
    int rem = idx - ch * (IN_T * IN_T);
    int r = rem / IN_T, c = rem - r * IN_T;
    int ih = oh0 * STRIDE + r, iw = ow0 * STRIDE + c;
    bool ok = (idx < ELEMS) && ((unsigned)ih < (unsigned)Hin) &&
              ((unsigned)iw < (unsigned)Win);
    goff[i] = ok ? (ch * HW + ih * Win + iw) : -1;
    soff[i] = (ch * IN_T + r) * ROWP + c;
  }

  unsigned long long acc2[NP], cmp2[NP];
#pragma unroll
  for (int i = 0; i < NP; i++) { acc2[i] = 0ull; cmp2[i] = 0ull; }

  for (int c0 = c_begin; c0 < c_begin + NCHUNK * WCH; c0 += WCH) {
    __syncthreads();
#pragma unroll
    for (int i = 0; i < WLD; ++i) {
      int idx = t + i * 256;
      if (idx < NW) {
        int co = idx / (WCH * 9);
        int rem = idx - co * (WCH * 9);
        int ccg = rem / 9, k = rem - ccg * 9;
        s_w[(ccg * 9 + k) * COUTS + co] =
            wgt[(size_t)(co0 + co) * CIN * 9 + (size_t)(c0 + ccg) * 9 + k];
      }
    }
    float rbuf[LD];
    {
      const float* inb = in + (size_t)c0 * HW;
#pragma unroll
      for (int i = 0; i < LD; ++i)
        rbuf[i] = (goff[i] >= 0) ? inb[goff[i]] : 0.f;
    }
    for (int g = 0; g < G; ++g) {
      __syncthreads();
#pragma unroll
      for (int i = 0; i < LD; ++i)
        if (t + i * 256 < ELEMS) s_in[soff[i]] = rbuf[i];
      if (g + 1 < G) {
        const float* inb = in + (size_t)(c0 + (g + 1) * NCH) * HW;
#pragma unroll
        for (int i = 0; i < LD; ++i)
          rbuf[i] = (goff[i] >= 0) ? inb[goff[i]] : 0.f;
      }
      __syncthreads();

#pragma unroll
      for (int cc = 0; cc < NCH; ++cc) {
        unsigned long long wsum2[NP];
#pragma unroll
        for (int i = 0; i < NP; ++i) wsum2[i] = 0ull;
#pragma unroll
        for (int kh = 0; kh < 3; ++kh)
#pragma unroll
          for (int kw = 0; kw < 3; ++kw) {
            float xv = s_in[(cc * IN_T + ty * STRIDE + kh) * ROWP +
                            tx * STRIDE + kw];
            unsigned long long xv2 = f2_bcast(xv);
            const ulonglong2* wp = (const ulonglong2*)&s_w[((g * NCH + cc) * 9 +
                                                            kh * 3 + kw) *
                                                           COUTS];
#pragma unroll
            for (int q = 0; q < COUTS / 4; ++q) {
              ulonglong2 w2 = wp[q];
              wsum2[q * 2 + 0] = f2_fma(xv2, w2.x, wsum2[q * 2 + 0]);
              wsum2[q * 2 + 1] = f2_fma(xv2, w2.y, wsum2[q * 2 + 1]);
            }
          }
#pragma unroll
        for (int i = 0; i < NP; ++i) {
          unsigned long long y = f2_fma(cmp2[i], F2_NEG1, wsum2[i]);
          unsigned long long tt = f2_add(acc2[i], y);
          unsigned long long t2 = f2_fma(acc2[i], F2_NEG1, tt);
          cmp2[i] = f2_fma(y, F2_NEG1, t2);
          acc2[i] = tt;
        }
      }
    }
  }

  const int oh = oh0 + ty, ow = ow0 + tx;
#pragma unroll
  for (int i = 0; i < NP; i++) {
    float lo, hi;
    f2_unpack(acc2[i], lo, hi);
    if (FINAL) {
      lo = fmaxf(lo + bias[co0 + 2 * i], 0.f);
      hi = fmaxf(hi + bias[co0 + 2 * i + 1], 0.f);
    }
    out[(size_t)(co0 + 2 * i) * Hout * Wout + (size_t)oh * Wout + ow] = lo;
    out[(size_t)(co0 + 2 * i + 1) * Hout * Wout + (size_t)oh * Wout + ow] = hi;
  }
}

__global__ void __launch_bounds__(256) k_conv1(const float* x, const float* w,
                                               const float* b) {
  conv_body<3, 3, 3, 2, 4, 1, true>(x, w, b, g_h1, 512, 512, 256, 256, 0,
                                    blockIdx.z * 4);
}

// ============= wide conv: 32x16 tile, 2 horizontal px/thread, 8 couts ========
// stride 2, SAME (pad_lo=0, pad_hi=1). 64 input channels per call (2 chunks of
// 32), 2-channel staging groups with register prefetch. Window sums are 18-term
// f32x2 FMA chains (2 channels), Kahan-folded per group into the accumulator.
template <int CINFULL, bool FINAL>
__device__ __forceinline__ void conv_wide(const float* __restrict__ in,
                                          const float* __restrict__ wgt,
                                          const float* __restrict__ bias,
                                          float* __restrict__ out, int Hin,
                                          int Win, int Hout, int Wout,
                                          int c_begin, int co0) {
  constexpr int WCH = 32, NCH = 2;
  constexpr int IN_W = 66, IN_H = 34, ROWP = 68;
  constexpr int CHE = IN_H * IN_W;     // 2244
  constexpr int ELEMS = NCH * CHE;     // 4488
  constexpr int LD = (ELEMS + 255) / 256;  // 18
  constexpr int G = WCH / NCH;         // 16
  constexpr int NW = WCH * 9 * 8;      // 2304

  __shared__ float s_in[NCH * IN_H * ROWP];
  __shared__ __align__(16) float s_w[NW];

  const int t = threadIdx.x;
  const int tx = t & 15, ty = t >> 4;
  const int ow0 = blockIdx.x * 32, oh0 = blockIdx.y * 16;
  const int HW = Hin * Win;

  unsigned long long acc2[8], cmp2[8];
#pragma unroll
  for (int i = 0; i < 8; ++i) { acc2[i] = 0ull; cmp2[i] = 0ull; }

  float rbuf[LD];

  for (int chunk = 0; chunk < 2; ++chunk) {
    const int c0 = c_begin + chunk * WCH;
    __syncthreads();  // prev chunk compute done; smem reusable
    // stage weight chunk: s_w[(ccg*9+k)*8 + co], 2304 floats = 9/thread
#pragma unroll
    for (int i = 0; i < 9; ++i) {
      int idx = t + i * 256;
      int co = idx / (WCH * 9);
      int rem = idx - co * (WCH * 9);
      int ccg = rem / 9, k = rem - ccg * 9;
      s_w[(ccg * 9 + k) * 8 + co] =
          wgt[(size_t)(co0 + co) * CINFULL * 9 + (size_t)(c0 + ccg) * 9 + k];
    }
    // prefetch group 0
#pragma unroll
    for (int i = 0; i < LD; ++i) {
      int idx = t + i * 256;
      float v = 0.f;
      if (idx < ELEMS) {
        int ch = idx / CHE;
        int rem = idx - ch * CHE;
        int r = rem / IN_W, c = rem - r * IN_W;
        int ih = oh0 * 2 + r, iw = ow0 * 2 + c;
        if ((unsigned)ih < (unsigned)Hin && (unsigned)iw < (unsigned)Win)
          v = in[(size_t)(c0 + ch) * HW + ih * Win + iw];
      }
      rbuf[i] = v;
    }
    for (int g = 0; g < G; ++g) {
      __syncthreads();  // compute(g-1) done before overwriting s_in
#pragma unroll
      for (int i = 0; i < LD; ++i) {
        int idx = t + i * 256;
        if (idx < ELEMS) {
          int ch = idx / CHE;
          int rem = idx - ch * CHE;
          int r = rem / IN_W, c = rem - r * IN_W;
          s_in[(ch * IN_H + r) * ROWP + c] = rbuf[i];
        }
      }
      if (g + 1 < G) {  // prefetch next group; overlaps with compute below
        const int cb = c0 + (g + 1) * NCH;
#pragma unroll
        for (int i = 0; i < LD; ++i) {
          int idx = t + i * 256;
          float v = 0.f;
          if (idx < ELEMS) {
            int ch = idx / CHE;
            int rem = idx - ch * CHE;
            int r = rem / IN_W, c = rem - r * IN_W;
            int ih = oh0 * 2 + r, iw = ow0 * 2 + c;
            if ((unsigned)ih < (unsigned)Hin && (unsigned)iw < (unsigned)Win)
              v = in[(size_t)(cb + ch) * HW + ih * Win + iw];
          }
          rbuf[i] = v;
        }
      }
      __syncthreads();  // staging visible

      // 18-term window chains for both pixels (A = px0, B = px1)
      unsigned long long wsA[4] = {0ull, 0ull, 0ull, 0ull};
      unsigned long long wsB[4] = {0ull, 0ull, 0ull, 0ull};
#pragma unroll
      for (int cc = 0; cc < NCH; ++cc) {
#pragma unroll
        for (int kh = 0; kh < 3; ++kh)
#pragma unroll
          for (int kw = 0; kw < 3; ++kw) {
            const int base = (cc * IN_H + ty * 2 + kh) * ROWP + tx * 4 + kw;
            unsigned long long x0 = f2_bcast(s_in[base]);
            unsigned long long x1 = f2_bcast(s_in[base + 2]);
            const ulonglong2* wp =
                (const ulonglong2*)&s_w[((g * NCH + cc) * 9 + kh * 3 + kw) * 8];
            ulonglong2 wa = wp[0], wb = wp[1];
            wsA[0] = f2_fma(x0, wa.x, wsA[0]);
            wsA[1] = f2_fma(x0, wa.y, wsA[1]);
            wsA[2] = f2_fma(x0, wb.x, wsA[2]);
            wsA[3] = f2_fma(x0, wb.y, wsA[3]);
            wsB[0] = f2_fma(x1, wa.x, wsB[0]);
            wsB[1] = f2_fma(x1, wa.y, wsB[1]);
            wsB[2] = f2_fma(x1, wb.x, wsB[2]);
            wsB[3] = f2_fma(x1, wb.y, wsB[3]);
          }
      }
      // Kahan fold once per 2-channel group (acc2[0..3]=px0, [4..7]=px1)
#pragma unroll
      for (int i = 0; i < 4; ++i) {
        unsigned long long y = f2_fma(cmp2[i], F2_NEG1, wsA[i]);
        unsigned long long tt = f2_add(acc2[i], y);
        unsigned long long t2 = f2_fma(acc2[i], F2_NEG1, tt);
        cmp2[i] = f2_fma(y, F2_NEG1, t2);
        acc2[i] = tt;
      }
#pragma unroll
      for (int i = 0; i < 4; ++i) {
        unsigned long long y = f2_fma(cmp2[4 + i], F2_NEG1, wsB[i]);
        unsigned long long tt = f2_add(acc2[4 + i], y);
        unsigned long long t2 = f2_fma(acc2[4 + i], F2_NEG1, tt);
        cmp2[4 + i] = f2_fma(y, F2_NEG1, t2);
        acc2[4 + i] = tt;
      }
    }
  }

  const int oh = oh0 + ty;
  const int ow = ow0 + tx * 2;
#pragma unroll
  for (int px = 0; px < 2; ++px) {
#pragma unroll
    for (int i = 0; i < 4; ++i) {
      float lo, hi;
      f2_unpack(acc2[px * 4 + i], lo, hi);
      if (FINAL) {
        lo = fmaxf(lo + bias[co0 + 2 * i], 0.f);
        hi = fmaxf(hi + bias[co0 + 2 * i + 1], 0.f);
      }
      out[(size_t)(co0 + 2 * i) * Hout * Wout + (size_t)oh * Wout + ow + px] =
          lo;
      out[(size_t)(co0 + 2 * i + 1) * Hout * Wout + (size_t)oh * Wout + ow +
          px] = hi;
    }
  }
}

__global__ void __launch_bounds__(256, 2) k_conv2(const float* w,
                                                  const float* b) {
  conv_wide<64, true>(g_h1, w, b, g_h2, 256, 256, 128, 128, 0, blockIdx.z * 8);
}
// conv3: split-C x2. z = split*32 + co_blk.
__global__ void __launch_bounds__(256, 2) k_conv3(const float* w) {
  const int split = blockIdx.z >> 5;
  const int co0 = (blockIdx.z & 31) * 8;
  conv_wide<128, false>(g_h2, w, nullptr,
                        g_c3part + (size_t)split * 256 * 64 * 64, 128, 128, 64,
                        64, split * 64, co0);
}
__global__ void k_comb3(const float* __restrict__ b) {
  const int i = blockIdx.x * 256 + threadIdx.x;  // 0 .. 256*64*64-1
  const int co = i >> 12;
  double s = (double)g_c3part[i] + (double)g_c3part[256 * 64 * 64 + i];
  float v = (float)(s + (double)b[co]);
  g_h3[i] = fmaxf(v, 0.f);
}
// ex: split-C x4. z = split*32 + co_blk.
__global__ void __launch_bounds__(256, 2) k_ex(const float* w) {
  const int split = blockIdx.z >> 5;
  const int co0 = (blockIdx.z & 31) * 8;
  conv_wide<256, false>(g_h3, w, nullptr,
                        g_expart + (size_t)split * 256 * 32 * 32, 64, 64, 32,
                        32, split * 64, co0);
}
__global__ void k_combex(const float* __restrict__ b) {
  const int i = blockIdx.x * 256 + threadIdx.x;  // 0 .. 256*32*32-1
  const int co = i >> 10;
  double s = 0.0;
#pragma unroll
  for (int sp = 0; sp < 4; ++sp)
    s += (double)g_expart[(size_t)sp * 256 * 32 * 32 + i];
  float v = (float)(s + (double)b[co]);
  g_h4[i] = fmaxf(v, 0.f);
}

// ---------------- head convs (reg 4ch + cls 21ch), stride1 pad1, split-K -------
__global__ void __launch_bounds__(256) k_head(const float* __restrict__ reg_w,
                                              const float* __restrict__ cls_w) {
  constexpr int IN_T = 34, ROWP = 35, NCH = 4;
  constexpr int ELEMS = NCH * IN_T * IN_T;
  constexpr int LD = (ELEMS + 255) / 256;
  const int split = blockIdx.x, co = blockIdx.y;
  const float* w = (co < 4) ? (reg_w + (size_t)co * 256 * 9)
                            : (cls_w + (size_t)(co - 4) * 256 * 9);
  __shared__ float s_in[NCH * IN_T * ROWP];
  __shared__ float s_w[32 * 9];
  const int t = threadIdx.x;

  int goff[LD], soff[LD];
#pragma unroll
  for (int i = 0; i < LD; ++i) {
    int idx = t + i * 256;
    int ch = idx / (IN_T * IN_T);
    int rem = idx - ch * (IN_T * IN_T);
    int r = rem / IN_T, c = rem - r * IN_T;
    int ih = r - 1, iw = c - 1;
    bool ok = (idx < ELEMS) && ((unsigned)ih < 32u) && ((unsigned)iw < 32u);
    goff[i] = ok ? (ch * 1024 + ih * 32 + iw) : -1;
    soff[i] = (ch * IN_T + r) * ROWP + c;
  }
  for (int idx = t; idx < 32 * 9; idx += 256)
    s_w[idx] = w[(size_t)(split * 32 + idx / 9) * 9 + (idx % 9)];

  float acc[4] = {0.f, 0.f, 0.f, 0.f};
  float cmp[4] = {0.f, 0.f, 0.f, 0.f};

  float rbuf[LD];
  {
    const float* inb = g_h4 + (size_t)split * 32 * 1024;
#pragma unroll
    for (int i = 0; i < LD; ++i) rbuf[i] = (goff[i] >= 0) ? inb[goff[i]] : 0.f;
  }
  for (int g = 0; g < 8; ++g) {
    __syncthreads();
#pragma unroll
    for (int i = 0; i < LD; ++i)
      if (t + i * 256 < ELEMS) s_in[soff[i]] = rbuf[i];
    if (g + 1 < 8) {
      const float* inb = g_h4 + (size_t)(split * 32 + (g + 1) * NCH) * 1024;
#pragma unroll
      for (int i = 0; i < LD; ++i)
        rbuf[i] = (goff[i] >= 0) ? inb[goff[i]] : 0.f;
    }
    __syncthreads();

#pragma unroll
    for (int cc = 0; cc < NCH; ++cc) {
      float wr[9];
#pragma unroll
      for (int k = 0; k < 9; ++k) wr[k] = s_w[(g * NCH + cc) * 9 + k];
#pragma unroll
      for (int px = 0; px < 4; ++px) {
        int p = t + px * 256;
        int oh = p >> 5, ow = p & 31;
        float a = 0.f;
#pragma unroll
        for (int kh = 0; kh < 3; ++kh)
#pragma unroll
          for (int kw = 0; kw < 3; ++kw)
            a = fmaf(s_in[(cc * IN_T + oh + kh) * ROWP + ow + kw],
                     wr[kh * 3 + kw], a);
        float y = a - cmp[px];
        float tt = acc[px] + y;
        cmp[px] = (tt - acc[px]) - y;
        acc[px] = tt;
      }
    }
  }
#pragma unroll
  for (int px = 0; px < 4; ++px)
    g_part[(size_t)(split * 25 + co) * 1024 + t + px * 256] = acc[px];
}

// ---------------- reduce partials (double) + transpose + softmax (double) ------
__global__ void k_prep(const float* __restrict__ reg_b,
                       const float* __restrict__ cls_b) {
  const int a = blockIdx.x * 256 + threadIdx.x;  // anchor 0..1023
#pragma unroll
  for (int j = 0; j < 4; ++j) {
    double s = 0.0;
    for (int sp = 0; sp < 8; ++sp)
      s += (double)g_part[(size_t)(sp * 25 + j) * 1024 + a];
    g_locs[a * 4 + j] = (float)(s + (double)reg_b[j]);
  }
  float conf[NCLS];
  for (int c = 0; c < NCLS; ++c) {
    double s = 0.0;
    for (int sp = 0; sp < 8; ++sp)
      s += (double)g_part[(size_t)(sp * 25 + 4 + c) * 1024 + a];
    conf[c] = (float)(s + (double)cls_b[c]);
    g_confs[a * NCLS + c] = conf[c];
  }
  float m = conf[0];
  int lab = 0;
  for (int c = 1; c < NCLS; ++c)
    if (conf[c] > m) { m = conf[c]; lab = c; }
  double sum = 0.0;
  for (int c = 0; c < NCLS; ++c) sum += exp((double)conf[c] - (double)m);
  g_scores[a] = (float)(1.0 / sum);  // max softmax prob
  g_labels[a] = lab;
}

// ---------------- stable bitonic sort by descending score ----------------
__global__ void k_sort() {
  __shared__ float s[1024];
  __shared__ int si[1024];
  const int t = threadIdx.x;
  s[t] = g_scores[t];
  si[t] = t;
  __syncthreads();
  for (int k = 2; k <= 1024; k <<= 1) {
    for (int j = k >> 1; j > 0; j >>= 1) {
      int ixj = t ^ j;
      if (ixj > t) {
        float sa = s[t], sb = s[ixj];
        int ia = si[t], ib = si[ixj];
        bool aFirst = (sa > sb) || (sa == sb && ia < ib);  // stable desc
        bool dirUp = ((t & k) == 0);
        if (dirUp ? !aFirst : aFirst) {
          s[t] = sb; s[ixj] = sa;
          si[t] = ib; si[ixj] = ia;
        }
      }
      __syncthreads();
    }
  }
  const int idx = si[t];
  g_order[t] = idx;
  g_sscore[t] = s[t];
  g_sbox[t] = make_float4(g_locs[idx * 4 + 0], g_locs[idx * 4 + 1],
                          g_locs[idx * 4 + 2], g_locs[idx * 4 + 3]);
  unsigned vb = __ballot_sync(0xffffffffu, s[t] > 0.04f);
  if ((t & 31) == 0) g_validmask[t >> 5] = vb;
}

// ---------------- pairwise IoU suppression bitmask (double precision) ----------
__global__ void k_iou() {
  const int i = blockIdx.x, j = threadIdx.x;
  float4 bi = g_sbox[i];
  float4 bj = g_sbox[j];
  double ai = ((double)bi.z - (double)bi.x) * ((double)bi.w - (double)bi.y);
  double aj = ((double)bj.z - (double)bj.x) * ((double)bj.w - (double)bj.y);
  double ltx = fmax((double)bi.x, (double)bj.x);
  double lty = fmax((double)bi.y, (double)bj.y);
  double rbx = fmin((double)bi.z, (double)bj.z);
  double rby = fmin((double)bi.w, (double)bj.w);
  double inter = fmax(rbx - ltx, 0.0) * fmax(rby - lty, 0.0);
  double uni = ai + aj - inter;
  double iou = inter / (uni + 1e-9);
  unsigned m = __ballot_sync(0xffffffffu, iou > 0.5);
  if ((j & 31) == 0) g_sup[i * 32 + (j >> 5)] = m;
}

// ---------------- sequential greedy NMS on bitmask, single warp ----------------
__global__ void k_nms() {
  const int lane = threadIdx.x;  // 32 threads
  unsigned kw = 0;
  const unsigned validw = g_validmask[lane];
  const int CH = 8;
  unsigned buf[CH], nbuf[CH];
#pragma unroll
  for (int q = 0; q < CH; ++q) buf[q] = g_sup[q * 32 + lane];
  for (int c = 0; c < 1024 / CH; ++c) {
    if (c + 1 < 1024 / CH) {
#pragma unroll
      for (int q = 0; q < CH; ++q)
        nbuf[q] = g_sup[((c + 1) * CH + q) * 32 + lane];
    }
#pragma unroll
    for (int q = 0; q < CH; ++q) {
      int i = c * CH + q;
      bool sup = __any_sync(0xffffffffu, (buf[q] & kw) != 0u);
      unsigned vbit =
          (__shfl_sync(0xffffffffu, validw, i >> 5) >> (i & 31)) & 1u;
      if (!sup && vbit && lane == (i >> 5)) kw |= (1u << (i & 31));
    }
#pragma unroll
    for (int q = 0; q < CH; ++q) buf[q] = nbuf[q];
  }
  g_keepmask[lane] = kw;
}

// ---------------- masked gather to output ----------------
// layout (float32): boxes[1024*4] | labels[1024] | scores[1024] | confs[1024*21]
__global__ void k_out(float* __restrict__ out) {
  const int p = blockIdx.x * 256 + threadIdx.x;  // 0..1023
  const bool keep = (g_keepmask[p >> 5] >> (p & 31)) & 1u;
  const int idx = g_order[p];
  float4 b = g_sbox[p];
  out[p * 4 + 0] = keep ? b.x : -1.0f;
  out[p * 4 + 1] = keep ? b.y : -1.0f;
  out[p * 4 + 2] = keep ? b.z : -1.0f;
  out[p * 4 + 3] = keep ? b.w : -1.0f;
  out[4096 + p] = keep ? (float)g_labels[idx] : 0.0f;
  out[5120 + p] = keep ? g_sscore[p] : -1.0f;
  for (int c = 0; c < NCLS; ++c)
    out[6144 + p * NCLS + c] = keep ? g_confs[idx * NCLS + c] : -1.0f;
}

// ---------------- launch ----------------
extern "C" void kernel_launch(void* const* d_in, const int* in_sizes, int n_in,
                              void* d_out, int out_size) {
  const float* x = (const float*)d_in[0];
  const float* bb_w1 = (const float*)d_in[1];
  const float* bb_b1 = (const float*)d_in[2];
  const float* bb_w2 = (const float*)d_in[3];
  const float* bb_b2 = (const float*)d_in[4];
  const float* bb_w3 = (const float*)d_in[5];
  const float* bb_b3 = (const float*)d_in[6];
  const float* ex_w = (const float*)d_in[7];
  const float* ex_b = (const float*)d_in[8];
  const float* reg_w = (const float*)d_in[9];
  const float* reg_b = (const float*)d_in[10];
  const float* cls_w = (const float*)d_in[11];
  const float* cls_b = (const float*)d_in[12];

  // only batch element 7 affects the output
  const float* x7 = x + (size_t)7 * 3 * 512 * 512;

  k_conv1<<<dim3(16, 16, 16), 256>>>(x7, bb_w1, bb_b1);
  k_conv2<<<dim3(4, 8, 16), 256>>>(bb_w2, bb_b2);
  k_conv3<<<dim3(2, 4, 64), 256>>>(bb_w3);
  k_comb3<<<4096, 256>>>(bb_b3);
  k_ex<<<dim3(1, 2, 128), 256>>>(ex_w);
  k_combex<<<1024, 256>>>(ex_b);
  k_head<<<dim3(8, 25), 256>>>(reg_w, cls_w);
  k_prep<<<4, 256>>>(reg_b, cls_b);
  k_sort<<<1, 1024>>>();
  k_iou<<<1024, 1024>>>();
  k_nms<<<1, 32>>>();
  k_out<<<4, 256>>>((float*)d_out);
}

// round 8
// speedup vs baseline: 1.2089x; 1.0920x over previous
#include <cuda_runtime.h>
#include <math.h>

#define NCLS 21

// ---------------- f32x2 packed helpers (Blackwell; ptxas never auto-emits) ----
__device__ __forceinline__ unsigned long long f2_fma(unsigned long long a,
                                                     unsigned long long b,
                                                     unsigned long long c) {
  unsigned long long d;
  asm("fma.rn.f32x2 %0, %1, %2, %3;" : "=l"(d) : "l"(a), "l"(b), "l"(c));
  return d;
}
__device__ __forceinline__ unsigned long long f2_add(unsigned long long a,
                                                     unsigned long long b) {
  unsigned long long d;
  asm("add.rn.f32x2 %0, %1, %2;" : "=l"(d) : "l"(a), "l"(b));
  return d;
}
__device__ __forceinline__ unsigned long long f2_bcast(float x) {
  unsigned long long d;
  asm("mov.b64 %0, {%1, %1};" : "=l"(d) : "f"(x));
  return d;
}
__device__ __forceinline__ void f2_unpack(unsigned long long v, float& lo,
                                          float& hi) {
  asm("mov.b64 {%0, %1}, %2;" : "=f"(lo), "=f"(hi) : "l"(v));
}
#define F2_NEG1 0xBF800000BF800000ULL  // (-1.0f, -1.0f)

// ---------------- scratch (static device globals; no allocation) ----------------
__device__ float g_h1[64 * 256 * 256];    // conv1 out
__device__ float g_h2[128 * 128 * 128];   // conv2 out
__device__ float g_h3[256 * 64 * 64];     // conv3 out
__device__ float g_h4[256 * 32 * 32];     // ex out
__device__ float g_c3part[2 * 256 * 64 * 64];  // conv3 split-C partials
__device__ float g_expart[4 * 256 * 32 * 32];  // ex split-C partials
__device__ float g_part[8 * 25 * 1024];   // head conv split-K partials
__device__ float g_locs[1024 * 4];
__device__ float g_confs[1024 * NCLS];
__device__ float g_scores[1024];
__device__ int g_labels[1024];
__device__ int g_order[1024];
__device__ float4 g_sbox[1024];
__device__ float g_sscore[1024];
__device__ unsigned g_validmask[32];
__device__ unsigned g_sup[1024 * 32];
__device__ unsigned g_keepmask[32];

// ================= conv1 (kept exactly as the R6-proven version) =============
template <int CIN, int WCH, int NCH, int STRIDE, int COUTS, int NCHUNK,
          bool FINAL>
__device__ __forceinline__ void conv_body(const float* __restrict__ in,
                                          const float* __restrict__ wgt,
                                          const float* __restrict__ bias,
                                          float* __restrict__ out, int Hin,
                                          int Win, int Hout, int Wout,
                                          int c_begin, int co0) {
  constexpr int TILE = 16;
  constexpr int IN_T = TILE * STRIDE + 2;
  constexpr int ROWP = IN_T + 2;
  constexpr int ELEMS = NCH * IN_T * IN_T;
  constexpr int LD = (ELEMS + 255) / 256;
  constexpr int G = WCH / NCH;
  constexpr int NW = WCH * 9 * COUTS;
  constexpr int WLD = (NW + 255) / 256;
  constexpr int NP = COUTS / 2;

  __shared__ float s_in[NCH * IN_T * ROWP];
  __shared__ __align__(16) float s_w[NW];

  const int t = threadIdx.x;
  const int tx = t & 15, ty = t >> 4;
  const int ow0 = blockIdx.x * TILE, oh0 = blockIdx.y * TILE;
  const int HW = Hin * Win;

  int goff[LD], soff[LD];
#pragma unroll
  for (int i = 0; i < LD; ++i) {
    int idx = t + i * 256;
    int ch = idx / (IN_T * IN_T);
    int rem = idx - ch * (IN_T * IN_T);
    int r = rem / IN_T, c = rem - r * IN_T;
    int ih = oh0 * STRIDE + r, iw = ow0 * STRIDE + c;
    bool ok = (idx < ELEMS) && ((unsigned)ih < (unsigned)Hin) &&
              ((unsigned)iw < (unsigned)Win);
    goff[i] = ok ? (ch * HW + ih * Win + iw) : -1;
    soff[i] = (ch * IN_T + r) * ROWP + c;
  }

  unsigned long long acc2[NP], cmp2[NP];
#pragma unroll
  for (int i = 0; i < NP; i++) { acc2[i] = 0ull; cmp2[i] = 0ull; }

  for (int c0 = c_begin; c0 < c_begin + NCHUNK * WCH; c0 += WCH) {
    __syncthreads();
#pragma unroll
    for (int i = 0; i < WLD; ++i) {
      int idx = t + i * 256;
      if (idx < NW) {
        int co = idx / (WCH * 9);
        int rem = idx - co * (WCH * 9);
        int ccg = rem / 9, k = rem - ccg * 9;
        s_w[(ccg * 9 + k) * COUTS + co] =
            wgt[(size_t)(co0 + co) * CIN * 9 + (size_t)(c0 + ccg) * 9 + k];
      }
    }
    float rbuf[LD];
    {
      const float* inb = in + (size_t)c0 * HW;
#pragma unroll
      for (int i = 0; i < LD; ++i)
        rbuf[i] = (goff[i] >= 0) ? inb[goff[i]] : 0.f;
    }
    for (int g = 0; g < G; ++g) {
      __syncthreads();
#pragma unroll
      for (int i = 0; i < LD; ++i)
        if (t + i * 256 < ELEMS) s_in[soff[i]] = rbuf[i];
      if (g + 1 < G) {
        const float* inb = in + (size_t)(c0 + (g + 1) * NCH) * HW;
#pragma unroll
        for (int i = 0; i < LD; ++i)
          rbuf[i] = (goff[i] >= 0) ? inb[goff[i]] : 0.f;
      }
      __syncthreads();

#pragma unroll
      for (int cc = 0; cc < NCH; ++cc) {
        unsigned long long wsum2[NP];
#pragma unroll
        for (int i = 0; i < NP; ++i) wsum2[i] = 0ull;
#pragma unroll
        for (int kh = 0; kh < 3; ++kh)
#pragma unroll
          for (int kw = 0; kw < 3; ++kw) {
            float xv = s_in[(cc * IN_T + ty * STRIDE + kh) * ROWP +
                            tx * STRIDE + kw];
            unsigned long long xv2 = f2_bcast(xv);
            const ulonglong2* wp = (const ulonglong2*)&s_w[((g * NCH + cc) * 9 +
                                                            kh * 3 + kw) *
                                                           COUTS];
#pragma unroll
            for (int q = 0; q < COUTS / 4; ++q) {
              ulonglong2 w2 = wp[q];
              wsum2[q * 2 + 0] = f2_fma(xv2, w2.x, wsum2[q * 2 + 0]);
              wsum2[q * 2 + 1] = f2_fma(xv2, w2.y, wsum2[q * 2 + 1]);
            }
          }
#pragma unroll
        for (int i = 0; i < NP; ++i) {
          unsigned long long y = f2_fma(cmp2[i], F2_NEG1, wsum2[i]);
          unsigned long long tt = f2_add(acc2[i], y);
          unsigned long long t2 = f2_fma(acc2[i], F2_NEG1, tt);
          cmp2[i] = f2_fma(y, F2_NEG1, t2);
          acc2[i] = tt;
        }
      }
    }
  }

  const int oh = oh0 + ty, ow = ow0 + tx;
#pragma unroll
  for (int i = 0; i < NP; i++) {
    float lo, hi;
    f2_unpack(acc2[i], lo, hi);
    if (FINAL) {
      lo = fmaxf(lo + bias[co0 + 2 * i], 0.f);
      hi = fmaxf(hi + bias[co0 + 2 * i + 1], 0.f);
    }
    out[(size_t)(co0 + 2 * i) * Hout * Wout + (size_t)oh * Wout + ow] = lo;
    out[(size_t)(co0 + 2 * i + 1) * Hout * Wout + (size_t)oh * Wout + ow] = hi;
  }
}

__global__ void __launch_bounds__(256) k_conv1(const float* x, const float* w,
                                               const float* b) {
  conv_body<3, 3, 3, 2, 4, 1, true>(x, w, b, g_h1, 512, 512, 256, 256, 0,
                                    blockIdx.z * 4);
}

// ============= wide conv: 32x16 tile, 2 horizontal px/thread, 8 couts ========
// stride 2, SAME (pad_lo=0, pad_hi=1). 64 input channels per call (2 chunks of
// 32), 2-channel staging groups. Input staged as float4 rows (17 per 66-wide
// row; cols 66-67 never read), descriptors precomputed once. Window sums are
// 18-term f32x2 FMA chains, Kahan-folded per group (identical math to R7).
template <int CINFULL, bool FINAL>
__device__ __forceinline__ void conv_wide(const float* __restrict__ in,
                                          const float* __restrict__ wgt,
                                          const float* __restrict__ bias,
                                          float* __restrict__ out, int Hin,
                                          int Win, int Hout, int Wout,
                                          int c_begin, int co0) {
  constexpr int WCH = 32, NCH = 2;
  constexpr int IN_H = 34, ROWP = 68;     // 68 floats = 17 float4 per row
  constexpr int IN_W4 = 17;               // float4 per row
  constexpr int CHE4 = IN_H * IN_W4;      // 578
  constexpr int ELEMS4 = NCH * CHE4;      // 1156
  constexpr int LD4 = (ELEMS4 + 255) / 256;  // 5
  constexpr int G = WCH / NCH;            // 16
  constexpr int NW = WCH * 9 * 8;         // 2304

  __shared__ __align__(16) float s_in[NCH * IN_H * ROWP];
  __shared__ __align__(16) float s_w[NW];

  const int t = threadIdx.x;
  const int tx = t & 15, ty = t >> 4;
  const int ow0 = blockIdx.x * 32, oh0 = blockIdx.y * 16;
  const int HW = Hin * Win;

  // precomputed float4 staging descriptors (channel-relative gmem offset)
  int goff4[LD4], soff4[LD4];
#pragma unroll
  for (int i = 0; i < LD4; ++i) {
    int idx = t + i * 256;
    int ch = (idx >= CHE4) ? 1 : 0;
    int rem = idx - ch * CHE4;
    int r = rem / IN_W4, c4 = rem - r * IN_W4;
    int ih = oh0 * 2 + r, iw = ow0 * 2 + c4 * 4;
    bool ok = (idx < ELEMS4) && ((unsigned)ih < (unsigned)Hin) &&
              ((unsigned)iw < (unsigned)Win);
    goff4[i] = ok ? (ch * HW + ih * Win + iw) : -1;
    soff4[i] = (ch * IN_H + r) * ROWP + c4 * 4;
  }

  unsigned long long acc2[8], cmp2[8];
#pragma unroll
  for (int i = 0; i < 8; ++i) { acc2[i] = 0ull; cmp2[i] = 0ull; }

  float4 rbuf[LD4];
  const float4 zero4 = make_float4(0.f, 0.f, 0.f, 0.f);

  for (int chunk = 0; chunk < 2; ++chunk) {
    const int c0 = c_begin + chunk * WCH;
    __syncthreads();  // prev chunk compute done; smem reusable
    // stage weight chunk: s_w[(ccg*9+k)*8 + co], 2304 floats = 9/thread
#pragma unroll
    for (int i = 0; i < 9; ++i) {
      int idx = t + i * 256;
      int co = idx / (WCH * 9);
      int rem = idx - co * (WCH * 9);
      int ccg = rem / 9, k = rem - ccg * 9;
      s_w[(ccg * 9 + k) * 8 + co] =
          wgt[(size_t)(co0 + co) * CINFULL * 9 + (size_t)(c0 + ccg) * 9 + k];
    }
    // prefetch group 0
    {
      const float* inb = in + (size_t)c0 * HW;
#pragma unroll
      for (int i = 0; i < LD4; ++i)
        rbuf[i] = (goff4[i] >= 0) ? *(const float4*)(inb + goff4[i]) : zero4;
    }
    for (int g = 0; g < G; ++g) {
      __syncthreads();  // compute(g-1) done before overwriting s_in
#pragma unroll
      for (int i = 0; i < LD4; ++i)
        if (t + i * 256 < ELEMS4) *(float4*)&s_in[soff4[i]] = rbuf[i];
      if (g + 1 < G) {  // prefetch next group; overlaps with compute below
        const float* inb = in + (size_t)(c0 + (g + 1) * NCH) * HW;
#pragma unroll
        for (int i = 0; i < LD4; ++i)
          rbuf[i] = (goff4[i] >= 0) ? *(const float4*)(inb + goff4[i]) : zero4;
      }
      __syncthreads();  // staging visible

      // 18-term window chains for both pixels (A = px0, B = px1)
      unsigned long long wsA[4] = {0ull, 0ull, 0ull, 0ull};
      unsigned long long wsB[4] = {0ull, 0ull, 0ull, 0ull};
#pragma unroll
      for (int cc = 0; cc < NCH; ++cc) {
#pragma unroll
        for (int kh = 0; kh < 3; ++kh) {
          const int rbase = (cc * IN_H + ty * 2 + kh) * ROWP + tx * 4;
          float4 xr = *(const float4*)&s_in[rbase];
          float x4v = s_in[rbase + 4];
          // kw=0: x0=xr.x, x1=xr.z ; kw=1: x0=xr.y, x1=xr.w ; kw=2: x0=xr.z, x1=x4v
          float x0s[3] = {xr.x, xr.y, xr.z};
          float x1s[3] = {xr.z, xr.w, x4v};
#pragma unroll
          for (int kw = 0; kw < 3; ++kw) {
            unsigned long long x0 = f2_bcast(x0s[kw]);
            unsigned long long x1 = f2_bcast(x1s[kw]);
            const ulonglong2* wp =
                (const ulonglong2*)&s_w[((g * NCH + cc) * 9 + kh * 3 + kw) * 8];
            ulonglong2 wa = wp[0], wb = wp[1];
            wsA[0] = f2_fma(x0, wa.x, wsA[0]);
            wsA[1] = f2_fma(x0, wa.y, wsA[1]);
            wsA[2] = f2_fma(x0, wb.x, wsA[2]);
            wsA[3] = f2_fma(x0, wb.y, wsA[3]);
            wsB[0] = f2_fma(x1, wa.x, wsB[0]);
            wsB[1] = f2_fma(x1, wa.y, wsB[1]);
            wsB[2] = f2_fma(x1, wb.x, wsB[2]);
            wsB[3] = f2_fma(x1, wb.y, wsB[3]);
          }
        }
      }
      // Kahan fold once per 2-channel group (acc2[0..3]=px0, [4..7]=px1)
#pragma unroll
      for (int i = 0; i < 4; ++i) {
        unsigned long long y = f2_fma(cmp2[i], F2_NEG1, wsA[i]);
        unsigned long long tt = f2_add(acc2[i], y);
        unsigned long long t2 = f2_fma(acc2[i], F2_NEG1, tt);
        cmp2[i] = f2_fma(y, F2_NEG1, t2);
        acc2[i] = tt;
      }
#pragma unroll
      for (int i = 0; i < 4; ++i) {
        unsigned long long y = f2_fma(cmp2[4 + i], F2_NEG1, wsB[i]);
        unsigned long long tt = f2_add(acc2[4 + i], y);
        unsigned long long t2 = f2_fma(acc2[4 + i], F2_NEG1, tt);
        cmp2[4 + i] = f2_fma(y, F2_NEG1, t2);
        acc2[4 + i] = tt;
      }
    }
  }

  const int oh = oh0 + ty;
  const int ow = ow0 + tx * 2;
#pragma unroll
  for (int px = 0; px < 2; ++px) {
#pragma unroll
    for (int i = 0; i < 4; ++i) {
      float lo, hi;
      f2_unpack(acc2[px * 4 + i], lo, hi);
      if (FINAL) {
        lo = fmaxf(lo + bias[co0 + 2 * i], 0.f);
        hi = fmaxf(hi + bias[co0 + 2 * i + 1], 0.f);
      }
      out[(size_t)(co0 + 2 * i) * Hout * Wout + (size_t)oh * Wout + ow + px] =
          lo;
      out[(size_t)(co0 + 2 * i + 1) * Hout * Wout + (size_t)oh * Wout + ow +
          px] = hi;
    }
  }
}

__global__ void __launch_bounds__(256, 2) k_conv2(const float* w,
                                                  const float* b) {
  conv_wide<64, true>(g_h1, w, b, g_h2, 256, 256, 128, 128, 0, blockIdx.z * 8);
}
// conv3: split-C x2. z = split*32 + co_blk.
__global__ void __launch_bounds__(256, 2) k_conv3(const float* w) {
  const int split = blockIdx.z >> 5;
  const int co0 = (blockIdx.z & 31) * 8;
  conv_wide<128, false>(g_h2, w, nullptr,
                        g_c3part + (size_t)split * 256 * 64 * 64, 128, 128, 64,
                        64, split * 64, co0);
}
__global__ void k_comb3(const float* __restrict__ b) {
  const int i = blockIdx.x * 256 + threadIdx.x;  // 0 .. 256*64*64-1
  const int co = i >> 12;
  double s = (double)g_c3part[i] + (double)g_c3part[256 * 64 * 64 + i];
  float v = (float)(s + (double)b[co]);
  g_h3[i] = fmaxf(v, 0.f);
}
// ex: split-C x4. z = split*32 + co_blk.
__global__ void __launch_bounds__(256, 2) k_ex(const float* w) {
  const int split = blockIdx.z >> 5;
  const int co0 = (blockIdx.z & 31) * 8;
  conv_wide<256, false>(g_h3, w, nullptr,
                        g_expart + (size_t)split * 256 * 32 * 32, 64, 64, 32,
                        32, split * 64, co0);
}
__global__ void k_combex(const float* __restrict__ b) {
  const int i = blockIdx.x * 256 + threadIdx.x;  // 0 .. 256*32*32-1
  const int co = i >> 10;
  double s = 0.0;
#pragma unroll
  for (int sp = 0; sp < 4; ++sp)
    s += (double)g_expart[(size_t)sp * 256 * 32 * 32 + i];
  float v = (float)(s + (double)b[co]);
  g_h4[i] = fmaxf(v, 0.f);
}

// ---------------- head convs (reg 4ch + cls 21ch), stride1 pad1, split-K -------
__global__ void __launch_bounds__(256) k_head(const float* __restrict__ reg_w,
                                              const float* __restrict__ cls_w) {
  constexpr int IN_T = 34, ROWP = 35, NCH = 4;
  constexpr int ELEMS = NCH * IN_T * IN_T;
  constexpr int LD = (ELEMS + 255) / 256;
  const int split = blockIdx.x, co = blockIdx.y;
  const float* w = (co < 4) ? (reg_w + (size_t)co * 256 * 9)
                            : (cls_w + (size_t)(co - 4) * 256 * 9);
  __shared__ float s_in[NCH * IN_T * ROWP];
  __shared__ float s_w[32 * 9];
  const int t = threadIdx.x;

  int goff[LD], soff[LD];
#pragma unroll
  for (int i = 0; i < LD; ++i) {
    int idx = t + i * 256;
    int ch = idx / (IN_T * IN_T);
    int rem = idx - ch * (IN_T * IN_T);
    int r = rem / IN_T, c = rem - r * IN_T;
    int ih = r - 1, iw = c - 1;
    bool ok = (idx < ELEMS) && ((unsigned)ih < 32u) && ((unsigned)iw < 32u);
    goff[i] = ok ? (ch * 1024 + ih * 32 + iw) : -1;
    soff[i] = (ch * IN_T + r) * ROWP + c;
  }
  for (int idx = t; idx < 32 * 9; idx += 256)
    s_w[idx] = w[(size_t)(split * 32 + idx / 9) * 9 + (idx % 9)];

  float acc[4] = {0.f, 0.f, 0.f, 0.f};
  float cmp[4] = {0.f, 0.f, 0.f, 0.f};

  float rbuf[LD];
  {
    const float* inb = g_h4 + (size_t)split * 32 * 1024;
#pragma unroll
    for (int i = 0; i < LD; ++i) rbuf[i] = (goff[i] >= 0) ? inb[goff[i]] : 0.f;
  }
  for (int g = 0; g < 8; ++g) {
    __syncthreads();
#pragma unroll
    for (int i = 0; i < LD; ++i)
      if (t + i * 256 < ELEMS) s_in[soff[i]] = rbuf[i];
    if (g + 1 < 8) {
      const float* inb = g_h4 + (size_t)(split * 32 + (g + 1) * NCH) * 1024;
#pragma unroll
      for (int i = 0; i < LD; ++i)
        rbuf[i] = (goff[i] >= 0) ? inb[goff[i]] : 0.f;
    }
    __syncthreads();

#pragma unroll
    for (int cc = 0; cc < NCH; ++cc) {
      float wr[9];
#pragma unroll
      for (int k = 0; k < 9; ++k) wr[k] = s_w[(g * NCH + cc) * 9 + k];
#pragma unroll
      for (int px = 0; px < 4; ++px) {
        int p = t + px * 256;
        int oh = p >> 5, ow = p & 31;
        float a = 0.f;
#pragma unroll
        for (int kh = 0; kh < 3; ++kh)
#pragma unroll
          for (int kw = 0; kw < 3; ++kw)
            a = fmaf(s_in[(cc * IN_T + oh + kh) * ROWP + ow + kw],
                     wr[kh * 3 + kw], a);
        float y = a - cmp[px];
        float tt = acc[px] + y;
        cmp[px] = (tt - acc[px]) - y;
        acc[px] = tt;
      }
    }
  }
#pragma unroll
  for (int px = 0; px < 4; ++px)
    g_part[(size_t)(split * 25 + co) * 1024 + t + px * 256] = acc[px];
}

// ---------------- reduce partials (double) + transpose + softmax (double) ------
__global__ void k_prep(const float* __restrict__ reg_b,
                       const float* __restrict__ cls_b) {
  const int a = blockIdx.x * 256 + threadIdx.x;  // anchor 0..1023
#pragma unroll
  for (int j = 0; j < 4; ++j) {
    double s = 0.0;
    for (int sp = 0; sp < 8; ++sp)
      s += (double)g_part[(size_t)(sp * 25 + j) * 1024 + a];
    g_locs[a * 4 + j] = (float)(s + (double)reg_b[j]);
  }
  float conf[NCLS];
  for (int c = 0; c < NCLS; ++c) {
    double s = 0.0;
    for (int sp = 0; sp < 8; ++sp)
      s += (double)g_part[(size_t)(sp * 25 + 4 + c) * 1024 + a];
    conf[c] = (float)(s + (double)cls_b[c]);
    g_confs[a * NCLS + c] = conf[c];
  }
  float m = conf[0];
  int lab = 0;
  for (int c = 1; c < NCLS; ++c)
    if (conf[c] > m) { m = conf[c]; lab = c; }
  double sum = 0.0;
  for (int c = 0; c < NCLS; ++c) sum += exp((double)conf[c] - (double)m);
  g_scores[a] = (float)(1.0 / sum);  // max softmax prob
  g_labels[a] = lab;
}

// ---------------- stable bitonic sort by descending score ----------------
__global__ void k_sort() {
  __shared__ float s[1024];
  __shared__ int si[1024];
  const int t = threadIdx.x;
  s[t] = g_scores[t];
  si[t] = t;
  __syncthreads();
  for (int k = 2; k <= 1024; k <<= 1) {
    for (int j = k >> 1; j > 0; j >>= 1) {
      int ixj = t ^ j;
      if (ixj > t) {
        float sa = s[t], sb = s[ixj];
        int ia = si[t], ib = si[ixj];
        bool aFirst = (sa > sb) || (sa == sb && ia < ib);  // stable desc
        bool dirUp = ((t & k) == 0);
        if (dirUp ? !aFirst : aFirst) {
          s[t] = sb; s[ixj] = sa;
          si[t] = ib; si[ixj] = ia;
        }
      }
      __syncthreads();
    }
  }
  const int idx = si[t];
  g_order[t] = idx;
  g_sscore[t] = s[t];
  g_sbox[t] = make_float4(g_locs[idx * 4 + 0], g_locs[idx * 4 + 1],
                          g_locs[idx * 4 + 2], g_locs[idx * 4 + 3]);
  unsigned vb = __ballot_sync(0xffffffffu, s[t] > 0.04f);
  if ((t & 31) == 0) g_validmask[t >> 5] = vb;
}

// ---------------- pairwise IoU suppression bitmask (double precision) ----------
__global__ void k_iou() {
  const int i = blockIdx.x, j = threadIdx.x;
  float4 bi = g_sbox[i];
  float4 bj = g_sbox[j];
  double ai = ((double)bi.z - (double)bi.x) * ((double)bi.w - (double)bi.y);
  double aj = ((double)bj.z - (double)bj.x) * ((double)bj.w - (double)bj.y);
  double ltx = fmax((double)bi.x, (double)bj.x);
  double lty = fmax((double)bi.y, (double)bj.y);
  double rbx = fmin((double)bi.z, (double)bj.z);
  double rby = fmin((double)bi.w, (double)bj.w);
  double inter = fmax(rbx - ltx, 0.0) * fmax(rby - lty, 0.0);
  double uni = ai + aj - inter;
  double iou = inter / (uni + 1e-9);
  unsigned m = __ballot_sync(0xffffffffu, iou > 0.5);
  if ((j & 31) == 0) g_sup[i * 32 + (j >> 5)] = m;
}

// ---------------- sequential greedy NMS on bitmask, single warp ----------------
__global__ void k_nms() {
  const int lane = threadIdx.x;  // 32 threads
  unsigned kw = 0;
  const unsigned validw = g_validmask[lane];
  const int CH = 8;
  unsigned buf[CH], nbuf[CH];
#pragma unroll
  for (int q = 0; q < CH; ++q) buf[q] = g_sup[q * 32 + lane];
  for (int c = 0; c < 1024 / CH; ++c) {
    if (c + 1 < 1024 / CH) {
#pragma unroll
      for (int q = 0; q < CH; ++q)
        nbuf[q] = g_sup[((c + 1) * CH + q) * 32 + lane];
    }
#pragma unroll
    for (int q = 0; q < CH; ++q) {
      int i = c * CH + q;
      bool sup = __any_sync(0xffffffffu, (buf[q] & kw) != 0u);
      unsigned vbit =
          (__shfl_sync(0xffffffffu, validw, i >> 5) >> (i & 31)) & 1u;
      if (!sup && vbit && lane == (i >> 5)) kw |= (1u << (i & 31));
    }
#pragma unroll
    for (int q = 0; q < CH; ++q) buf[q] = nbuf[q];
  }
  g_keepmask[lane] = kw;
}

// ---------------- masked gather to output ----------------
// layout (float32): boxes[1024*4] | labels[1024] | scores[1024] | confs[1024*21]
__global__ void k_out(float* __restrict__ out) {
  const int p = blockIdx.x * 256 + threadIdx.x;  // 0..1023
  const bool keep = (g_keepmask[p >> 5] >> (p & 31)) & 1u;
  const int idx = g_order[p];
  float4 b = g_sbox[p];
  out[p * 4 + 0] = keep ? b.x : -1.0f;
  out[p * 4 + 1] = keep ? b.y : -1.0f;
  out[p * 4 + 2] = keep ? b.z : -1.0f;
  out[p * 4 + 3] = keep ? b.w : -1.0f;
  out[4096 + p] = keep ? (float)g_labels[idx] : 0.0f;
  out[5120 + p] = keep ? g_sscore[p] : -1.0f;
  for (int c = 0; c < NCLS; ++c)
    out[6144 + p * NCLS + c] = keep ? g_confs[idx * NCLS + c] : -1.0f;
}

// ---------------- launch ----------------
extern "C" void kernel_launch(void* const* d_in, const int* in_sizes, int n_in,
                              void* d_out, int out_size) {
  const float* x = (const float*)d_in[0];
  const float* bb_w1 = (const float*)d_in[1];
  const float* bb_b1 = (const float*)d_in[2];
  const float* bb_w2 = (const float*)d_in[3];
  const float* bb_b2 = (const float*)d_in[4];
  const float* bb_w3 = (const float*)d_in[5];
  const float* bb_b3 = (const float*)d_in[6];
  const float* ex_w = (const float*)d_in[7];
  const float* ex_b = (const float*)d_in[8];
  const float* reg_w = (const float*)d_in[9];
  const float* reg_b = (const float*)d_in[10];
  const float* cls_w = (const float*)d_in[11];
  const float* cls_b = (const float*)d_in[12];

  // only batch element 7 affects the output
  const float* x7 = x + (size_t)7 * 3 * 512 * 512;

  k_conv1<<<dim3(16, 16, 16), 256>>>(x7, bb_w1, bb_b1);
  k_conv2<<<dim3(4, 8, 16), 256>>>(bb_w2, bb_b2);
  k_conv3<<<dim3(2, 4, 64), 256>>>(bb_w3);
  k_comb3<<<4096, 256>>>(bb_b3);
  k_ex<<<dim3(1, 2, 128), 256>>>(ex_w);
  k_combex<<<1024, 256>>>(ex_b);
  k_head<<<dim3(8, 25), 256>>>(reg_w, cls_w);
  k_prep<<<4, 256>>>(reg_b, cls_b);
  k_sort<<<1, 1024>>>();
  k_iou<<<1024, 1024>>>();
  k_nms<<<1, 32>>>();
  k_out<<<4, 256>>>((float*)d_out);
}

// round 9
// speedup vs baseline: 1.2371x; 1.0233x over previous
#include <cuda_runtime.h>
#include <math.h>

#define NCLS 21

// ---------------- f32x2 packed helpers (Blackwell; ptxas never auto-emits) ----
__device__ __forceinline__ unsigned long long f2_fma(unsigned long long a,
                                                     unsigned long long b,
                                                     unsigned long long c) {
  unsigned long long d;
  asm("fma.rn.f32x2 %0, %1, %2, %3;" : "=l"(d) : "l"(a), "l"(b), "l"(c));
  return d;
}
__device__ __forceinline__ unsigned long long f2_add(unsigned long long a,
                                                     unsigned long long b) {
  unsigned long long d;
  asm("add.rn.f32x2 %0, %1, %2;" : "=l"(d) : "l"(a), "l"(b));
  return d;
}
__device__ __forceinline__ unsigned long long f2_bcast(float x) {
  unsigned long long d;
  asm("mov.b64 %0, {%1, %1};" : "=l"(d) : "f"(x));
  return d;
}
__device__ __forceinline__ void f2_unpack(unsigned long long v, float& lo,
                                          float& hi) {
  asm("mov.b64 {%0, %1}, %2;" : "=f"(lo), "=f"(hi) : "l"(v));
}
#define F2_NEG1 0xBF800000BF800000ULL  // (-1.0f, -1.0f)

// ---------------- scratch (static device globals; no allocation) ----------------
__device__ float g_h1[64 * 256 * 256];    // conv1 out
__device__ float g_h2[128 * 128 * 128];   // conv2 out
__device__ float g_h3[256 * 64 * 64];     // conv3 out
__device__ float g_h4[256 * 32 * 32];     // ex out
__device__ float g_c3part[2 * 256 * 64 * 64];  // conv3 split-C partials
__device__ float g_expart[4 * 256 * 32 * 32];  // ex split-C partials
__device__ float g_part[8 * 25 * 1024];   // head conv split-K partials
__device__ float g_locs[1024 * 4];
__device__ float g_confs[1024 * NCLS];
__device__ float g_scores[1024];
__device__ int g_labels[1024];
__device__ int g_order[1024];
__device__ float4 g_sbox[1024];
__device__ float g_sscore[1024];
__device__ unsigned g_validmask[32];
__device__ unsigned g_sup[1024 * 32];
__device__ unsigned g_keepmask[32];

// ================= conv1 (kept exactly as the R6-proven version) =============
template <int CIN, int WCH, int NCH, int STRIDE, int COUTS, int NCHUNK,
          bool FINAL>
__device__ __forceinline__ void conv_body(const float* __restrict__ in,
                                          const float* __restrict__ wgt,
                                          const float* __restrict__ bias,
                                          float* __restrict__ out, int Hin,
                                          int Win, int Hout, int Wout,
                                          int c_begin, int co0) {
  constexpr int TILE = 16;
  constexpr int IN_T = TILE * STRIDE + 2;
  constexpr int ROWP = IN_T + 2;
  constexpr int ELEMS = NCH * IN_T * IN_T;
  constexpr int LD = (ELEMS + 255) / 256;
  constexpr int G = WCH / NCH;
  constexpr int NW = WCH * 9 * COUTS;
  constexpr int WLD = (NW + 255) / 256;
  constexpr int NP = COUTS / 2;

  __shared__ float s_in[NCH * IN_T * ROWP];
  __shared__ __align__(16) float s_w[NW];

  const int t = threadIdx.x;
  const int tx = t & 15, ty = t >> 4;
  const int ow0 = blockIdx.x * TILE, oh0 = blockIdx.y * TILE;
  const int HW = Hin * Win;

  int goff[LD], soff[LD];
#pragma unroll
  for (int i = 0; i < LD; ++i) {
    int idx = t + i * 256;
    int ch = idx / (IN_T * IN_T);
    int rem = idx - ch * (IN_T * IN_T);
    int r = rem / IN_T, c = rem - r * IN_T;
    int ih = oh0 * STRIDE + r, iw = ow0 * STRIDE + c;
    bool ok = (idx < ELEMS) && ((unsigned)ih < (unsigned)Hin) &&
              ((unsigned)iw < (unsigned)Win);
    goff[i] = ok ? (ch * HW + ih * Win + iw) : -1;
    soff[i] = (ch * IN_T + r) * ROWP + c;
  }

  unsigned long long acc2[NP], cmp2[NP];
#pragma unroll
  for (int i = 0; i < NP; i++) { acc2[i] = 0ull; cmp2[i] = 0ull; }

  for (int c0 = c_begin; c0 < c_begin + NCHUNK * WCH; c0 += WCH) {
    __syncthreads();
#pragma unroll
    for (int i = 0; i < WLD; ++i) {
      int idx = t + i * 256;
      if (idx < NW) {
        int co = idx / (WCH * 9);
        int rem = idx - co * (WCH * 9);
        int ccg = rem / 9, k = rem - ccg * 9;
        s_w[(ccg * 9 + k) * COUTS + co] =
            wgt[(size_t)(co0 + co) * CIN * 9 + (size_t)(c0 + ccg) * 9 + k];
      }
    }
    float rbuf[LD];
    {
      const float* inb = in + (size_t)c0 * HW;
#pragma unroll
      for (int i = 0; i < LD; ++i)
        rbuf[i] = (goff[i] >= 0) ? inb[goff[i]] : 0.f;
    }
    for (int g = 0; g < G; ++g) {
      __syncthreads();
#pragma unroll
      for (int i = 0; i < LD; ++i)
        if (t + i * 256 < ELEMS) s_in[soff[i]] = rbuf[i];
      if (g + 1 < G) {
        const float* inb = in + (size_t)(c0 + (g + 1) * NCH) * HW;
#pragma unroll
        for (int i = 0; i < LD; ++i)
          rbuf[i] = (goff[i] >= 0) ? inb[goff[i]] : 0.f;
      }
      __syncthreads();

#pragma unroll
      for (int cc = 0; cc < NCH; ++cc) {
        unsigned long long wsum2[NP];
#pragma unroll
        for (int i = 0; i < NP; ++i) wsum2[i] = 0ull;
#pragma unroll
        for (int kh = 0; kh < 3; ++kh)
#pragma unroll
          for (int kw = 0; kw < 3; ++kw) {
            float xv = s_in[(cc * IN_T + ty * STRIDE + kh) * ROWP +
                            tx * STRIDE + kw];
            unsigned long long xv2 = f2_bcast(xv);
            const ulonglong2* wp = (const ulonglong2*)&s_w[((g * NCH + cc) * 9 +
                                                            kh * 3 + kw) *
                                                           COUTS];
#pragma unroll
            for (int q = 0; q < COUTS / 4; ++q) {
              ulonglong2 w2 = wp[q];
              wsum2[q * 2 + 0] = f2_fma(xv2, w2.x, wsum2[q * 2 + 0]);
              wsum2[q * 2 + 1] = f2_fma(xv2, w2.y, wsum2[q * 2 + 1]);
            }
          }
#pragma unroll
        for (int i = 0; i < NP; ++i) {
          unsigned long long y = f2_fma(cmp2[i], F2_NEG1, wsum2[i]);
          unsigned long long tt = f2_add(acc2[i], y);
          unsigned long long t2 = f2_fma(acc2[i], F2_NEG1, tt);
          cmp2[i] = f2_fma(y, F2_NEG1, t2);
          acc2[i] = tt;
        }
      }
    }
  }

  const int oh = oh0 + ty, ow = ow0 + tx;
#pragma unroll
  for (int i = 0; i < NP; i++) {
    float lo, hi;
    f2_unpack(acc2[i], lo, hi);
    if (FINAL) {
      lo = fmaxf(lo + bias[co0 + 2 * i], 0.f);
      hi = fmaxf(hi + bias[co0 + 2 * i + 1], 0.f);
    }
    out[(size_t)(co0 + 2 * i) * Hout * Wout + (size_t)oh * Wout + ow] = lo;
    out[(size_t)(co0 + 2 * i + 1) * Hout * Wout + (size_t)oh * Wout + ow] = hi;
  }
}

__global__ void __launch_bounds__(256) k_conv1(const float* x, const float* w,
                                               const float* b) {
  conv_body<3, 3, 3, 2, 4, 1, true>(x, w, b, g_h1, 512, 512, 256, 256, 0,
                                    blockIdx.z * 4);
}

// ============= wide conv: 32x16 tile, 2 horizontal px/thread, 8 couts ========
// stride 2, SAME (pad_lo=0, pad_hi=1). 64 input channels per call (2 chunks of
// 32), 2-channel staging groups. DOUBLE-BUFFERED s_in: one barrier per group.
// Race-freedom: storing into buf[g&1] at iteration g is safe because every
// thread passed the barrier of iteration g-1 only after finishing compute g-2
// (the last reader of buf[g&1]). Arithmetic identical to R8 (bit-exact).
template <int CINFULL, bool FINAL>
__device__ __forceinline__ void conv_wide(const float* __restrict__ in,
                                          const float* __restrict__ wgt,
                                          const float* __restrict__ bias,
                                          float* __restrict__ out, int Hin,
                                          int Win, int Hout, int Wout,
                                          int c_begin, int co0) {
  constexpr int WCH = 32, NCH = 2;
  constexpr int IN_H = 34, ROWP = 68;     // 68 floats = 17 float4 per row
  constexpr int IN_W4 = 17;               // float4 per row
  constexpr int CHE4 = IN_H * IN_W4;      // 578
  constexpr int ELEMS4 = NCH * CHE4;      // 1156
  constexpr int LD4 = (ELEMS4 + 255) / 256;  // 5
  constexpr int G = WCH / NCH;            // 16
  constexpr int NW = WCH * 9 * 8;         // 2304
  constexpr int BUFSZ = NCH * IN_H * ROWP;  // 4624 floats

  __shared__ __align__(16) float s_in[2 * BUFSZ];
  __shared__ __align__(16) float s_w[NW];

  const int t = threadIdx.x;
  const int tx = t & 15, ty = t >> 4;
  const int ow0 = blockIdx.x * 32, oh0 = blockIdx.y * 16;
  const int HW = Hin * Win;

  // precomputed float4 staging descriptors (channel-relative gmem offset)
  int goff4[LD4], soff4[LD4];
#pragma unroll
  for (int i = 0; i < LD4; ++i) {
    int idx = t + i * 256;
    int ch = (idx >= CHE4) ? 1 : 0;
    int rem = idx - ch * CHE4;
    int r = rem / IN_W4, c4 = rem - r * IN_W4;
    int ih = oh0 * 2 + r, iw = ow0 * 2 + c4 * 4;
    bool ok = (idx < ELEMS4) && ((unsigned)ih < (unsigned)Hin) &&
              ((unsigned)iw < (unsigned)Win);
    goff4[i] = ok ? (ch * HW + ih * Win + iw) : -1;
    soff4[i] = (ch * IN_H + r) * ROWP + c4 * 4;
  }

  unsigned long long acc2[8], cmp2[8];
#pragma unroll
  for (int i = 0; i < 8; ++i) { acc2[i] = 0ull; cmp2[i] = 0ull; }

  float4 rbuf[LD4];
  const float4 zero4 = make_float4(0.f, 0.f, 0.f, 0.f);

  for (int chunk = 0; chunk < 2; ++chunk) {
    const int c0 = c_begin + chunk * WCH;
    __syncthreads();  // prev chunk fully computed before s_w overwrite
    // stage weight chunk: s_w[(ccg*9+k)*8 + co], 2304 floats = 9/thread
#pragma unroll
    for (int i = 0; i < 9; ++i) {
      int idx = t + i * 256;
      int co = idx / (WCH * 9);
      int rem = idx - co * (WCH * 9);
      int ccg = rem / 9, k = rem - ccg * 9;
      s_w[(ccg * 9 + k) * 8 + co] =
          wgt[(size_t)(co0 + co) * CINFULL * 9 + (size_t)(c0 + ccg) * 9 + k];
    }
    // prefetch group 0
    {
      const float* inb = in + (size_t)c0 * HW;
#pragma unroll
      for (int i = 0; i < LD4; ++i)
        rbuf[i] = (goff4[i] >= 0) ? *(const float4*)(inb + goff4[i]) : zero4;
    }
    for (int g = 0; g < G; ++g) {
      float* buf = s_in + (g & 1) * BUFSZ;
      // store current group's data (other threads may still compute g-1 on
      // the OTHER buffer — safe)
#pragma unroll
      for (int i = 0; i < LD4; ++i)
        if (t + i * 256 < ELEMS4) *(float4*)&buf[soff4[i]] = rbuf[i];
      if (g + 1 < G) {  // prefetch next group; overlaps with compute below
        const float* inb = in + (size_t)(c0 + (g + 1) * NCH) * HW;
#pragma unroll
        for (int i = 0; i < LD4; ++i)
          rbuf[i] = (goff4[i] >= 0) ? *(const float4*)(inb + goff4[i]) : zero4;
      }
      __syncthreads();  // buf (and s_w on g==0) fully staged

      // 18-term window chains for both pixels (A = px0, B = px1)
      unsigned long long wsA[4] = {0ull, 0ull, 0ull, 0ull};
      unsigned long long wsB[4] = {0ull, 0ull, 0ull, 0ull};
#pragma unroll
      for (int cc = 0; cc < NCH; ++cc) {
#pragma unroll
        for (int kh = 0; kh < 3; ++kh) {
          const int rbase = (cc * IN_H + ty * 2 + kh) * ROWP + tx * 4;
          float4 xr = *(const float4*)&buf[rbase];
          float x4v = buf[rbase + 4];
          float x0s[3] = {xr.x, xr.y, xr.z};
          float x1s[3] = {xr.z, xr.w, x4v};
#pragma unroll
          for (int kw = 0; kw < 3; ++kw) {
            unsigned long long x0 = f2_bcast(x0s[kw]);
            unsigned long long x1 = f2_bcast(x1s[kw]);
            const ulonglong2* wp =
                (const ulonglong2*)&s_w[((g * NCH + cc) * 9 + kh * 3 + kw) * 8];
            ulonglong2 wa = wp[0], wb = wp[1];
            wsA[0] = f2_fma(x0, wa.x, wsA[0]);
            wsA[1] = f2_fma(x0, wa.y, wsA[1]);
            wsA[2] = f2_fma(x0, wb.x, wsA[2]);
            wsA[3] = f2_fma(x0, wb.y, wsA[3]);
            wsB[0] = f2_fma(x1, wa.x, wsB[0]);
            wsB[1] = f2_fma(x1, wa.y, wsB[1]);
            wsB[2] = f2_fma(x1, wb.x, wsB[2]);
            wsB[3] = f2_fma(x1, wb.y, wsB[3]);
          }
        }
      }
      // Kahan fold once per 2-channel group (acc2[0..3]=px0, [4..7]=px1)
#pragma unroll
      for (int i = 0; i < 4; ++i) {
        unsigned long long y = f2_fma(cmp2[i], F2_NEG1, wsA[i]);
        unsigned long long tt = f2_add(acc2[i], y);
        unsigned long long t2 = f2_fma(acc2[i], F2_NEG1, tt);
        cmp2[i] = f2_fma(y, F2_NEG1, t2);
        acc2[i] = tt;
      }
#pragma unroll
      for (int i = 0; i < 4; ++i) {
        unsigned long long y = f2_fma(cmp2[4 + i], F2_NEG1, wsB[i]);
        unsigned long long tt = f2_add(acc2[4 + i], y);
        unsigned long long t2 = f2_fma(acc2[4 + i], F2_NEG1, tt);
        cmp2[4 + i] = f2_fma(y, F2_NEG1, t2);
        acc2[4 + i] = tt;
      }
    }
  }

  const int oh = oh0 + ty;
  const int ow = ow0 + tx * 2;
#pragma unroll
  for (int px = 0; px < 2; ++px) {
#pragma unroll
    for (int i = 0; i < 4; ++i) {
      float lo, hi;
      f2_unpack(acc2[px * 4 + i], lo, hi);
      if (FINAL) {
        lo = fmaxf(lo + bias[co0 + 2 * i], 0.f);
        hi = fmaxf(hi + bias[co0 + 2 * i + 1], 0.f);
      }
      out[(size_t)(co0 + 2 * i) * Hout * Wout + (size_t)oh * Wout + ow + px] =
          lo;
      out[(size_t)(co0 + 2 * i + 1) * Hout * Wout + (size_t)oh * Wout + ow +
          px] = hi;
    }
  }
}

__global__ void __launch_bounds__(256, 2) k_conv2(const float* w,
                                                  const float* b) {
  conv_wide<64, true>(g_h1, w, b, g_h2, 256, 256, 128, 128, 0, blockIdx.z * 8);
}
// conv3: split-C x2. z = split*32 + co_blk.
__global__ void __launch_bounds__(256, 2) k_conv3(const float* w) {
  const int split = blockIdx.z >> 5;
  const int co0 = (blockIdx.z & 31) * 8;
  conv_wide<128, false>(g_h2, w, nullptr,
                        g_c3part + (size_t)split * 256 * 64 * 64, 128, 128, 64,
                        64, split * 64, co0);
}
// vectorized combine: 4 elements/thread (same fp64 math per element)
__global__ void k_comb3(const float* __restrict__ b) {
  const int i4 = (blockIdx.x * 256 + threadIdx.x) * 4;  // 0..256*64*64-4
  const int co = i4 >> 12;
  const double bv = (double)b[co];
  float4 a = *(const float4*)&g_c3part[i4];
  float4 c = *(const float4*)&g_c3part[256 * 64 * 64 + i4];
  float4 o;
  o.x = fmaxf((float)(((double)a.x + (double)c.x) + bv), 0.f);
  o.y = fmaxf((float)(((double)a.y + (double)c.y) + bv), 0.f);
  o.z = fmaxf((float)(((double)a.z + (double)c.z) + bv), 0.f);
  o.w = fmaxf((float)(((double)a.w + (double)c.w) + bv), 0.f);
  *(float4*)&g_h3[i4] = o;
}
// ex: split-C x4. z = split*32 + co_blk.
__global__ void __launch_bounds__(256, 2) k_ex(const float* w) {
  const int split = blockIdx.z >> 5;
  const int co0 = (blockIdx.z & 31) * 8;
  conv_wide<256, false>(g_h3, w, nullptr,
                        g_expart + (size_t)split * 256 * 32 * 32, 64, 64, 32,
                        32, split * 64, co0);
}
__global__ void k_combex(const float* __restrict__ b) {
  const int i4 = (blockIdx.x * 256 + threadIdx.x) * 4;  // 0..256*32*32-4
  const int co = i4 >> 10;
  const double bv = (double)b[co];
  float4 p0 = *(const float4*)&g_expart[i4];
  float4 p1 = *(const float4*)&g_expart[256 * 32 * 32 + i4];
  float4 p2 = *(const float4*)&g_expart[2 * 256 * 32 * 32 + i4];
  float4 p3 = *(const float4*)&g_expart[3 * 256 * 32 * 32 + i4];
  float4 o;
  o.x = fmaxf((float)((((double)p0.x + (double)p1.x) + (double)p2.x) +
                      (double)p3.x + bv), 0.f);
  o.y = fmaxf((float)((((double)p0.y + (double)p1.y) + (double)p2.y) +
                      (double)p3.y + bv), 0.f);
  o.z = fmaxf((float)((((double)p0.z + (double)p1.z) + (double)p2.z) +
                      (double)p3.z + bv), 0.f);
  o.w = fmaxf((float)((((double)p0.w + (double)p1.w) + (double)p2.w) +
                      (double)p3.w + bv), 0.f);
  *(float4*)&g_h4[i4] = o;
}

// ---------------- head convs (reg 4ch + cls 21ch), stride1 pad1, split-K -------
__global__ void __launch_bounds__(256) k_head(const float* __restrict__ reg_w,
                                              const float* __restrict__ cls_w) {
  constexpr int IN_T = 34, ROWP = 35, NCH = 4;
  constexpr int ELEMS = NCH * IN_T * IN_T;
  constexpr int LD = (ELEMS + 255) / 256;
  const int split = blockIdx.x, co = blockIdx.y;
  const float* w = (co < 4) ? (reg_w + (size_t)co * 256 * 9)
                            : (cls_w + (size_t)(co - 4) * 256 * 9);
  __shared__ float s_in[NCH * IN_T * ROWP];
  __shared__ float s_w[32 * 9];
  const int t = threadIdx.x;

  int goff[LD], soff[LD];
#pragma unroll
  for (int i = 0; i < LD; ++i) {
    int idx = t + i * 256;
    int ch = idx / (IN_T * IN_T);
    int rem = idx - ch * (IN_T * IN_T);
    int r = rem / IN_T, c = rem - r * IN_T;
    int ih = r - 1, iw = c - 1;
    bool ok = (idx < ELEMS) && ((unsigned)ih < 32u) && ((unsigned)iw < 32u);
    goff[i] = ok ? (ch * 1024 + ih * 32 + iw) : -1;
    soff[i] = (ch * IN_T + r) * ROWP + c;
  }
  for (int idx = t; idx < 32 * 9; idx += 256)
    s_w[idx] = w[(size_t)(split * 32 + idx / 9) * 9 + (idx % 9)];

  float acc[4] = {0.f, 0.f, 0.f, 0.f};
  float cmp[4] = {0.f, 0.f, 0.f, 0.f};

  float rbuf[LD];
  {
    const float* inb = g_h4 + (size_t)split * 32 * 1024;
#pragma unroll
    for (int i = 0; i < LD; ++i) rbuf[i] = (goff[i] >= 0) ? inb[goff[i]] : 0.f;
  }
  for (int g = 0; g < 8; ++g) {
    __syncthreads();
#pragma unroll
    for (int i = 0; i < LD; ++i)
      if (t + i * 256 < ELEMS) s_in[soff[i]] = rbuf[i];
    if (g + 1 < 8) {
      const float* inb = g_h4 + (size_t)(split * 32 + (g + 1) * NCH) * 1024;
#pragma unroll
      for (int i = 0; i < LD; ++i)
        rbuf[i] = (goff[i] >= 0) ? inb[goff[i]] : 0.f;
    }
    __syncthreads();

#pragma unroll
    for (int cc = 0; cc < NCH; ++cc) {
      float wr[9];
#pragma unroll
      for (int k = 0; k < 9; ++k) wr[k] = s_w[(g * NCH + cc) * 9 + k];
#pragma unroll
      for (int px = 0; px < 4; ++px) {
        int p = t + px * 256;
        int oh = p >> 5, ow = p & 31;
        float a = 0.f;
#pragma unroll
        for (int kh = 0; kh < 3; ++kh)
#pragma unroll
          for (int kw = 0; kw < 3; ++kw)
            a = fmaf(s_in[(cc * IN_T + oh + kh) * ROWP + ow + kw],
                     wr[kh * 3 + kw], a);
        float y = a - cmp[px];
        float tt = acc[px] + y;
        cmp[px] = (tt - acc[px]) - y;
        acc[px] = tt;
      }
    }
  }
#pragma unroll
  for (int px = 0; px < 4; ++px)
    g_part[(size_t)(split * 25 + co) * 1024 + t + px * 256] = acc[px];
}

// ---------------- reduce partials (double) + transpose + softmax (double) ------
__global__ void k_prep(const float* __restrict__ reg_b,
                       const float* __restrict__ cls_b) {
  const int a = blockIdx.x * 256 + threadIdx.x;  // anchor 0..1023
#pragma unroll
  for (int j = 0; j < 4; ++j) {
    double s = 0.0;
    for (int sp = 0; sp < 8; ++sp)
      s += (double)g_part[(size_t)(sp * 25 + j) * 1024 + a];
    g_locs[a * 4 + j] = (float)(s + (double)reg_b[j]);
  }
  float conf[NCLS];
  for (int c = 0; c < NCLS; ++c) {
    double s = 0.0;
    for (int sp = 0; sp < 8; ++sp)
      s += (double)g_part[(size_t)(sp * 25 + 4 + c) * 1024 + a];
    conf[c] = (float)(s + (double)cls_b[c]);
    g_confs[a * NCLS + c] = conf[c];
  }
  float m = conf[0];
  int lab = 0;
  for (int c = 1; c < NCLS; ++c)
    if (conf[c] > m) { m = conf[c]; lab = c; }
  double sum = 0.0;
  for (int c = 0; c < NCLS; ++c) sum += exp((double)conf[c] - (double)m);
  g_scores[a] = (float)(1.0 / sum);  // max softmax prob
  g_labels[a] = lab;
}

// ---------------- stable bitonic sort by descending score ----------------
__global__ void k_sort() {
  __shared__ float s[1024];
  __shared__ int si[1024];
  const int t = threadIdx.x;
  s[t] = g_scores[t];
  si[t] = t;
  __syncthreads();
  for (int k = 2; k <= 1024; k <<= 1) {
    for (int j = k >> 1; j > 0; j >>= 1) {
      int ixj = t ^ j;
      if (ixj > t) {
        float sa = s[t], sb = s[ixj];
        int ia = si[t], ib = si[ixj];
        bool aFirst = (sa > sb) || (sa == sb && ia < ib);  // stable desc
        bool dirUp = ((t & k) == 0);
        if (dirUp ? !aFirst : aFirst) {
          s[t] = sb; s[ixj] = sa;
          si[t] = ib; si[ixj] = ia;
        }
      }
      __syncthreads();
    }
  }
  const int idx = si[t];
  g_order[t] = idx;
  g_sscore[t] = s[t];
  g_sbox[t] = make_float4(g_locs[idx * 4 + 0], g_locs[idx * 4 + 1],
                          g_locs[idx * 4 + 2], g_locs[idx * 4 + 3]);
  unsigned vb = __ballot_sync(0xffffffffu, s[t] > 0.04f);
  if ((t & 31) == 0) g_validmask[t >> 5] = vb;
}

// ---------------- pairwise IoU suppression bitmask (double precision) ----------
__global__ void k_iou() {
  const int i = blockIdx.x, j = threadIdx.x;
  float4 bi = g_sbox[i];
  float4 bj = g_sbox[j];
  double ai = ((double)bi.z - (double)bi.x) * ((double)bi.w - (double)bi.y);
  double aj = ((double)bj.z - (double)bj.x) * ((double)bj.w - (double)bj.y);
  double ltx = fmax((double)bi.x, (double)bj.x);
  double lty = fmax((double)bi.y, (double)bj.y);
  double rbx = fmin((double)bi.z, (double)bj.z);
  double rby = fmin((double)bi.w, (double)bj.w);
  double inter = fmax(rbx - ltx, 0.0) * fmax(rby - lty, 0.0);
  double uni = ai + aj - inter;
  double iou = inter / (uni + 1e-9);
  unsigned m = __ballot_sync(0xffffffffu, iou > 0.5);
  if ((j & 31) == 0) g_sup[i * 32 + (j >> 5)] = m;
}

// ---------------- sequential greedy NMS on bitmask, single warp ----------------
__global__ void k_nms() {
  const int lane = threadIdx.x;  // 32 threads
  unsigned kw = 0;
  const unsigned validw = g_validmask[lane];
  const int CH = 8;
  unsigned buf[CH], nbuf[CH];
#pragma unroll
  for (int q = 0; q < CH; ++q) buf[q] = g_sup[q * 32 + lane];
  for (int c = 0; c < 1024 / CH; ++c) {
    if (c + 1 < 1024 / CH) {
#pragma unroll
      for (int q = 0; q < CH; ++q)
        nbuf[q] = g_sup[((c + 1) * CH + q) * 32 + lane];
    }
#pragma unroll
    for (int q = 0; q < CH; ++q) {
      int i = c * CH + q;
      bool sup = __any_sync(0xffffffffu, (buf[q] & kw) != 0u);
      unsigned vbit =
          (__shfl_sync(0xffffffffu, validw, i >> 5) >> (i & 31)) & 1u;
      if (!sup && vbit && lane == (i >> 5)) kw |= (1u << (i & 31));
    }
#pragma unroll
    for (int q = 0; q < CH; ++q) buf[q] = nbuf[q];
  }
  g_keepmask[lane] = kw;
}

// ---------------- masked gather to output ----------------
// layout (float32): boxes[1024*4] | labels[1024] | scores[1024] | confs[1024*21]
__global__ void k_out(float* __restrict__ out) {
  const int p = blockIdx.x * 256 + threadIdx.x;  // 0..1023
  const bool keep = (g_keepmask[p >> 5] >> (p & 31)) & 1u;
  const int idx = g_order[p];
  float4 b = g_sbox[p];
  out[p * 4 + 0] = keep ? b.x : -1.0f;
  out[p * 4 + 1] = keep ? b.y : -1.0f;
  out[p * 4 + 2] = keep ? b.z : -1.0f;
  out[p * 4 + 3] = keep ? b.w : -1.0f;
  out[4096 + p] = keep ? (float)g_labels[idx] : 0.0f;
  out[5120 + p] = keep ? g_sscore[p] : -1.0f;
  for (int c = 0; c < NCLS; ++c)
    out[6144 + p * NCLS + c] = keep ? g_confs[idx * NCLS + c] : -1.0f;
}

// ---------------- launch ----------------
extern "C" void kernel_launch(void* const* d_in, const int* in_sizes, int n_in,
                              void* d_out, int out_size) {
  const float* x = (const float*)d_in[0];
  const float* bb_w1 = (const float*)d_in[1];
  const float* bb_b1 = (const float*)d_in[2];
  const float* bb_w2 = (const float*)d_in[3];
  const float* bb_b2 = (const float*)d_in[4];
  const float* bb_w3 = (const float*)d_in[5];
  const float* bb_b3 = (const float*)d_in[6];
  const float* ex_w = (const float*)d_in[7];
  const float* ex_b = (const float*)d_in[8];
  const float* reg_w = (const float*)d_in[9];
  const float* reg_b = (const float*)d_in[10];
  const float* cls_w = (const float*)d_in[11];
  const float* cls_b = (const float*)d_in[12];

  // only batch element 7 affects the output
  const float* x7 = x + (size_t)7 * 3 * 512 * 512;

  k_conv1<<<dim3(16, 16, 16), 256>>>(x7, bb_w1, bb_b1);
  k_conv2<<<dim3(4, 8, 16), 256>>>(bb_w2, bb_b2);
  k_conv3<<<dim3(2, 4, 64), 256>>>(bb_w3);
  k_comb3<<<1024, 256>>>(bb_b3);
  k_ex<<<dim3(1, 2, 128), 256>>>(ex_w);
  k_combex<<<256, 256>>>(ex_b);
  k_head<<<dim3(8, 25), 256>>>(reg_w, cls_w);
  k_prep<<<4, 256>>>(reg_b, cls_b);
  k_sort<<<1, 1024>>>();
  k_iou<<<1024, 1024>>>();
  k_nms<<<1, 32>>>();
  k_out<<<4, 256>>>((float*)d_out);
}

// round 10
// speedup vs baseline: 1.3029x; 1.0532x over previous
#include <cuda_runtime.h>
#include <math.h>

#define NCLS 21

// ---------------- f32x2 packed helpers (Blackwell; ptxas never auto-emits) ----
__device__ __forceinline__ unsigned long long f2_fma(unsigned long long a,
                                                     unsigned long long b,
                                                     unsigned long long c) {
  unsigned long long d;
  asm("fma.rn.f32x2 %0, %1, %2, %3;" : "=l"(d) : "l"(a), "l"(b), "l"(c));
  return d;
}
__device__ __forceinline__ unsigned long long f2_add(unsigned long long a,
                                                     unsigned long long b) {
  unsigned long long d;
  asm("add.rn.f32x2 %0, %1, %2;" : "=l"(d) : "l"(a), "l"(b));
  return d;
}
__device__ __forceinline__ unsigned long long f2_bcast(float x) {
  unsigned long long d;
  asm("mov.b64 %0, {%1, %1};" : "=l"(d) : "f"(x));
  return d;
}
__device__ __forceinline__ void f2_unpack(unsigned long long v, float& lo,
                                          float& hi) {
  asm("mov.b64 {%0, %1}, %2;" : "=f"(lo), "=f"(hi) : "l"(v));
}
#define F2_NEG1 0xBF800000BF800000ULL  // (-1.0f, -1.0f)

// ---------------- cp.async helpers ----------------
__device__ __forceinline__ void cp16(unsigned dst, const void* src,
                                     int srcsize) {
  asm volatile("cp.async.cg.shared.global [%0], [%1], 16, %2;" ::"r"(dst),
               "l"(src), "r"(srcsize));
}
__device__ __forceinline__ void cp_commit() {
  asm volatile("cp.async.commit_group;");
}
__device__ __forceinline__ void cp_wait_all() {
  asm volatile("cp.async.wait_group 0;");
}

// ---------------- scratch (static device globals; no allocation) ----------------
__device__ float g_h1[64 * 256 * 256];    // conv1 out
__device__ float g_h2[128 * 128 * 128];   // conv2 out
__device__ float g_h3[256 * 64 * 64];     // conv3 out
__device__ float g_h4[256 * 32 * 32];     // ex out
__device__ float g_c3part[2 * 256 * 64 * 64];  // conv3 split-C partials
__device__ float g_expart[4 * 256 * 32 * 32];  // ex split-C partials
__device__ float g_part[8 * 25 * 1024];   // head conv split-K partials
__device__ float g_locs[1024 * 4];
__device__ float g_confs[1024 * NCLS];
__device__ float g_scores[1024];
__device__ int g_labels[1024];
__device__ int g_order[1024];
__device__ float4 g_sbox[1024];
__device__ float g_sscore[1024];
__device__ unsigned g_validmask[32];
__device__ unsigned g_sup[1024 * 32];
__device__ unsigned g_keepmask[32];

// ================= conv1 (kept exactly as the R6-proven version) =============
template <int CIN, int WCH, int NCH, int STRIDE, int COUTS, int NCHUNK,
          bool FINAL>
__device__ __forceinline__ void conv_body(const float* __restrict__ in,
                                          const float* __restrict__ wgt,
                                          const float* __restrict__ bias,
                                          float* __restrict__ out, int Hin,
                                          int Win, int Hout, int Wout,
                                          int c_begin, int co0) {
  constexpr int TILE = 16;
  constexpr int IN_T = TILE * STRIDE + 2;
  constexpr int ROWP = IN_T + 2;
  constexpr int ELEMS = NCH * IN_T * IN_T;
  constexpr int LD = (ELEMS + 255) / 256;
  constexpr int G = WCH / NCH;
  constexpr int NW = WCH * 9 * COUTS;
  constexpr int WLD = (NW + 255) / 256;
  constexpr int NP = COUTS / 2;

  __shared__ float s_in[NCH * IN_T * ROWP];
  __shared__ __align__(16) float s_w[NW];

  const int t = threadIdx.x;
  const int tx = t & 15, ty = t >> 4;
  const int ow0 = blockIdx.x * TILE, oh0 = blockIdx.y * TILE;
  const int HW = Hin * Win;

  int goff[LD], soff[LD];
#pragma unroll
  for (int i = 0; i < LD; ++i) {
    int idx = t + i * 256;
    int ch = idx / (IN_T * IN_T);
    int rem = idx - ch * (IN_T * IN_T);
    int r = rem / IN_T, c = rem - r * IN_T;
    int ih = oh0 * STRIDE + r, iw = ow0 * STRIDE + c;
    bool ok = (idx < ELEMS) && ((unsigned)ih < (unsigned)Hin) &&
              ((unsigned)iw < (unsigned)Win);
    goff[i] = ok ? (ch * HW + ih * Win + iw) : -1;
    soff[i] = (ch * IN_T + r) * ROWP + c;
  }

  unsigned long long acc2[NP], cmp2[NP];
#pragma unroll
  for (int i = 0; i < NP; i++) { acc2[i] = 0ull; cmp2[i] = 0ull; }

  for (int c0 = c_begin; c0 < c_begin + NCHUNK * WCH; c0 += WCH) {
    __syncthreads();
#pragma unroll
    for (int i = 0; i < WLD; ++i) {
      int idx = t + i * 256;
      if (idx < NW) {
        int co = idx / (WCH * 9);
        int rem = idx - co * (WCH * 9);
        int ccg = rem / 9, k = rem - ccg * 9;
        s_w[(ccg * 9 + k) * COUTS + co] =
            wgt[(size_t)(co0 + co) * CIN * 9 + (size_t)(c0 + ccg) * 9 + k];
      }
    }
    float rbuf[LD];
    {
      const float* inb = in + (size_t)c0 * HW;
#pragma unroll
      for (int i = 0; i < LD; ++i)
        rbuf[i] = (goff[i] >= 0) ? inb[goff[i]] : 0.f;
    }
    for (int g = 0; g < G; ++g) {
      __syncthreads();
#pragma unroll
      for (int i = 0; i < LD; ++i)
        if (t + i * 256 < ELEMS) s_in[soff[i]] = rbuf[i];
      if (g + 1 < G) {
        const float* inb = in + (size_t)(c0 + (g + 1) * NCH) * HW;
#pragma unroll
        for (int i = 0; i < LD; ++i)
          rbuf[i] = (goff[i] >= 0) ? inb[goff[i]] : 0.f;
      }
      __syncthreads();

#pragma unroll
      for (int cc = 0; cc < NCH; ++cc) {
        unsigned long long wsum2[NP];
#pragma unroll
        for (int i = 0; i < NP; ++i) wsum2[i] = 0ull;
#pragma unroll
        for (int kh = 0; kh < 3; ++kh)
#pragma unroll
          for (int kw = 0; kw < 3; ++kw) {
            float xv = s_in[(cc * IN_T + ty * STRIDE + kh) * ROWP +
                            tx * STRIDE + kw];
            unsigned long long xv2 = f2_bcast(xv);
            const ulonglong2* wp = (const ulonglong2*)&s_w[((g * NCH + cc) * 9 +
                                                            kh * 3 + kw) *
                                                           COUTS];
#pragma unroll
            for (int q = 0; q < COUTS / 4; ++q) {
              ulonglong2 w2 = wp[q];
              wsum2[q * 2 + 0] = f2_fma(xv2, w2.x, wsum2[q * 2 + 0]);
              wsum2[q * 2 + 1] = f2_fma(xv2, w2.y, wsum2[q * 2 + 1]);
            }
          }
#pragma unroll
        for (int i = 0; i < NP; ++i) {
          unsigned long long y = f2_fma(cmp2[i], F2_NEG1, wsum2[i]);
          unsigned long long tt = f2_add(acc2[i], y);
          unsigned long long t2 = f2_fma(acc2[i], F2_NEG1, tt);
          cmp2[i] = f2_fma(y, F2_NEG1, t2);
          acc2[i] = tt;
        }
      }
    }
  }

  const int oh = oh0 + ty, ow = ow0 + tx;
#pragma unroll
  for (int i = 0; i < NP; i++) {
    float lo, hi;
    f2_unpack(acc2[i], lo, hi);
    if (FINAL) {
      lo = fmaxf(lo + bias[co0 + 2 * i], 0.f);
      hi = fmaxf(hi + bias[co0 + 2 * i + 1], 0.f);
    }
    out[(size_t)(co0 + 2 * i) * Hout * Wout + (size_t)oh * Wout + ow] = lo;
    out[(size_t)(co0 + 2 * i + 1) * Hout * Wout + (size_t)oh * Wout + ow] = hi;
  }
}

__global__ void __launch_bounds__(256) k_conv1(const float* x, const float* w,
                                               const float* b) {
  conv_body<3, 3, 3, 2, 4, 1, true>(x, w, b, g_h1, 512, 512, 256, 256, 0,
                                    blockIdx.z * 4);
}

// ============= wide conv: 32x16 tile, 2 horizontal px/thread, 8 couts ========
// stride 2, SAME (pad_lo=0, pad_hi=1). 64 input channels per call (2 chunks of
// 32). Staging: 4 channels per group via cp.async into double-buffered dynamic
// smem — ONE barrier per group; copies for group g+1 land while group g
// computes. Compute loop processes channels in the SAME pairs with the SAME
// 18-term f32x2 chains + per-pair Kahan fold as R9 -> bit-identical results.
template <int CINFULL, bool FINAL>
__device__ __forceinline__ void conv_wide(const float* __restrict__ in,
                                          const float* __restrict__ wgt,
                                          const float* __restrict__ bias,
                                          float* __restrict__ out, int Hin,
                                          int Win, int Hout, int Wout,
                                          int c_begin, int co0) {
  constexpr int WCH = 32, NCH = 4;
  constexpr int IN_H = 34, ROWP = 68;     // 68 floats = 17 float4 per row
  constexpr int IN_W4 = 17;               // float4 per row
  constexpr int CHE4 = IN_H * IN_W4;      // 578 float4 per channel
  constexpr int ELEMS4 = NCH * CHE4;      // 2312
  constexpr int LD4 = (ELEMS4 + 255) / 256;  // 10
  constexpr int G = WCH / NCH;            // 8
  constexpr int NW = WCH * 9 * 8;         // 2304
  constexpr int BUFSZ = NCH * IN_H * ROWP;  // 9248 floats

  extern __shared__ float smem_dyn[];
  float* s_in = smem_dyn;                 // 2 * BUFSZ floats
  float* s_w = smem_dyn + 2 * BUFSZ;      // NW floats (16B-aligned offset)

  const int t = threadIdx.x;
  const int tx = t & 15, ty = t >> 4;
  const int ow0 = blockIdx.x * 32, oh0 = blockIdx.y * 16;
  const int HW = Hin * Win;

  // staging descriptors: soff4 = -1 -> no slot; goff4 = -1 -> zero-fill
  int goff4[LD4], soff4[LD4];
#pragma unroll
  for (int i = 0; i < LD4; ++i) {
    int idx = t + i * 256;
    int ch = idx / CHE4;
    int rem = idx - ch * CHE4;
    int r = rem / IN_W4, c4 = rem - r * IN_W4;
    int ih = oh0 * 2 + r, iw = ow0 * 2 + c4 * 4;
    bool slot = (idx < ELEMS4);
    bool ok = slot && ((unsigned)ih < (unsigned)Hin) &&
              ((unsigned)iw < (unsigned)Win);
    goff4[i] = ok ? (ch * HW + ih * Win + iw) : -1;
    soff4[i] = slot ? ((ch * IN_H + r) * ROWP + c4 * 4) : -1;
  }

  unsigned long long acc2[8], cmp2[8];
#pragma unroll
  for (int i = 0; i < 8; ++i) { acc2[i] = 0ull; cmp2[i] = 0ull; }

  for (int chunk = 0; chunk < 2; ++chunk) {
    const int c0 = c_begin + chunk * WCH;
    __syncthreads();  // all compute of prev chunk done (s_w + buffers free)
    // stage weight chunk: s_w[(ccg*9+k)*8 + co], 2304 floats = 9/thread
#pragma unroll
    for (int i = 0; i < 9; ++i) {
      int idx = t + i * 256;
      int co = idx / (WCH * 9);
      int rem = idx - co * (WCH * 9);
      int ccg = rem / 9, k = rem - ccg * 9;
      s_w[(ccg * 9 + k) * 8 + co] =
          wgt[(size_t)(co0 + co) * CINFULL * 9 + (size_t)(c0 + ccg) * 9 + k];
    }
    // issue group 0 copies into buf0
    {
      const float* inb = in + (size_t)c0 * HW;
      unsigned bufb = (unsigned)__cvta_generic_to_shared(s_in);
#pragma unroll
      for (int i = 0; i < LD4; ++i)
        if (soff4[i] >= 0)
          cp16(bufb + (unsigned)soff4[i] * 4,
               inb + (goff4[i] >= 0 ? goff4[i] : 0), goff4[i] >= 0 ? 16 : 0);
      cp_commit();
    }
    for (int g = 0; g < G; ++g) {
      cp_wait_all();    // my copies for group g landed
      __syncthreads();  // everyone's copies visible (and s_w on g==0)
      if (g + 1 < G) {  // issue next group; overlaps with compute below.
        // Safe: buf[(g+1)&1] was last read in compute g-1, which every
        // thread finished before arriving at THIS barrier.
        const float* inb = in + (size_t)(c0 + (g + 1) * NCH) * HW;
        unsigned bufb = (unsigned)__cvta_generic_to_shared(
            s_in + ((g + 1) & 1) * BUFSZ);
#pragma unroll
        for (int i = 0; i < LD4; ++i)
          if (soff4[i] >= 0)
            cp16(bufb + (unsigned)soff4[i] * 4,
                 inb + (goff4[i] >= 0 ? goff4[i] : 0), goff4[i] >= 0 ? 16 : 0);
        cp_commit();
      }
      const float* buf = s_in + (g & 1) * BUFSZ;

      // two channel-pairs, each: 18-term chains + Kahan fold (R9-identical)
#pragma unroll
      for (int sub = 0; sub < 2; ++sub) {
        unsigned long long wsA[4] = {0ull, 0ull, 0ull, 0ull};
        unsigned long long wsB[4] = {0ull, 0ull, 0ull, 0ull};
#pragma unroll
        for (int cc = 0; cc < 2; ++cc) {
          const int chl = sub * 2 + cc;  // channel within staged group
#pragma unroll
          for (int kh = 0; kh < 3; ++kh) {
            const int rbase = (chl * IN_H + ty * 2 + kh) * ROWP + tx * 4;
            float4 xr = *(const float4*)&buf[rbase];
            float x4v = buf[rbase + 4];
            float x0s[3] = {xr.x, xr.y, xr.z};
            float x1s[3] = {xr.z, xr.w, x4v};
#pragma unroll
            for (int kw = 0; kw < 3; ++kw) {
              unsigned long long x0 = f2_bcast(x0s[kw]);
              unsigned long long x1 = f2_bcast(x1s[kw]);
              const ulonglong2* wp =
                  (const ulonglong2*)&s_w[((g * NCH + chl) * 9 + kh * 3 + kw) *
                                          8];
              ulonglong2 wa = wp[0], wb = wp[1];
              wsA[0] = f2_fma(x0, wa.x, wsA[0]);
              wsA[1] = f2_fma(x0, wa.y, wsA[1]);
              wsA[2] = f2_fma(x0, wb.x, wsA[2]);
              wsA[3] = f2_fma(x0, wb.y, wsA[3]);
              wsB[0] = f2_fma(x1, wa.x, wsB[0]);
              wsB[1] = f2_fma(x1, wa.y, wsB[1]);
              wsB[2] = f2_fma(x1, wb.x, wsB[2]);
              wsB[3] = f2_fma(x1, wb.y, wsB[3]);
            }
          }
        }
#pragma unroll
        for (int i = 0; i < 4; ++i) {
          unsigned long long y = f2_fma(cmp2[i], F2_NEG1, wsA[i]);
          unsigned long long tt = f2_add(acc2[i], y);
          unsigned long long t2 = f2_fma(acc2[i], F2_NEG1, tt);
          cmp2[i] = f2_fma(y, F2_NEG1, t2);
          acc2[i] = tt;
        }
#pragma unroll
        for (int i = 0; i < 4; ++i) {
          unsigned long long y = f2_fma(cmp2[4 + i], F2_NEG1, wsB[i]);
          unsigned long long tt = f2_add(acc2[4 + i], y);
          unsigned long long t2 = f2_fma(acc2[4 + i], F2_NEG1, tt);
          cmp2[4 + i] = f2_fma(y, F2_NEG1, t2);
          acc2[4 + i] = tt;
        }
      }
    }
  }

  const int oh = oh0 + ty;
  const int ow = ow0 + tx * 2;
#pragma unroll
  for (int px = 0; px < 2; ++px) {
#pragma unroll
    for (int i = 0; i < 4; ++i) {
      float lo, hi;
      f2_unpack(acc2[px * 4 + i], lo, hi);
      if (FINAL) {
        lo = fmaxf(lo + bias[co0 + 2 * i], 0.f);
        hi = fmaxf(hi + bias[co0 + 2 * i + 1], 0.f);
      }
      out[(size_t)(co0 + 2 * i) * Hout * Wout + (size_t)oh * Wout + ow + px] =
          lo;
      out[(size_t)(co0 + 2 * i + 1) * Hout * Wout + (size_t)oh * Wout + ow +
          px] = hi;
    }
  }
}

static const int CW_SMEM = (2 * 4 * 34 * 68 + 32 * 9 * 8) * 4;  // 83200 B

__global__ void __launch_bounds__(256, 2) k_conv2(const float* w,
                                                  const float* b) {
  conv_wide<64, true>(g_h1, w, b, g_h2, 256, 256, 128, 128, 0, blockIdx.z * 8);
}
// conv3: split-C x2. z = split*32 + co_blk.
__global__ void __launch_bounds__(256, 2) k_conv3(const float* w) {
  const int split = blockIdx.z >> 5;
  const int co0 = (blockIdx.z & 31) * 8;
  conv_wide<128, false>(g_h2, w, nullptr,
                        g_c3part + (size_t)split * 256 * 64 * 64, 128, 128, 64,
                        64, split * 64, co0);
}
// vectorized combine: 4 elements/thread (same fp64 math per element)
__global__ void k_comb3(const float* __restrict__ b) {
  const int i4 = (blockIdx.x * 256 + threadIdx.x) * 4;  // 0..256*64*64-4
  const int co = i4 >> 12;
  const double bv = (double)b[co];
  float4 a = *(const float4*)&g_c3part[i4];
  float4 c = *(const float4*)&g_c3part[256 * 64 * 64 + i4];
  float4 o;
  o.x = fmaxf((float)(((double)a.x + (double)c.x) + bv), 0.f);
  o.y = fmaxf((float)(((double)a.y + (double)c.y) + bv), 0.f);
  o.z = fmaxf((float)(((double)a.z + (double)c.z) + bv), 0.f);
  o.w = fmaxf((float)(((double)a.w + (double)c.w) + bv), 0.f);
  *(float4*)&g_h3[i4] = o;
}
// ex: split-C x4. z = split*32 + co_blk.
__global__ void __launch_bounds__(256, 2) k_ex(const float* w) {
  const int split = blockIdx.z >> 5;
  const int co0 = (blockIdx.z & 31) * 8;
  conv_wide<256, false>(g_h3, w, nullptr,
                        g_expart + (size_t)split * 256 * 32 * 32, 64, 64, 32,
                        32, split * 64, co0);
}
__global__ void k_combex(const float* __restrict__ b) {
  const int i4 = (blockIdx.x * 256 + threadIdx.x) * 4;  // 0..256*32*32-4
  const int co = i4 >> 10;
  const double bv = (double)b[co];
  float4 p0 = *(const float4*)&g_expart[i4];
  float4 p1 = *(const float4*)&g_expart[256 * 32 * 32 + i4];
  float4 p2 = *(const float4*)&g_expart[2 * 256 * 32 * 32 + i4];
  float4 p3 = *(const float4*)&g_expart[3 * 256 * 32 * 32 + i4];
  float4 o;
  o.x = fmaxf((float)((((double)p0.x + (double)p1.x) + (double)p2.x) +
                      (double)p3.x + bv), 0.f);
  o.y = fmaxf((float)((((double)p0.y + (double)p1.y) + (double)p2.y) +
                      (double)p3.y + bv), 0.f);
  o.z = fmaxf((float)((((double)p0.z + (double)p1.z) + (double)p2.z) +
                      (double)p3.z + bv), 0.f);
  o.w = fmaxf((float)((((double)p0.w + (double)p1.w) + (double)p2.w) +
                      (double)p3.w + bv), 0.f);
  *(float4*)&g_h4[i4] = o;
}

// ---------------- head convs (reg 4ch + cls 21ch), stride1 pad1, split-K -------
__global__ void __launch_bounds__(256) k_head(const float* __restrict__ reg_w,
                                              const float* __restrict__ cls_w) {
  constexpr int IN_T = 34, ROWP = 35, NCH = 4;
  constexpr int ELEMS = NCH * IN_T * IN_T;
  constexpr int LD = (ELEMS + 255) / 256;
  const int split = blockIdx.x, co = blockIdx.y;
  const float* w = (co < 4) ? (reg_w + (size_t)co * 256 * 9)
                            : (cls_w + (size_t)(co - 4) * 256 * 9);
  __shared__ float s_in[NCH * IN_T * ROWP];
  __shared__ float s_w[32 * 9];
  const int t = threadIdx.x;

  int goff[LD], soff[LD];
#pragma unroll
  for (int i = 0; i < LD; ++i) {
    int idx = t + i * 256;
    int ch = idx / (IN_T * IN_T);
    int rem = idx - ch * (IN_T * IN_T);
    int r = rem / IN_T, c = rem - r * IN_T;
    int ih = r - 1, iw = c - 1;
    bool ok = (idx < ELEMS) && ((unsigned)ih < 32u) && ((unsigned)iw < 32u);
    goff[i] = ok ? (ch * 1024 + ih * 32 + iw) : -1;
    soff[i] = (ch * IN_T + r) * ROWP + c;
  }
  for (int idx = t; idx < 32 * 9; idx += 256)
    s_w[idx] = w[(size_t)(split * 32 + idx / 9) * 9 + (idx % 9)];

  float acc[4] = {0.f, 0.f, 0.f, 0.f};
  float cmp[4] = {0.f, 0.f, 0.f, 0.f};

  float rbuf[LD];
  {
    const float* inb = g_h4 + (size_t)split * 32 * 1024;
#pragma unroll
    for (int i = 0; i < LD; ++i) rbuf[i] = (goff[i] >= 0) ? inb[goff[i]] : 0.f;
  }
  for (int g = 0; g < 8; ++g) {
    __syncthreads();
#pragma unroll
    for (int i = 0; i < LD; ++i)
      if (t + i * 256 < ELEMS) s_in[soff[i]] = rbuf[i];
    if (g + 1 < 8) {
      const float* inb = g_h4 + (size_t)(split * 32 + (g + 1) * NCH) * 1024;
#pragma unroll
      for (int i = 0; i < LD; ++i)
        rbuf[i] = (goff[i] >= 0) ? inb[goff[i]] : 0.f;
    }
    __syncthreads();

#pragma unroll
    for (int cc = 0; cc < NCH; ++cc) {
      float wr[9];
#pragma unroll
      for (int k = 0; k < 9; ++k) wr[k] = s_w[(g * NCH + cc) * 9 + k];
#pragma unroll
      for (int px = 0; px < 4; ++px) {
        int p = t + px * 256;
        int oh = p >> 5, ow = p & 31;
        float a = 0.f;
#pragma unroll
        for (int kh = 0; kh < 3; ++kh)
#pragma unroll
          for (int kw = 0; kw < 3; ++kw)
            a = fmaf(s_in[(cc * IN_T + oh + kh) * ROWP + ow + kw],
                     wr[kh * 3 + kw], a);
        float y = a - cmp[px];
        float tt = acc[px] + y;
        cmp[px] = (tt - acc[px]) - y;
        acc[px] = tt;
      }
    }
  }
#pragma unroll
  for (int px = 0; px < 4; ++px)
    g_part[(size_t)(split * 25 + co) * 1024 + t + px * 256] = acc[px];
}

// ---------------- reduce partials (double) + transpose + softmax (double) ------
__global__ void k_prep(const float* __restrict__ reg_b,
                       const float* __restrict__ cls_b) {
  const int a = blockIdx.x * 256 + threadIdx.x;  // anchor 0..1023
#pragma unroll
  for (int j = 0; j < 4; ++j) {
    double s = 0.0;
    for (int sp = 0; sp < 8; ++sp)
      s += (double)g_part[(size_t)(sp * 25 + j) * 1024 + a];
    g_locs[a * 4 + j] = (float)(s + (double)reg_b[j]);
  }
  float conf[NCLS];
  for (int c = 0; c < NCLS; ++c) {
    double s = 0.0;
    for (int sp = 0; sp < 8; ++sp)
      s += (double)g_part[(size_t)(sp * 25 + 4 + c) * 1024 + a];
    conf[c] = (float)(s + (double)cls_b[c]);
    g_confs[a * NCLS + c] = conf[c];
  }
  float m = conf[0];
  int lab = 0;
  for (int c = 1; c < NCLS; ++c)
    if (conf[c] > m) { m = conf[c]; lab = c; }
  double sum = 0.0;
  for (int c = 0; c < NCLS; ++c) sum += exp((double)conf[c] - (double)m);
  g_scores[a] = (float)(1.0 / sum);  // max softmax prob
  g_labels[a] = lab;
}

// ---------------- stable bitonic sort by descending score ----------------
__global__ void k_sort() {
  __shared__ float s[1024];
  __shared__ int si[1024];
  const int t = threadIdx.x;
  s[t] = g_scores[t];
  si[t] = t;
  __syncthreads();
  for (int k = 2; k <= 1024; k <<= 1) {
    for (int j = k >> 1; j > 0; j >>= 1) {
      int ixj = t ^ j;
      if (ixj > t) {
        float sa = s[t], sb = s[ixj];
        int ia = si[t], ib = si[ixj];
        bool aFirst = (sa > sb) || (sa == sb && ia < ib);  // stable desc
        bool dirUp = ((t & k) == 0);
        if (dirUp ? !aFirst : aFirst) {
          s[t] = sb; s[ixj] = sa;
          si[t] = ib; si[ixj] = ia;
        }
      }
      __syncthreads();
    }
  }
  const int idx = si[t];
  g_order[t] = idx;
  g_sscore[t] = s[t];
  g_sbox[t] = make_float4(g_locs[idx * 4 + 0], g_locs[idx * 4 + 1],
                          g_locs[idx * 4 + 2], g_locs[idx * 4 + 3]);
  unsigned vb = __ballot_sync(0xffffffffu, s[t] > 0.04f);
  if ((t & 31) == 0) g_validmask[t >> 5] = vb;
}

// ---------------- pairwise IoU suppression bitmask (double precision) ----------
__global__ void k_iou() {
  const int i = blockIdx.x, j = threadIdx.x;
  float4 bi = g_sbox[i];
  float4 bj = g_sbox[j];
  double ai = ((double)bi.z - (double)bi.x) * ((double)bi.w - (double)bi.y);
  double aj = ((double)bj.z - (double)bj.x) * ((double)bj.w - (double)bj.y);
  double ltx = fmax((double)bi.x, (double)bj.x);
  double lty = fmax((double)bi.y, (double)bj.y);
  double rbx = fmin((double)bi.z, (double)bj.z);
  double rby = fmin((double)bi.w, (double)bj.w);
  double inter = fmax(rbx - ltx, 0.0) * fmax(rby - lty, 0.0);
  double uni = ai + aj - inter;
  double iou = inter / (uni + 1e-9);
  unsigned m = __ballot_sync(0xffffffffu, iou > 0.5);
  if ((j & 31) == 0) g_sup[i * 32 + (j >> 5)] = m;
}

// ---------------- sequential greedy NMS on bitmask, single warp ----------------
__global__ void k_nms() {
  const int lane = threadIdx.x;  // 32 threads
  unsigned kw = 0;
  const unsigned validw = g_validmask[lane];
  const int CH = 8;
  unsigned buf[CH], nbuf[CH];
#pragma unroll
  for (int q = 0; q < CH; ++q) buf[q] = g_sup[q * 32 + lane];
  for (int c = 0; c < 1024 / CH; ++c) {
    if (c + 1 < 1024 / CH) {
#pragma unroll
      for (int q = 0; q < CH; ++q)
        nbuf[q] = g_sup[((c + 1) * CH + q) * 32 + lane];
    }
#pragma unroll
    for (int q = 0; q < CH; ++q) {
      int i = c * CH + q;
      bool sup = __any_sync(0xffffffffu, (buf[q] & kw) != 0u);
      unsigned vbit =
          (__shfl_sync(0xffffffffu, validw, i >> 5) >> (i & 31)) & 1u;
      if (!sup && vbit && lane == (i >> 5)) kw |= (1u << (i & 31));
    }
#pragma unroll
    for (int q = 0; q < CH; ++q) buf[q] = nbuf[q];
  }
  g_keepmask[lane] = kw;
}

// ---------------- masked gather to output ----------------
// layout (float32): boxes[1024*4] | labels[1024] | scores[1024] | confs[1024*21]
__global__ void k_out(float* __restrict__ out) {
  const int p = blockIdx.x * 256 + threadIdx.x;  // 0..1023
  const bool keep = (g_keepmask[p >> 5] >> (p & 31)) & 1u;
  const int idx = g_order[p];
  float4 b = g_sbox[p];
  out[p * 4 + 0] = keep ? b.x : -1.0f;
  out[p * 4 + 1] = keep ? b.y : -1.0f;
  out[p * 4 + 2] = keep ? b.z : -1.0f;
  out[p * 4 + 3] = keep ? b.w : -1.0f;
  out[4096 + p] = keep ? (float)g_labels[idx] : 0.0f;
  out[5120 + p] = keep ? g_sscore[p] : -1.0f;
  for (int c = 0; c < NCLS; ++c)
    out[6144 + p * NCLS + c] = keep ? g_confs[idx * NCLS + c] : -1.0f;
}

// ---------------- launch ----------------
extern "C" void kernel_launch(void* const* d_in, const int* in_sizes, int n_in,
                              void* d_out, int out_size) {
  const float* x = (const float*)d_in[0];
  const float* bb_w1 = (const float*)d_in[1];
  const float* bb_b1 = (const float*)d_in[2];
  const float* bb_w2 = (const float*)d_in[3];
  const float* bb_b2 = (const float*)d_in[4];
  const float* bb_w3 = (const float*)d_in[5];
  const float* bb_b3 = (const float*)d_in[6];
  const float* ex_w = (const float*)d_in[7];
  const float* ex_b = (const float*)d_in[8];
  const float* reg_w = (const float*)d_in[9];
  const float* reg_b = (const float*)d_in[10];
  const float* cls_w = (const float*)d_in[11];
  const float* cls_b = (const float*)d_in[12];

  // allow 83.2 KB dynamic smem (idempotent; host-side, not a stream op)
  cudaFuncSetAttribute(k_conv2, cudaFuncAttributeMaxDynamicSharedMemorySize,
                       CW_SMEM);
  cudaFuncSetAttribute(k_conv3, cudaFuncAttributeMaxDynamicSharedMemorySize,
                       CW_SMEM);
  cudaFuncSetAttribute(k_ex, cudaFuncAttributeMaxDynamicSharedMemorySize,
                       CW_SMEM);

  // only batch element 7 affects the output
  const float* x7 = x + (size_t)7 * 3 * 512 * 512;

  k_conv1<<<dim3(16, 16, 16), 256>>>(x7, bb_w1, bb_b1);
  k_conv2<<<dim3(4, 8, 16), 256, CW_SMEM>>>(bb_w2, bb_b2);
  k_conv3<<<dim3(2, 4, 64), 256, CW_SMEM>>>(bb_w3);
  k_comb3<<<1024, 256>>>(bb_b3);
  k_ex<<<dim3(1, 2, 128), 256, CW_SMEM>>>(ex_w);
  k_combex<<<256, 256>>>(ex_b);
  k_head<<<dim3(8, 25), 256>>>(reg_w, cls_w);
  k_prep<<<4, 256>>>(reg_b, cls_b);
  k_sort<<<1, 1024>>>();
  k_iou<<<1024, 1024>>>();
  k_nms<<<1, 32>>>();
  k_out<<<4, 256>>>((float*)d_out);
}

// round 11
// speedup vs baseline: 1.3030x; 1.0001x over previous
#include <cuda_runtime.h>
#include <math.h>

#define NCLS 21

// ---------------- f32x2 packed helpers (Blackwell; ptxas never auto-emits) ----
__device__ __forceinline__ unsigned long long f2_fma(unsigned long long a,
                                                     unsigned long long b,
                                                     unsigned long long c) {
  unsigned long long d;
  asm("fma.rn.f32x2 %0, %1, %2, %3;" : "=l"(d) : "l"(a), "l"(b), "l"(c));
  return d;
}
__device__ __forceinline__ unsigned long long f2_add(unsigned long long a,
                                                     unsigned long long b) {
  unsigned long long d;
  asm("add.rn.f32x2 %0, %1, %2;" : "=l"(d) : "l"(a), "l"(b));
  return d;
}
__device__ __forceinline__ unsigned long long f2_bcast(float x) {
  unsigned long long d;
  asm("mov.b64 %0, {%1, %1};" : "=l"(d) : "f"(x));
  return d;
}
__device__ __forceinline__ void f2_unpack(unsigned long long v, float& lo,
                                          float& hi) {
  asm("mov.b64 {%0, %1}, %2;" : "=f"(lo), "=f"(hi) : "l"(v));
}
#define F2_NEG1 0xBF800000BF800000ULL  // (-1.0f, -1.0f)

// ---------------- cp.async helpers ----------------
__device__ __forceinline__ void cp16(unsigned dst, const void* src,
                                     int srcsize) {
  asm volatile("cp.async.cg.shared.global [%0], [%1], 16, %2;" ::"r"(dst),
               "l"(src), "r"(srcsize));
}
__device__ __forceinline__ void cp_commit() {
  asm volatile("cp.async.commit_group;");
}
__device__ __forceinline__ void cp_wait_all() {
  asm volatile("cp.async.wait_group 0;");
}

// ---------------- scratch (static device globals; no allocation) ----------------
__device__ float g_h1[64 * 256 * 256];    // conv1 out
__device__ float g_h2[128 * 128 * 128];   // conv2 out
__device__ float g_h3[256 * 64 * 64];     // conv3 out
__device__ float g_h4[256 * 32 * 32];     // ex out
__device__ float g_c3part[2 * 256 * 64 * 64];  // conv3 split-C partials
__device__ float g_expart[4 * 256 * 32 * 32];  // ex split-C partials
__device__ float g_part[8 * 25 * 1024];   // head conv split-K partials
__device__ float g_locs[1024 * 4];
__device__ float g_confs[1024 * NCLS];
__device__ float g_scores[1024];
__device__ int g_labels[1024];
__device__ int g_order[1024];
__device__ float4 g_sbox[1024];
__device__ float g_sscore[1024];
__device__ unsigned g_validmask[32];
__device__ unsigned g_sup[1024 * 32];
__device__ unsigned g_keepmask[32];

// ================= conv1: 3->64ch, 512->256, stride2 ==========================
// 32x16 output tile, 2 horizontal px/thread, 8 couts/block, single staging pass
// (all 3 channels), one barrier. Per-output arithmetic: per-channel 9-term FMA
// chain + Kahan fold (channel order 0,1,2; tap order kh,kw) — IDENTICAL to the
// proven conv_body conv1 per-lane sequence -> bit-identical g_h1.
__global__ void __launch_bounds__(256) k_conv1(const float* __restrict__ x,
                                               const float* __restrict__ w,
                                               const float* __restrict__ b) {
  constexpr int IN_H = 34, ROWP = 68, IN_W4 = 17;
  constexpr int CHE4 = IN_H * IN_W4;  // 578
  constexpr int ELEMS4 = 3 * CHE4;    // 1734
  constexpr int LD4 = 7;
  __shared__ __align__(16) float s_in[3 * IN_H * ROWP];
  __shared__ __align__(16) float s_w[3 * 9 * 8];

  const int t = threadIdx.x;
  const int tx = t & 15, ty = t >> 4;
  const int ow0 = blockIdx.x * 32, oh0 = blockIdx.y * 16;
  const int co0 = blockIdx.z * 8;

  // stage weights: s_w[(ch*9+k)*8 + co]
  if (t < 216) {
    int co = t / 27, rem = t - co * 27;  // rem = ch*9 + k
    s_w[rem * 8 + co] = w[(size_t)(co0 + co) * 27 + rem];
  }
  // stage input (float4, zero-filled OOB; pad_lo=0, pad_hi=1)
#pragma unroll
  for (int i = 0; i < LD4; ++i) {
    int idx = t + i * 256;
    if (idx < ELEMS4) {
      int ch = idx / CHE4, rem = idx - ch * CHE4;
      int r = rem / IN_W4, c4 = rem - r * IN_W4;
      int ih = oh0 * 2 + r, iw = ow0 * 2 + c4 * 4;
      float4 v = make_float4(0.f, 0.f, 0.f, 0.f);
      if (ih < 512 && iw < 512)
        v = *(const float4*)(x + (size_t)ch * 512 * 512 + ih * 512 + iw);
      *(float4*)&s_in[(ch * IN_H + r) * ROWP + c4 * 4] = v;
    }
  }
  __syncthreads();

  unsigned long long acc2[8], cmp2[8];
#pragma unroll
  for (int i = 0; i < 8; ++i) { acc2[i] = 0ull; cmp2[i] = 0ull; }

#pragma unroll
  for (int ch = 0; ch < 3; ++ch) {
    unsigned long long wsA[4] = {0ull, 0ull, 0ull, 0ull};
    unsigned long long wsB[4] = {0ull, 0ull, 0ull, 0ull};
#pragma unroll
    for (int kh = 0; kh < 3; ++kh) {
      const int rbase = (ch * IN_H + ty * 2 + kh) * ROWP + tx * 4;
      float4 xr = *(const float4*)&s_in[rbase];
      float x4v = s_in[rbase + 4];
      float x0s[3] = {xr.x, xr.y, xr.z};
      float x1s[3] = {xr.z, xr.w, x4v};
#pragma unroll
      for (int kw = 0; kw < 3; ++kw) {
        unsigned long long x0 = f2_bcast(x0s[kw]);
        unsigned long long x1 = f2_bcast(x1s[kw]);
        const ulonglong2* wp = (const ulonglong2*)&s_w[(ch * 9 + kh * 3 + kw) * 8];
        ulonglong2 wa = wp[0], wb = wp[1];
        wsA[0] = f2_fma(x0, wa.x, wsA[0]);
        wsA[1] = f2_fma(x0, wa.y, wsA[1]);
        wsA[2] = f2_fma(x0, wb.x, wsA[2]);
        wsA[3] = f2_fma(x0, wb.y, wsA[3]);
        wsB[0] = f2_fma(x1, wa.x, wsB[0]);
        wsB[1] = f2_fma(x1, wa.y, wsB[1]);
        wsB[2] = f2_fma(x1, wb.x, wsB[2]);
        wsB[3] = f2_fma(x1, wb.y, wsB[3]);
      }
    }
    // Kahan fold per channel (matches proven conv1 numerics)
#pragma unroll
    for (int i = 0; i < 4; ++i) {
      unsigned long long y = f2_fma(cmp2[i], F2_NEG1, wsA[i]);
      unsigned long long tt = f2_add(acc2[i], y);
      unsigned long long t2 = f2_fma(acc2[i], F2_NEG1, tt);
      cmp2[i] = f2_fma(y, F2_NEG1, t2);
      acc2[i] = tt;
    }
#pragma unroll
    for (int i = 0; i < 4; ++i) {
      unsigned long long y = f2_fma(cmp2[4 + i], F2_NEG1, wsB[i]);
      unsigned long long tt = f2_add(acc2[4 + i], y);
      unsigned long long t2 = f2_fma(acc2[4 + i], F2_NEG1, tt);
      cmp2[4 + i] = f2_fma(y, F2_NEG1, t2);
      acc2[4 + i] = tt;
    }
  }

  const int oh = oh0 + ty;
  const int ow = ow0 + tx * 2;
#pragma unroll
  for (int px = 0; px < 2; ++px) {
#pragma unroll
    for (int i = 0; i < 4; ++i) {
      float lo, hi;
      f2_unpack(acc2[px * 4 + i], lo, hi);
      lo = fmaxf(lo + b[co0 + 2 * i], 0.f);
      hi = fmaxf(hi + b[co0 + 2 * i + 1], 0.f);
      g_h1[(size_t)(co0 + 2 * i) * 65536 + (size_t)oh * 256 + ow + px] = lo;
      g_h1[(size_t)(co0 + 2 * i + 1) * 65536 + (size_t)oh * 256 + ow + px] = hi;
    }
  }
}

// ============= wide conv: 32x16 tile, 2 horizontal px/thread, 8 couts ========
// (R10-proven: cp.async double-buffered, one barrier per 4-channel group)
template <int CINFULL, bool FINAL>
__device__ __forceinline__ void conv_wide(const float* __restrict__ in,
                                          const float* __restrict__ wgt,
                                          const float* __restrict__ bias,
                                          float* __restrict__ out, int Hin,
                                          int Win, int Hout, int Wout,
                                          int c_begin, int co0) {
  constexpr int WCH = 32, NCH = 4;
  constexpr int IN_H = 34, ROWP = 68;
  constexpr int IN_W4 = 17;
  constexpr int CHE4 = IN_H * IN_W4;
  constexpr int ELEMS4 = NCH * CHE4;
  constexpr int LD4 = (ELEMS4 + 255) / 256;
  constexpr int G = WCH / NCH;
  constexpr int NW = WCH * 9 * 8;
  constexpr int BUFSZ = NCH * IN_H * ROWP;

  extern __shared__ float smem_dyn[];
  float* s_in = smem_dyn;
  float* s_w = smem_dyn + 2 * BUFSZ;

  const int t = threadIdx.x;
  const int tx = t & 15, ty = t >> 4;
  const int ow0 = blockIdx.x * 32, oh0 = blockIdx.y * 16;
  const int HW = Hin * Win;

  int goff4[LD4], soff4[LD4];
#pragma unroll
  for (int i = 0; i < LD4; ++i) {
    int idx = t + i * 256;
    int ch = idx / CHE4;
    int rem = idx - ch * CHE4;
    int r = rem / IN_W4, c4 = rem - r * IN_W4;
    int ih = oh0 * 2 + r, iw = ow0 * 2 + c4 * 4;
    bool slot = (idx < ELEMS4);
    bool ok = slot && ((unsigned)ih < (unsigned)Hin) &&
              ((unsigned)iw < (unsigned)Win);
    goff4[i] = ok ? (ch * HW + ih * Win + iw) : -1;
    soff4[i] = slot ? ((ch * IN_H + r) * ROWP + c4 * 4) : -1;
  }

  unsigned long long acc2[8], cmp2[8];
#pragma unroll
  for (int i = 0; i < 8; ++i) { acc2[i] = 0ull; cmp2[i] = 0ull; }

  for (int chunk = 0; chunk < 2; ++chunk) {
    const int c0 = c_begin + chunk * WCH;
    __syncthreads();
#pragma unroll
    for (int i = 0; i < 9; ++i) {
      int idx = t + i * 256;
      int co = idx / (WCH * 9);
      int rem = idx - co * (WCH * 9);
      int ccg = rem / 9, k = rem - ccg * 9;
      s_w[(ccg * 9 + k) * 8 + co] =
          wgt[(size_t)(co0 + co) * CINFULL * 9 + (size_t)(c0 + ccg) * 9 + k];
    }
    {
      const float* inb = in + (size_t)c0 * HW;
      unsigned bufb = (unsigned)__cvta_generic_to_shared(s_in);
#pragma unroll
      for (int i = 0; i < LD4; ++i)
        if (soff4[i] >= 0)
          cp16(bufb + (unsigned)soff4[i] * 4,
               inb + (goff4[i] >= 0 ? goff4[i] : 0), goff4[i] >= 0 ? 16 : 0);
      cp_commit();
    }
    for (int g = 0; g < G; ++g) {
      cp_wait_all();
      __syncthreads();
      if (g + 1 < G) {
        const float* inb = in + (size_t)(c0 + (g + 1) * NCH) * HW;
        unsigned bufb = (unsigned)__cvta_generic_to_shared(
            s_in + ((g + 1) & 1) * BUFSZ);
#pragma unroll
        for (int i = 0; i < LD4; ++i)
          if (soff4[i] >= 0)
            cp16(bufb + (unsigned)soff4[i] * 4,
                 inb + (goff4[i] >= 0 ? goff4[i] : 0), goff4[i] >= 0 ? 16 : 0);
        cp_commit();
      }
      const float* buf = s_in + (g & 1) * BUFSZ;

#pragma unroll
      for (int sub = 0; sub < 2; ++sub) {
        unsigned long long wsA[4] = {0ull, 0ull, 0ull, 0ull};
        unsigned long long wsB[4] = {0ull, 0ull, 0ull, 0ull};
#pragma unroll
        for (int cc = 0; cc < 2; ++cc) {
          const int chl = sub * 2 + cc;
#pragma unroll
          for (int kh = 0; kh < 3; ++kh) {
            const int rbase = (chl * IN_H + ty * 2 + kh) * ROWP + tx * 4;
            float4 xr = *(const float4*)&buf[rbase];
            float x4v = buf[rbase + 4];
            float x0s[3] = {xr.x, xr.y, xr.z};
            float x1s[3] = {xr.z, xr.w, x4v};
#pragma unroll
            for (int kw = 0; kw < 3; ++kw) {
              unsigned long long x0 = f2_bcast(x0s[kw]);
              unsigned long long x1 = f2_bcast(x1s[kw]);
              const ulonglong2* wp =
                  (const ulonglong2*)&s_w[((g * NCH + chl) * 9 + kh * 3 + kw) *
                                          8];
              ulonglong2 wa = wp[0], wb = wp[1];
              wsA[0] = f2_fma(x0, wa.x, wsA[0]);
              wsA[1] = f2_fma(x0, wa.y, wsA[1]);
              wsA[2] = f2_fma(x0, wb.x, wsA[2]);
              wsA[3] = f2_fma(x0, wb.y, wsA[3]);
              wsB[0] = f2_fma(x1, wa.x, wsB[0]);
              wsB[1] = f2_fma(x1, wa.y, wsB[1]);
              wsB[2] = f2_fma(x1, wb.x, wsB[2]);
              wsB[3] = f2_fma(x1, wb.y, wsB[3]);
            }
          }
        }
#pragma unroll
        for (int i = 0; i < 4; ++i) {
          unsigned long long y = f2_fma(cmp2[i], F2_NEG1, wsA[i]);
          unsigned long long tt = f2_add(acc2[i], y);
          unsigned long long t2 = f2_fma(acc2[i], F2_NEG1, tt);
          cmp2[i] = f2_fma(y, F2_NEG1, t2);
          acc2[i] = tt;
        }
#pragma unroll
        for (int i = 0; i < 4; ++i) {
          unsigned long long y = f2_fma(cmp2[4 + i], F2_NEG1, wsB[i]);
          unsigned long long tt = f2_add(acc2[4 + i], y);
          unsigned long long t2 = f2_fma(acc2[4 + i], F2_NEG1, tt);
          cmp2[4 + i] = f2_fma(y, F2_NEG1, t2);
          acc2[4 + i] = tt;
        }
      }
    }
  }

  const int oh = oh0 + ty;
  const int ow = ow0 + tx * 2;
#pragma unroll
  for (int px = 0; px < 2; ++px) {
#pragma unroll
    for (int i = 0; i < 4; ++i) {
      float lo, hi;
      f2_unpack(acc2[px * 4 + i], lo, hi);
      if (FINAL) {
        lo = fmaxf(lo + bias[co0 + 2 * i], 0.f);
        hi = fmaxf(hi + bias[co0 + 2 * i + 1], 0.f);
      }
      out[(size_t)(co0 + 2 * i) * Hout * Wout + (size_t)oh * Wout + ow + px] =
          lo;
      out[(size_t)(co0 + 2 * i + 1) * Hout * Wout + (size_t)oh * Wout + ow +
          px] = hi;
    }
  }
}

static const int CW_SMEM = (2 * 4 * 34 * 68 + 32 * 9 * 8) * 4;  // 83200 B

__global__ void __launch_bounds__(256, 2) k_conv2(const float* w,
                                                  const float* b) {
  conv_wide<64, true>(g_h1, w, b, g_h2, 256, 256, 128, 128, 0, blockIdx.z * 8);
}
__global__ void __launch_bounds__(256, 2) k_conv3(const float* w) {
  const int split = blockIdx.z >> 5;
  const int co0 = (blockIdx.z & 31) * 8;
  conv_wide<128, false>(g_h2, w, nullptr,
                        g_c3part + (size_t)split * 256 * 64 * 64, 128, 128, 64,
                        64, split * 64, co0);
}
// combine with 4 float4/thread ILP (same fp64 math per element)
__global__ void k_comb3(const float* __restrict__ b) {
  const int tid = blockIdx.x * 256 + threadIdx.x;  // 65536 threads
#pragma unroll
  for (int k = 0; k < 4; ++k) {
    const int i4 = (tid + k * 65536) * 4;
    const int co = i4 >> 12;
    const double bv = (double)b[co];
    float4 a = *(const float4*)&g_c3part[i4];
    float4 c = *(const float4*)&g_c3part[1048576 + i4];
    float4 o;
    o.x = fmaxf((float)(((double)a.x + (double)c.x) + bv), 0.f);
    o.y = fmaxf((float)(((double)a.y + (double)c.y) + bv), 0.f);
    o.z = fmaxf((float)(((double)a.z + (double)c.z) + bv), 0.f);
    o.w = fmaxf((float)(((double)a.w + (double)c.w) + bv), 0.f);
    *(float4*)&g_h3[i4] = o;
  }
}
__global__ void __launch_bounds__(256, 2) k_ex(const float* w) {
  const int split = blockIdx.z >> 5;
  const int co0 = (blockIdx.z & 31) * 8;
  conv_wide<256, false>(g_h3, w, nullptr,
                        g_expart + (size_t)split * 256 * 32 * 32, 64, 64, 32,
                        32, split * 64, co0);
}
__global__ void k_combex(const float* __restrict__ b) {
  const int tid = blockIdx.x * 256 + threadIdx.x;  // 16384 threads
#pragma unroll
  for (int k = 0; k < 4; ++k) {
    const int i4 = (tid + k * 16384) * 4;
    const int co = i4 >> 10;
    const double bv = (double)b[co];
    float4 p0 = *(const float4*)&g_expart[i4];
    float4 p1 = *(const float4*)&g_expart[262144 + i4];
    float4 p2 = *(const float4*)&g_expart[2 * 262144 + i4];
    float4 p3 = *(const float4*)&g_expart[3 * 262144 + i4];
    float4 o;
    o.x = fmaxf((float)((((double)p0.x + (double)p1.x) + (double)p2.x) +
                        (double)p3.x + bv), 0.f);
    o.y = fmaxf((float)((((double)p0.y + (double)p1.y) + (double)p2.y) +
                        (double)p3.y + bv), 0.f);
    o.z = fmaxf((float)((((double)p0.z + (double)p1.z) + (double)p2.z) +
                        (double)p3.z + bv), 0.f);
    o.w = fmaxf((float)((((double)p0.w + (double)p1.w) + (double)p2.w) +
                        (double)p3.w + bv), 0.f);
    *(float4*)&g_h4[i4] = o;
  }
}

// ---------------- head convs (reg 4ch + cls 21ch), stride1 pad1, split-K -------
__global__ void __launch_bounds__(256) k_head(const float* __restrict__ reg_w,
                                              const float* __restrict__ cls_w) {
  constexpr int IN_T = 34, ROWP = 35, NCH = 4;
  constexpr int ELEMS = NCH * IN_T * IN_T;
  constexpr int LD = (ELEMS + 255) / 256;
  const int split = blockIdx.x, co = blockIdx.y;
  const float* w = (co < 4) ? (reg_w + (size_t)co * 256 * 9)
                            : (cls_w + (size_t)(co - 4) * 256 * 9);
  __shared__ float s_in[NCH * IN_T * ROWP];
  __shared__ float s_w[32 * 9];
  const int t = threadIdx.x;

  int goff[LD], soff[LD];
#pragma unroll
  for (int i = 0; i < LD; ++i) {
    int idx = t + i * 256;
    int ch = idx / (IN_T * IN_T);
    int rem = idx - ch * (IN_T * IN_T);
    int r = rem / IN_T, c = rem - r * IN_T;
    int ih = r - 1, iw = c - 1;
    bool ok = (idx < ELEMS) && ((unsigned)ih < 32u) && ((unsigned)iw < 32u);
    goff[i] = ok ? (ch * 1024 + ih * 32 + iw) : -1;
    soff[i] = (ch * IN_T + r) * ROWP + c;
  }
  for (int idx = t; idx < 32 * 9; idx += 256)
    s_w[idx] = w[(size_t)(split * 32 + idx / 9) * 9 + (idx % 9)];

  float acc[4] = {0.f, 0.f, 0.f, 0.f};
  float cmp[4] = {0.f, 0.f, 0.f, 0.f};

  float rbuf[LD];
  {
    const float* inb = g_h4 + (size_t)split * 32 * 1024;
#pragma unroll
    for (int i = 0; i < LD; ++i) rbuf[i] = (goff[i] >= 0) ? inb[goff[i]] : 0.f;
  }
  for (int g = 0; g < 8; ++g) {
    __syncthreads();
#pragma unroll
    for (int i = 0; i < LD; ++i)
      if (t + i * 256 < ELEMS) s_in[soff[i]] = rbuf[i];
    if (g + 1 < 8) {
      const float* inb = g_h4 + (size_t)(split * 32 + (g + 1) * NCH) * 1024;
#pragma unroll
      for (int i = 0; i < LD; ++i)
        rbuf[i] = (goff[i] >= 0) ? inb[goff[i]] : 0.f;
    }
    __syncthreads();

#pragma unroll
    for (int cc = 0; cc < NCH; ++cc) {
      float wr[9];
#pragma unroll
      for (int k = 0; k < 9; ++k) wr[k] = s_w[(g * NCH + cc) * 9 + k];
#pragma unroll
      for (int px = 0; px < 4; ++px) {
        int p = t + px * 256;
        int oh = p >> 5, ow = p & 31;
        float a = 0.f;
#pragma unroll
        for (int kh = 0; kh < 3; ++kh)
#pragma unroll
          for (int kw = 0; kw < 3; ++kw)
            a = fmaf(s_in[(cc * IN_T + oh + kh) * ROWP + ow + kw],
                     wr[kh * 3 + kw], a);
        float y = a - cmp[px];
        float tt = acc[px] + y;
        cmp[px] = (tt - acc[px]) - y;
        acc[px] = tt;
      }
    }
  }
#pragma unroll
  for (int px = 0; px < 4; ++px)
    g_part[(size_t)(split * 25 + co) * 1024 + t + px * 256] = acc[px];
}

// ---------------- reduce partials (double) + transpose + softmax (double) ------
__global__ void k_prep(const float* __restrict__ reg_b,
                       const float* __restrict__ cls_b) {
  const int a = blockIdx.x * 256 + threadIdx.x;  // anchor 0..1023
#pragma unroll
  for (int j = 0; j < 4; ++j) {
    double s = 0.0;
    for (int sp = 0; sp < 8; ++sp)
      s += (double)g_part[(size_t)(sp * 25 + j) * 1024 + a];
    g_locs[a * 4 + j] = (float)(s + (double)reg_b[j]);
  }
  float conf[NCLS];
  for (int c = 0; c < NCLS; ++c) {
    double s = 0.0;
    for (int sp = 0; sp < 8; ++sp)
      s += (double)g_part[(size_t)(sp * 25 + 4 + c) * 1024 + a];
    conf[c] = (float)(s + (double)cls_b[c]);
    g_confs[a * NCLS + c] = conf[c];
  }
  float m = conf[0];
  int lab = 0;
  for (int c = 1; c < NCLS; ++c)
    if (conf[c] > m) { m = conf[c]; lab = c; }
  double sum = 0.0;
  for (int c = 0; c < NCLS; ++c) sum += exp((double)conf[c] - (double)m);
  g_scores[a] = (float)(1.0 / sum);  // max softmax prob
  g_labels[a] = lab;
}

// ---------------- stable bitonic sort by descending score ----------------
__global__ void k_sort() {
  __shared__ float s[1024];
  __shared__ int si[1024];
  const int t = threadIdx.x;
  s[t] = g_scores[t];
  si[t] = t;
  __syncthreads();
  for (int k = 2; k <= 1024; k <<= 1) {
    for (int j = k >> 1; j > 0; j >>= 1) {
      int ixj = t ^ j;
      if (ixj > t) {
        float sa = s[t], sb = s[ixj];
        int ia = si[t], ib = si[ixj];
        bool aFirst = (sa > sb) || (sa == sb && ia < ib);  // stable desc
        bool dirUp = ((t & k) == 0);
        if (dirUp ? !aFirst : aFirst) {
          s[t] = sb; s[ixj] = sa;
          si[t] = ib; si[ixj] = ia;
        }
      }
      __syncthreads();
    }
  }
  const int idx = si[t];
  g_order[t] = idx;
  g_sscore[t] = s[t];
  g_sbox[t] = make_float4(g_locs[idx * 4 + 0], g_locs[idx * 4 + 1],
                          g_locs[idx * 4 + 2], g_locs[idx * 4 + 3]);
  unsigned vb = __ballot_sync(0xffffffffu, s[t] > 0.04f);
  if ((t & 31) == 0) g_validmask[t >> 5] = vb;
}

// ---------------- pairwise IoU suppression bitmask (double precision) ----------
__global__ void k_iou() {
  const int i = blockIdx.x, j = threadIdx.x;
  float4 bi = g_sbox[i];
  float4 bj = g_sbox[j];
  double ai = ((double)bi.z - (double)bi.x) * ((double)bi.w - (double)bi.y);
  double aj = ((double)bj.z - (double)bj.x) * ((double)bj.w - (double)bj.y);
  double ltx = fmax((double)bi.x, (double)bj.x);
  double lty = fmax((double)bi.y, (double)bj.y);
  double rbx = fmin((double)bi.z, (double)bj.z);
  double rby = fmin((double)bi.w, (double)bj.w);
  double inter = fmax(rbx - ltx, 0.0) * fmax(rby - lty, 0.0);
  double uni = ai + aj - inter;
  double iou = inter / (uni + 1e-9);
  unsigned m = __ballot_sync(0xffffffffu, iou > 0.5);
  if ((j & 31) == 0) g_sup[i * 32 + (j >> 5)] = m;
}

// ---------------- sequential greedy NMS on bitmask, single warp ----------------
__global__ void k_nms() {
  const int lane = threadIdx.x;  // 32 threads
  unsigned kw = 0;
  const unsigned validw = g_validmask[lane];
  const int CH = 8;
  unsigned buf[CH], nbuf[CH];
#pragma unroll
  for (int q = 0; q < CH; ++q) buf[q] = g_sup[q * 32 + lane];
  for (int c = 0; c < 1024 / CH; ++c) {
    if (c + 1 < 1024 / CH) {
#pragma unroll
      for (int q = 0; q < CH; ++q)
        nbuf[q] = g_sup[((c + 1) * CH + q) * 32 + lane];
    }
#pragma unroll
    for (int q = 0; q < CH; ++q) {
      int i = c * CH + q;
      bool sup = __any_sync(0xffffffffu, (buf[q] & kw) != 0u);
      // only the owning lane needs the valid bit -> no shfl
      if (!sup && lane == (i >> 5)) {
        if ((validw >> (i & 31)) & 1u) kw |= (1u << (i & 31));
      }
    }
#pragma unroll
    for (int q = 0; q < CH; ++q) buf[q] = nbuf[q];
  }
  g_keepmask[lane] = kw;
}

// ---------------- masked gather to output ----------------
// layout (float32): boxes[1024*4] | labels[1024] | scores[1024] | confs[1024*21]
__global__ void k_out(float* __restrict__ out) {
  const int p = blockIdx.x * 256 + threadIdx.x;  // 0..1023
  const bool keep = (g_keepmask[p >> 5] >> (p & 31)) & 1u;
  const int idx = g_order[p];
  float4 b = g_sbox[p];
  out[p * 4 + 0] = keep ? b.x : -1.0f;
  out[p * 4 + 1] = keep ? b.y : -1.0f;
  out[p * 4 + 2] = keep ? b.z : -1.0f;
  out[p * 4 + 3] = keep ? b.w : -1.0f;
  out[4096 + p] = keep ? (float)g_labels[idx] : 0.0f;
  out[5120 + p] = keep ? g_sscore[p] : -1.0f;
  for (int c = 0; c < NCLS; ++c)
    out[6144 + p * NCLS + c] = keep ? g_confs[idx * NCLS + c] : -1.0f;
}

// ---------------- launch ----------------
extern "C" void kernel_launch(void* const* d_in, const int* in_sizes, int n_in,
                              void* d_out, int out_size) {
  const float* x = (const float*)d_in[0];
  const float* bb_w1 = (const float*)d_in[1];
  const float* bb_b1 = (const float*)d_in[2];
  const float* bb_w2 = (const float*)d_in[3];
  const float* bb_b2 = (const float*)d_in[4];
  const float* bb_w3 = (const float*)d_in[5];
  const float* bb_b3 = (const float*)d_in[6];
  const float* ex_w = (const float*)d_in[7];
  const float* ex_b = (const float*)d_in[8];
  const float* reg_w = (const float*)d_in[9];
  const float* reg_b = (const float*)d_in[10];
  const float* cls_w = (const float*)d_in[11];
  const float* cls_b = (const float*)d_in[12];

  cudaFuncSetAttribute(k_conv2, cudaFuncAttributeMaxDynamicSharedMemorySize,
                       CW_SMEM);
  cudaFuncSetAttribute(k_conv3, cudaFuncAttributeMaxDynamicSharedMemorySize,
                       CW_SMEM);
  cudaFuncSetAttribute(k_ex, cudaFuncAttributeMaxDynamicSharedMemorySize,
                       CW_SMEM);

  // only batch element 7 affects the output
  const float* x7 = x + (size_t)7 * 3 * 512 * 512;

  k_conv1<<<dim3(8, 16, 8), 256>>>(x7, bb_w1, bb_b1);
  k_conv2<<<dim3(4, 8, 16), 256, CW_SMEM>>>(bb_w2, bb_b2);
  k_conv3<<<dim3(2, 4, 64), 256, CW_SMEM>>>(bb_w3);
  k_comb3<<<256, 256>>>(bb_b3);
  k_ex<<<dim3(1, 2, 128), 256, CW_SMEM>>>(ex_w);
  k_combex<<<64, 256>>>(ex_b);
  k_head<<<dim3(8, 25), 256>>>(reg_w, cls_w);
  k_prep<<<4, 256>>>(reg_b, cls_b);
  k_sort<<<1, 1024>>>();
  k_iou<<<1024, 1024>>>();
  k_nms<<<1, 32>>>();
  k_out<<<4, 256>>>((float*)d_out);
}

// round 12
// speedup vs baseline: 1.3414x; 1.0295x over previous
#include <cuda_runtime.h>
#include <math.h>

#define NCLS 21

// ---------------- f32x2 packed helpers (Blackwell; ptxas never auto-emits) ----
__device__ __forceinline__ unsigned long long f2_fma(unsigned long long a,
                                                     unsigned long long b,
                                                     unsigned long long c) {
  unsigned long long d;
  asm("fma.rn.f32x2 %0, %1, %2, %3;" : "=l"(d) : "l"(a), "l"(b), "l"(c));
  return d;
}
__device__ __forceinline__ unsigned long long f2_add(unsigned long long a,
                                                     unsigned long long b) {
  unsigned long long d;
  asm("add.rn.f32x2 %0, %1, %2;" : "=l"(d) : "l"(a), "l"(b));
  return d;
}
__device__ __forceinline__ unsigned long long f2_bcast(float x) {
  unsigned long long d;
  asm("mov.b64 %0, {%1, %1};" : "=l"(d) : "f"(x));
  return d;
}
__device__ __forceinline__ void f2_unpack(unsigned long long v, float& lo,
                                          float& hi) {
  asm("mov.b64 {%0, %1}, %2;" : "=f"(lo), "=f"(hi) : "l"(v));
}
#define F2_NEG1 0xBF800000BF800000ULL  // (-1.0f, -1.0f)

// ---------------- cp.async helpers ----------------
__device__ __forceinline__ void cp16(unsigned dst, const void* src,
                                     int srcsize) {
  asm volatile("cp.async.cg.shared.global [%0], [%1], 16, %2;" ::"r"(dst),
               "l"(src), "r"(srcsize));
}
__device__ __forceinline__ void cp_commit() {
  asm volatile("cp.async.commit_group;");
}
__device__ __forceinline__ void cp_wait_all() {
  asm volatile("cp.async.wait_group 0;");
}

// ---------------- scratch (static device globals; no allocation) ----------------
__device__ float g_h1[64 * 256 * 256];    // conv1 out
__device__ float g_h2[128 * 128 * 128];   // conv2 out
__device__ float g_h3[256 * 64 * 64];     // conv3 out
__device__ float g_h4[256 * 32 * 32];     // ex out
__device__ float g_c3part[2 * 256 * 64 * 64];  // conv3 split-C partials
__device__ float g_expart[4 * 256 * 32 * 32];  // ex split-C partials
__device__ float g_part[8 * 25 * 1024];   // head conv split-K partials
__device__ float g_locs[1024 * 4];
__device__ float g_confs[1024 * NCLS];
__device__ float g_scores[1024];
__device__ int g_labels[1024];
__device__ int g_order[1024];
__device__ float4 g_sbox[1024];
__device__ float g_sscore[1024];
__device__ unsigned g_validmask[32];
__device__ unsigned g_sup[1024 * 32];
__device__ unsigned g_keepmask[32];

// ================= conv1: 3->64ch, 512->256, stride2 (R11-proven) =============
__global__ void __launch_bounds__(256) k_conv1(const float* __restrict__ x,
                                               const float* __restrict__ w,
                                               const float* __restrict__ b) {
  constexpr int IN_H = 34, ROWP = 68, IN_W4 = 17;
  constexpr int CHE4 = IN_H * IN_W4;  // 578
  constexpr int ELEMS4 = 3 * CHE4;    // 1734
  constexpr int LD4 = 7;
  __shared__ __align__(16) float s_in[3 * IN_H * ROWP];
  __shared__ __align__(16) float s_w[3 * 9 * 8];

  const int t = threadIdx.x;
  const int tx = t & 15, ty = t >> 4;
  const int ow0 = blockIdx.x * 32, oh0 = blockIdx.y * 16;
  const int co0 = blockIdx.z * 8;

  if (t < 216) {
    int co = t / 27, rem = t - co * 27;
    s_w[rem * 8 + co] = w[(size_t)(co0 + co) * 27 + rem];
  }
#pragma unroll
  for (int i = 0; i < LD4; ++i) {
    int idx = t + i * 256;
    if (idx < ELEMS4) {
      int ch = idx / CHE4, rem = idx - ch * CHE4;
      int r = rem / IN_W4, c4 = rem - r * IN_W4;
      int ih = oh0 * 2 + r, iw = ow0 * 2 + c4 * 4;
      float4 v = make_float4(0.f, 0.f, 0.f, 0.f);
      if (ih < 512 && iw < 512)
        v = *(const float4*)(x + (size_t)ch * 512 * 512 + ih * 512 + iw);
      *(float4*)&s_in[(ch * IN_H + r) * ROWP + c4 * 4] = v;
    }
  }
  __syncthreads();

  unsigned long long acc2[8], cmp2[8];
#pragma unroll
  for (int i = 0; i < 8; ++i) { acc2[i] = 0ull; cmp2[i] = 0ull; }

#pragma unroll
  for (int ch = 0; ch < 3; ++ch) {
    unsigned long long wsA[4] = {0ull, 0ull, 0ull, 0ull};
    unsigned long long wsB[4] = {0ull, 0ull, 0ull, 0ull};
#pragma unroll
    for (int kh = 0; kh < 3; ++kh) {
      const int rbase = (ch * IN_H + ty * 2 + kh) * ROWP + tx * 4;
      float4 xr = *(const float4*)&s_in[rbase];
      float x4v = s_in[rbase + 4];
      float x0s[3] = {xr.x, xr.y, xr.z};
      float x1s[3] = {xr.z, xr.w, x4v};
#pragma unroll
      for (int kw = 0; kw < 3; ++kw) {
        unsigned long long x0 = f2_bcast(x0s[kw]);
        unsigned long long x1 = f2_bcast(x1s[kw]);
        const ulonglong2* wp = (const ulonglong2*)&s_w[(ch * 9 + kh * 3 + kw) * 8];
        ulonglong2 wa = wp[0], wb = wp[1];
        wsA[0] = f2_fma(x0, wa.x, wsA[0]);
        wsA[1] = f2_fma(x0, wa.y, wsA[1]);
        wsA[2] = f2_fma(x0, wb.x, wsA[2]);
        wsA[3] = f2_fma(x0, wb.y, wsA[3]);
        wsB[0] = f2_fma(x1, wa.x, wsB[0]);
        wsB[1] = f2_fma(x1, wa.y, wsB[1]);
        wsB[2] = f2_fma(x1, wb.x, wsB[2]);
        wsB[3] = f2_fma(x1, wb.y, wsB[3]);
      }
    }
#pragma unroll
    for (int i = 0; i < 4; ++i) {
      unsigned long long y = f2_fma(cmp2[i], F2_NEG1, wsA[i]);
      unsigned long long tt = f2_add(acc2[i], y);
      unsigned long long t2 = f2_fma(acc2[i], F2_NEG1, tt);
      cmp2[i] = f2_fma(y, F2_NEG1, t2);
      acc2[i] = tt;
    }
#pragma unroll
    for (int i = 0; i < 4; ++i) {
      unsigned long long y = f2_fma(cmp2[4 + i], F2_NEG1, wsB[i]);
      unsigned long long tt = f2_add(acc2[4 + i], y);
      unsigned long long t2 = f2_fma(acc2[4 + i], F2_NEG1, tt);
      cmp2[4 + i] = f2_fma(y, F2_NEG1, t2);
      acc2[4 + i] = tt;
    }
  }

  const int oh = oh0 + ty;
  const int ow = ow0 + tx * 2;
#pragma unroll
  for (int px = 0; px < 2; ++px) {
#pragma unroll
    for (int i = 0; i < 4; ++i) {
      float lo, hi;
      f2_unpack(acc2[px * 4 + i], lo, hi);
      lo = fmaxf(lo + b[co0 + 2 * i], 0.f);
      hi = fmaxf(hi + b[co0 + 2 * i + 1], 0.f);
      g_h1[(size_t)(co0 + 2 * i) * 65536 + (size_t)oh * 256 + ow + px] = lo;
      g_h1[(size_t)(co0 + 2 * i + 1) * 65536 + (size_t)oh * 256 + ow + px] = hi;
    }
  }
}

// ============= wide conv: 32x16 tile, 2 horizontal px/thread, 8 couts ========
// cp.async double-buffered, one barrier per 4-channel group (R10-proven).
// NEW (R12): 36-term window chains (all 4 staged channels) with ONE Kahan fold
// per group — fold fma-pipe ops halved (the fma pipe is the measured binding
// constraint at FFMA2 rt~4/SMSP).
template <int CINFULL, bool FINAL>
__device__ __forceinline__ void conv_wide(const float* __restrict__ in,
                                          const float* __restrict__ wgt,
                                          const float* __restrict__ bias,
                                          float* __restrict__ out, int Hin,
                                          int Win, int Hout, int Wout,
                                          int c_begin, int co0) {
  constexpr int WCH = 32, NCH = 4;
  constexpr int IN_H = 34, ROWP = 68;
  constexpr int IN_W4 = 17;
  constexpr int CHE4 = IN_H * IN_W4;
  constexpr int ELEMS4 = NCH * CHE4;
  constexpr int LD4 = (ELEMS4 + 255) / 256;
  constexpr int G = WCH / NCH;
  constexpr int BUFSZ = NCH * IN_H * ROWP;

  extern __shared__ float smem_dyn[];
  float* s_in = smem_dyn;
  float* s_w = smem_dyn + 2 * BUFSZ;

  const int t = threadIdx.x;
  const int tx = t & 15, ty = t >> 4;
  const int ow0 = blockIdx.x * 32, oh0 = blockIdx.y * 16;
  const int HW = Hin * Win;

  int goff4[LD4], soff4[LD4];
#pragma unroll
  for (int i = 0; i < LD4; ++i) {
    int idx = t + i * 256;
    int ch = idx / CHE4;
    int rem = idx - ch * CHE4;
    int r = rem / IN_W4, c4 = rem - r * IN_W4;
    int ih = oh0 * 2 + r, iw = ow0 * 2 + c4 * 4;
    bool slot = (idx < ELEMS4);
    bool ok = slot && ((unsigned)ih < (unsigned)Hin) &&
              ((unsigned)iw < (unsigned)Win);
    goff4[i] = ok ? (ch * HW + ih * Win + iw) : -1;
    soff4[i] = slot ? ((ch * IN_H + r) * ROWP + c4 * 4) : -1;
  }

  unsigned long long acc2[8], cmp2[8];
#pragma unroll
  for (int i = 0; i < 8; ++i) { acc2[i] = 0ull; cmp2[i] = 0ull; }

  for (int chunk = 0; chunk < 2; ++chunk) {
    const int c0 = c_begin + chunk * WCH;
    __syncthreads();
#pragma unroll
    for (int i = 0; i < 9; ++i) {
      int idx = t + i * 256;
      int co = idx / (WCH * 9);
      int rem = idx - co * (WCH * 9);
      int ccg = rem / 9, k = rem - ccg * 9;
      s_w[(ccg * 9 + k) * 8 + co] =
          wgt[(size_t)(co0 + co) * CINFULL * 9 + (size_t)(c0 + ccg) * 9 + k];
    }
    {
      const float* inb = in + (size_t)c0 * HW;
      unsigned bufb = (unsigned)__cvta_generic_to_shared(s_in);
#pragma unroll
      for (int i = 0; i < LD4; ++i)
        if (soff4[i] >= 0)
          cp16(bufb + (unsigned)soff4[i] * 4,
               inb + (goff4[i] >= 0 ? goff4[i] : 0), goff4[i] >= 0 ? 16 : 0);
      cp_commit();
    }
    for (int g = 0; g < G; ++g) {
      cp_wait_all();
      __syncthreads();
      if (g + 1 < G) {
        const float* inb = in + (size_t)(c0 + (g + 1) * NCH) * HW;
        unsigned bufb = (unsigned)__cvta_generic_to_shared(
            s_in + ((g + 1) & 1) * BUFSZ);
#pragma unroll
        for (int i = 0; i < LD4; ++i)
          if (soff4[i] >= 0)
            cp16(bufb + (unsigned)soff4[i] * 4,
                 inb + (goff4[i] >= 0 ? goff4[i] : 0), goff4[i] >= 0 ? 16 : 0);
        cp_commit();
      }
      const float* buf = s_in + (g & 1) * BUFSZ;

      // 36-term window chains over the 4 staged channels (A=px0, B=px1)
      unsigned long long wsA[4] = {0ull, 0ull, 0ull, 0ull};
      unsigned long long wsB[4] = {0ull, 0ull, 0ull, 0ull};
#pragma unroll
      for (int chl = 0; chl < NCH; ++chl) {
#pragma unroll
        for (int kh = 0; kh < 3; ++kh) {
          const int rbase = (chl * IN_H + ty * 2 + kh) * ROWP + tx * 4;
          float4 xr = *(const float4*)&buf[rbase];
          float x4v = buf[rbase + 4];
          float x0s[3] = {xr.x, xr.y, xr.z};
          float x1s[3] = {xr.z, xr.w, x4v};
#pragma unroll
          for (int kw = 0; kw < 3; ++kw) {
            unsigned long long x0 = f2_bcast(x0s[kw]);
            unsigned long long x1 = f2_bcast(x1s[kw]);
            const ulonglong2* wp =
                (const ulonglong2*)&s_w[((g * NCH + chl) * 9 + kh * 3 + kw) *
                                        8];
            ulonglong2 wa = wp[0], wb = wp[1];
            wsA[0] = f2_fma(x0, wa.x, wsA[0]);
            wsA[1] = f2_fma(x0, wa.y, wsA[1]);
            wsA[2] = f2_fma(x0, wb.x, wsA[2]);
            wsA[3] = f2_fma(x0, wb.y, wsA[3]);
            wsB[0] = f2_fma(x1, wa.x, wsB[0]);
            wsB[1] = f2_fma(x1, wa.y, wsB[1]);
            wsB[2] = f2_fma(x1, wb.x, wsB[2]);
            wsB[3] = f2_fma(x1, wb.y, wsB[3]);
          }
        }
      }
      // ONE Kahan fold per 4-channel group
#pragma unroll
      for (int i = 0; i < 4; ++i) {
        unsigned long long y = f2_fma(cmp2[i], F2_NEG1, wsA[i]);
        unsigned long long tt = f2_add(acc2[i], y);
        unsigned long long t2 = f2_fma(acc2[i], F2_NEG1, tt);
        cmp2[i] = f2_fma(y, F2_NEG1, t2);
        acc2[i] = tt;
      }
#pragma unroll
      for (int i = 0; i < 4; ++i) {
        unsigned long long y = f2_fma(cmp2[4 + i], F2_NEG1, wsB[i]);
        unsigned long long tt = f2_add(acc2[4 + i], y);
        unsigned long long t2 = f2_fma(acc2[4 + i], F2_NEG1, tt);
        cmp2[4 + i] = f2_fma(y, F2_NEG1, t2);
        acc2[4 + i] = tt;
      }
    }
  }

  const int oh = oh0 + ty;
  const int ow = ow0 + tx * 2;
#pragma unroll
  for (int px = 0; px < 2; ++px) {
#pragma unroll
    for (int i = 0; i < 4; ++i) {
      float lo, hi;
      f2_unpack(acc2[px * 4 + i], lo, hi);
      if (FINAL) {
        lo = fmaxf(lo + bias[co0 + 2 * i], 0.f);
        hi = fmaxf(hi + bias[co0 + 2 * i + 1], 0.f);
      }
      out[(size_t)(co0 + 2 * i) * Hout * Wout + (size_t)oh * Wout + ow + px] =
          lo;
      out[(size_t)(co0 + 2 * i + 1) * Hout * Wout + (size_t)oh * Wout + ow +
          px] = hi;
    }
  }
}

static const int CW_SMEM = (2 * 4 * 34 * 68 + 32 * 9 * 8) * 4;  // 83200 B

__global__ void __launch_bounds__(256, 2) k_conv2(const float* w,
                                                  const float* b) {
  conv_wide<64, true>(g_h1, w, b, g_h2, 256, 256, 128, 128, 0, blockIdx.z * 8);
}
__global__ void __launch_bounds__(256, 2) k_conv3(const float* w) {
  const int split = blockIdx.z >> 5;
  const int co0 = (blockIdx.z & 31) * 8;
  conv_wide<128, false>(g_h2, w, nullptr,
                        g_c3part + (size_t)split * 256 * 64 * 64, 128, 128, 64,
                        64, split * 64, co0);
}
// combine kernels (R10-proven best: 1 float4/thread, max blocks)
__global__ void k_comb3(const float* __restrict__ b) {
  const int i4 = (blockIdx.x * 256 + threadIdx.x) * 4;
  const int co = i4 >> 12;
  const double bv = (double)b[co];
  float4 a = *(const float4*)&g_c3part[i4];
  float4 c = *(const float4*)&g_c3part[1048576 + i4];
  float4 o;
  o.x = fmaxf((float)(((double)a.x + (double)c.x) + bv), 0.f);
  o.y = fmaxf((float)(((double)a.y + (double)c.y) + bv), 0.f);
  o.z = fmaxf((float)(((double)a.z + (double)c.z) + bv), 0.f);
  o.w = fmaxf((float)(((double)a.w + (double)c.w) + bv), 0.f);
  *(float4*)&g_h3[i4] = o;
}
__global__ void __launch_bounds__(256, 2) k_ex(const float* w) {
  const int split = blockIdx.z >> 5;
  const int co0 = (blockIdx.z & 31) * 8;
  conv_wide<256, false>(g_h3, w, nullptr,
                        g_expart + (size_t)split * 256 * 32 * 32, 64, 64, 32,
                        32, split * 64, co0);
}
__global__ void k_combex(const float* __restrict__ b) {
  const int i4 = (blockIdx.x * 256 + threadIdx.x) * 4;
  const int co = i4 >> 10;
  const double bv = (double)b[co];
  float4 p0 = *(const float4*)&g_expart[i4];
  float4 p1 = *(const float4*)&g_expart[262144 + i4];
  float4 p2 = *(const float4*)&g_expart[2 * 262144 + i4];
  float4 p3 = *(const float4*)&g_expart[3 * 262144 + i4];
  float4 o;
  o.x = fmaxf((float)((((double)p0.x + (double)p1.x) + (double)p2.x) +
                      (double)p3.x + bv), 0.f);
  o.y = fmaxf((float)((((double)p0.y + (double)p1.y) + (double)p2.y) +
                      (double)p3.y + bv), 0.f);
  o.z = fmaxf((float)((((double)p0.z + (double)p1.z) + (double)p2.z) +
                      (double)p3.z + bv), 0.f);
  o.w = fmaxf((float)((((double)p0.w + (double)p1.w) + (double)p2.w) +
                      (double)p3.w + bv), 0.f);
  *(float4*)&g_h4[i4] = o;
}

// ---------------- head convs (reg 4ch + cls 21ch), stride1 pad1, split-K -------
__global__ void __launch_bounds__(256) k_head(const float* __restrict__ reg_w,
                                              const float* __restrict__ cls_w) {
  constexpr int IN_T = 34, ROWP = 35, NCH = 4;
  constexpr int ELEMS = NCH * IN_T * IN_T;
  constexpr int LD = (ELEMS + 255) / 256;
  const int split = blockIdx.x, co = blockIdx.y;
  const float* w = (co < 4) ? (reg_w + (size_t)co * 256 * 9)
                            : (cls_w + (size_t)(co - 4) * 256 * 9);
  __shared__ float s_in[NCH * IN_T * ROWP];
  __shared__ float s_w[32 * 9];
  const int t = threadIdx.x;

  int goff[LD], soff[LD];
#pragma unroll
  for (int i = 0; i < LD; ++i) {
    int idx = t + i * 256;
    int ch = idx / (IN_T * IN_T);
    int rem = idx - ch * (IN_T * IN_T);
    int r = rem / IN_T, c = rem - r * IN_T;
    int ih = r - 1, iw = c - 1;
    bool ok = (idx < ELEMS) && ((unsigned)ih < 32u) && ((unsigned)iw < 32u);
    goff[i] = ok ? (ch * 1024 + ih * 32 + iw) : -1;
    soff[i] = (ch * IN_T + r) * ROWP + c;
  }
  for (int idx = t; idx < 32 * 9; idx += 256)
    s_w[idx] = w[(size_t)(split * 32 + idx / 9) * 9 + (idx % 9)];

  float acc[4] = {0.f, 0.f, 0.f, 0.f};
  float cmp[4] = {0.f, 0.f, 0.f, 0.f};

  float rbuf[LD];
  {
    const float* inb = g_h4 + (size_t)split * 32 * 1024;
#pragma unroll
    for (int i = 0; i < LD; ++i) rbuf[i] = (goff[i] >= 0) ? inb[goff[i]] : 0.f;
  }
  for (int g = 0; g < 8; ++g) {
    __syncthreads();
#pragma unroll
    for (int i = 0; i < LD; ++i)
      if (t + i * 256 < ELEMS) s_in[soff[i]] = rbuf[i];
    if (g + 1 < 8) {
      const float* inb = g_h4 + (size_t)(split * 32 + (g + 1) * NCH) * 1024;
#pragma unroll
      for (int i = 0; i < LD; ++i)
        rbuf[i] = (goff[i] >= 0) ? inb[goff[i]] : 0.f;
    }
    __syncthreads();

#pragma unroll
    for (int cc = 0; cc < NCH; ++cc) {
      float wr[9];
#pragma unroll
      for (int k = 0; k < 9; ++k) wr[k] = s_w[(g * NCH + cc) * 9 + k];
#pragma unroll
      for (int px = 0; px < 4; ++px) {
        int p = t + px * 256;
        int oh = p >> 5, ow = p & 31;
        float a = 0.f;
#pragma unroll
        for (int kh = 0; kh < 3; ++kh)
#pragma unroll
          for (int kw = 0; kw < 3; ++kw)
            a = fmaf(s_in[(cc * IN_T + oh + kh) * ROWP + ow + kw],
                     wr[kh * 3 + kw], a);
        float y = a - cmp[px];
        float tt = acc[px] + y;
        cmp[px] = (tt - acc[px]) - y;
        acc[px] = tt;
      }
    }
  }
#pragma unroll
  for (int px = 0; px < 4; ++px)
    g_part[(size_t)(split * 25 + co) * 1024 + t + px * 256] = acc[px];
}

// ---------------- reduce partials (double) + transpose + softmax (double) ------
__global__ void k_prep(const float* __restrict__ reg_b,
                       const float* __restrict__ cls_b) {
  const int a = blockIdx.x * 256 + threadIdx.x;  // anchor 0..1023
#pragma unroll
  for (int j = 0; j < 4; ++j) {
    double s = 0.0;
    for (int sp = 0; sp < 8; ++sp)
      s += (double)g_part[(size_t)(sp * 25 + j) * 1024 + a];
    g_locs[a * 4 + j] = (float)(s + (double)reg_b[j]);
  }
  float conf[NCLS];
  for (int c = 0; c < NCLS; ++c) {
    double s = 0.0;
    for (int sp = 0; sp < 8; ++sp)
      s += (double)g_part[(size_t)(sp * 25 + 4 + c) * 1024 + a];
    conf[c] = (float)(s + (double)cls_b[c]);
    g_confs[a * NCLS + c] = conf[c];
  }
  float m = conf[0];
  int lab = 0;
  for (int c = 1; c < NCLS; ++c)
    if (conf[c] > m) { m = conf[c]; lab = c; }
  double sum = 0.0;
  for (int c = 0; c < NCLS; ++c) sum += exp((double)conf[c] - (double)m);
  g_scores[a] = (float)(1.0 / sum);  // max softmax prob
  g_labels[a] = lab;
}

// ---------------- stable bitonic sort by descending score ----------------
__global__ void k_sort() {
  __shared__ float s[1024];
  __shared__ int si[1024];
  const int t = threadIdx.x;
  s[t] = g_scores[t];
  si[t] = t;
  __syncthreads();
  for (int k = 2; k <= 1024; k <<= 1) {
    for (int j = k >> 1; j > 0; j >>= 1) {
      int ixj = t ^ j;
      if (ixj > t) {
        float sa = s[t], sb = s[ixj];
        int ia = si[t], ib = si[ixj];
        bool aFirst = (sa > sb) || (sa == sb && ia < ib);  // stable desc
        bool dirUp = ((t & k) == 0);
        if (dirUp ? !aFirst : aFirst) {
          s[t] = sb; s[ixj] = sa;
          si[t] = ib; si[ixj] = ia;
        }
      }
      __syncthreads();
    }
  }
  const int idx = si[t];
  g_order[t] = idx;
  g_sscore[t] = s[t];
  g_sbox[t] = make_float4(g_locs[idx * 4 + 0], g_locs[idx * 4 + 1],
                          g_locs[idx * 4 + 2], g_locs[idx * 4 + 3]);
  unsigned vb = __ballot_sync(0xffffffffu, s[t] > 0.04f);
  if ((t & 31) == 0) g_validmask[t >> 5] = vb;
}

// ---------------- pairwise IoU suppression bitmask (double precision) ----------
__global__ void k_iou() {
  const int i = blockIdx.x, j = threadIdx.x;
  float4 bi = g_sbox[i];
  float4 bj = g_sbox[j];
  double ai = ((double)bi.z - (double)bi.x) * ((double)bi.w - (double)bi.y);
  double aj = ((double)bj.z - (double)bj.x) * ((double)bj.w - (double)bj.y);
  double ltx = fmax((double)bi.x, (double)bj.x);
  double lty = fmax((double)bi.y, (double)bj.y);
  double rbx = fmin((double)bi.z, (double)bj.z);
  double rby = fmin((double)bi.w, (double)bj.w);
  double inter = fmax(rbx - ltx, 0.0) * fmax(rby - lty, 0.0);
  double uni = ai + aj - inter;
  double iou = inter / (uni + 1e-9);
  unsigned m = __ballot_sync(0xffffffffu, iou > 0.5);
  if ((j & 31) == 0) g_sup[i * 32 + (j >> 5)] = m;
}

// ---------------- sequential greedy NMS on bitmask, single warp ----------------
__global__ void k_nms() {
  const int lane = threadIdx.x;  // 32 threads
  unsigned kw = 0;
  const unsigned validw = g_validmask[lane];
  const int CH = 8;
  unsigned buf[CH], nbuf[CH];
#pragma unroll
  for (int q = 0; q < CH; ++q) buf[q] = g_sup[q * 32 + lane];
  for (int c = 0; c < 1024 / CH; ++c) {
    if (c + 1 < 1024 / CH) {
#pragma unroll
      for (int q = 0; q < CH; ++q)
        nbuf[q] = g_sup[((c + 1) * CH + q) * 32 + lane];
    }
#pragma unroll
    for (int q = 0; q < CH; ++q) {
      int i = c * CH + q;
      bool sup = __any_sync(0xffffffffu, (buf[q] & kw) != 0u);
      if (!sup && lane == (i >> 5)) {
        if ((validw >> (i & 31)) & 1u) kw |= (1u << (i & 31));
      }
    }
#pragma unroll
    for (int q = 0; q < CH; ++q) buf[q] = nbuf[q];
  }
  g_keepmask[lane] = kw;
}

// ---------------- masked gather to output ----------------
// layout (float32): boxes[1024*4] | labels[1024] | scores[1024] | confs[1024*21]
__global__ void k_out(float* __restrict__ out) {
  const int p = blockIdx.x * 256 + threadIdx.x;  // 0..1023
  const bool keep = (g_keepmask[p >> 5] >> (p & 31)) & 1u;
  const int idx = g_order[p];
  float4 b = g_sbox[p];
  out[p * 4 + 0] = keep ? b.x : -1.0f;
  out[p * 4 + 1] = keep ? b.y : -1.0f;
  out[p * 4 + 2] = keep ? b.z : -1.0f;
  out[p * 4 + 3] = keep ? b.w : -1.0f;
  out[4096 + p] = keep ? (float)g_labels[idx] : 0.0f;
  out[5120 + p] = keep ? g_sscore[p] : -1.0f;
  for (int c = 0; c < NCLS; ++c)
    out[6144 + p * NCLS + c] = keep ? g_confs[idx * NCLS + c] : -1.0f;
}

// ---------------- launch ----------------
extern "C" void kernel_launch(void* const* d_in, const int* in_sizes, int n_in,
                              void* d_out, int out_size) {
  const float* x = (const float*)d_in[0];
  const float* bb_w1 = (const float*)d_in[1];
  const float* bb_b1 = (const float*)d_in[2];
  const float* bb_w2 = (const float*)d_in[3];
  const float* bb_b2 = (const float*)d_in[4];
  const float* bb_w3 = (const float*)d_in[5];
  const float* bb_b3 = (const float*)d_in[6];
  const float* ex_w = (const float*)d_in[7];
  const float* ex_b = (const float*)d_in[8];
  const float* reg_w = (const float*)d_in[9];
  const float* reg_b = (const float*)d_in[10];
  const float* cls_w = (const float*)d_in[11];
  const float* cls_b = (const float*)d_in[12];

  cudaFuncSetAttribute(k_conv2, cudaFuncAttributeMaxDynamicSharedMemorySize,
                       CW_SMEM);
  cudaFuncSetAttribute(k_conv3, cudaFuncAttributeMaxDynamicSharedMemorySize,
                       CW_SMEM);
  cudaFuncSetAttribute(k_ex, cudaFuncAttributeMaxDynamicSharedMemorySize,
                       CW_SMEM);

  // only batch element 7 affects the output
  const float* x7 = x + (size_t)7 * 3 * 512 * 512;

  k_conv1<<<dim3(8, 16, 8), 256>>>(x7, bb_w1, bb_b1);
  k_conv2<<<dim3(4, 8, 16), 256, CW_SMEM>>>(bb_w2, bb_b2);
  k_conv3<<<dim3(2, 4, 64), 256, CW_SMEM>>>(bb_w3);
  k_comb3<<<1024, 256>>>(bb_b3);
  k_ex<<<dim3(1, 2, 128), 256, CW_SMEM>>>(ex_w);
  k_combex<<<256, 256>>>(ex_b);
  k_head<<<dim3(8, 25), 256>>>(reg_w, cls_w);
  k_prep<<<4, 256>>>(reg_b, cls_b);
  k_sort<<<1, 1024>>>();
  k_iou<<<1024, 1024>>>();
  k_nms<<<1, 32>>>();
  k_out<<<4, 256>>>((float*)d_out);
}

// round 13
// speedup vs baseline: 1.6573x; 1.2355x over previous
#include <cuda_runtime.h>
#include <math.h>

#define NCLS 21

// ---------------- f32x2 packed helpers (Blackwell; ptxas never auto-emits) ----
__device__ __forceinline__ unsigned long long f2_fma(unsigned long long a,
                                                     unsigned long long b,
                                                     unsigned long long c) {
  unsigned long long d;
  asm("fma.rn.f32x2 %0, %1, %2, %3;" : "=l"(d) : "l"(a), "l"(b), "l"(c));
  return d;
}
__device__ __forceinline__ unsigned long long f2_add(unsigned long long a,
                                                     unsigned long long b) {
  unsigned long long d;
  asm("add.rn.f32x2 %0, %1, %2;" : "=l"(d) : "l"(a), "l"(b));
  return d;
}
__device__ __forceinline__ unsigned long long f2_bcast(float x) {
  unsigned long long d;
  asm("mov.b64 %0, {%1, %1};" : "=l"(d) : "f"(x));
  return d;
}
__device__ __forceinline__ void f2_unpack(unsigned long long v, float& lo,
                                          float& hi) {
  asm("mov.b64 {%0, %1}, %2;" : "=f"(lo), "=f"(hi) : "l"(v));
}
#define F2_NEG1 0xBF800000BF800000ULL  // (-1.0f, -1.0f)

// ---------------- cp.async helpers ----------------
__device__ __forceinline__ void cp16(unsigned dst, const void* src,
                                     int srcsize) {
  asm volatile("cp.async.cg.shared.global [%0], [%1], 16, %2;" ::"r"(dst),
               "l"(src), "r"(srcsize));
}
__device__ __forceinline__ void cp_commit() {
  asm volatile("cp.async.commit_group;");
}
__device__ __forceinline__ void cp_wait_all() {
  asm volatile("cp.async.wait_group 0;");
}

// ---------------- scratch (static device globals; no allocation) ----------------
__device__ float g_h1[64 * 256 * 256];    // conv1 out
__device__ float g_h2[128 * 128 * 128];   // conv2 out
__device__ float g_h3[256 * 64 * 64];     // conv3 out
__device__ float g_h4[256 * 32 * 32];     // ex out
__device__ float g_expart[4 * 256 * 32 * 32];  // ex split-C partials
__device__ float g_part[8 * 25 * 1024];   // head conv split-K partials
__device__ float g_locs[1024 * 4];
__device__ float g_confs[1024 * NCLS];
__device__ float g_scores[1024];
__device__ int g_labels[1024];
__device__ int g_order[1024];
__device__ float4 g_sbox[1024];
__device__ float g_sscore[1024];
__device__ unsigned g_validmask[32];
__device__ unsigned g_sup[1024 * 32];
__device__ unsigned g_keepmask[32];

// ================= conv1: 3->64ch, 512->256, stride2 (R11-proven) =============
__global__ void __launch_bounds__(256) k_conv1(const float* __restrict__ x,
                                               const float* __restrict__ w,
                                               const float* __restrict__ b) {
  constexpr int IN_H = 34, ROWP = 68, IN_W4 = 17;
  constexpr int CHE4 = IN_H * IN_W4;  // 578
  constexpr int ELEMS4 = 3 * CHE4;    // 1734
  constexpr int LD4 = 7;
  __shared__ __align__(16) float s_in[3 * IN_H * ROWP];
  __shared__ __align__(16) float s_w[3 * 9 * 8];

  const int t = threadIdx.x;
  const int tx = t & 15, ty = t >> 4;
  const int ow0 = blockIdx.x * 32, oh0 = blockIdx.y * 16;
  const int co0 = blockIdx.z * 8;

  if (t < 216) {
    int co = t / 27, rem = t - co * 27;
    s_w[rem * 8 + co] = w[(size_t)(co0 + co) * 27 + rem];
  }
#pragma unroll
  for (int i = 0; i < LD4; ++i) {
    int idx = t + i * 256;
    if (idx < ELEMS4) {
      int ch = idx / CHE4, rem = idx - ch * CHE4;
      int r = rem / IN_W4, c4 = rem - r * IN_W4;
      int ih = oh0 * 2 + r, iw = ow0 * 2 + c4 * 4;
      float4 v = make_float4(0.f, 0.f, 0.f, 0.f);
      if (ih < 512 && iw < 512)
        v = *(const float4*)(x + (size_t)ch * 512 * 512 + ih * 512 + iw);
      *(float4*)&s_in[(ch * IN_H + r) * ROWP + c4 * 4] = v;
    }
  }
  __syncthreads();

  unsigned long long acc2[8], cmp2[8];
#pragma unroll
  for (int i = 0; i < 8; ++i) { acc2[i] = 0ull; cmp2[i] = 0ull; }

#pragma unroll
  for (int ch = 0; ch < 3; ++ch) {
    unsigned long long wsA[4] = {0ull, 0ull, 0ull, 0ull};
    unsigned long long wsB[4] = {0ull, 0ull, 0ull, 0ull};
#pragma unroll
    for (int kh = 0; kh < 3; ++kh) {
      const int rbase = (ch * IN_H + ty * 2 + kh) * ROWP + tx * 4;
      float4 xr = *(const float4*)&s_in[rbase];
      float x4v = s_in[rbase + 4];
      float x0s[3] = {xr.x, xr.y, xr.z};
      float x1s[3] = {xr.z, xr.w, x4v};
#pragma unroll
      for (int kw = 0; kw < 3; ++kw) {
        unsigned long long x0 = f2_bcast(x0s[kw]);
        unsigned long long x1 = f2_bcast(x1s[kw]);
        const ulonglong2* wp = (const ulonglong2*)&s_w[(ch * 9 + kh * 3 + kw) * 8];
        ulonglong2 wa = wp[0], wb = wp[1];
        wsA[0] = f2_fma(x0, wa.x, wsA[0]);
        wsA[1] = f2_fma(x0, wa.y, wsA[1]);
        wsA[2] = f2_fma(x0, wb.x, wsA[2]);
        wsA[3] = f2_fma(x0, wb.y, wsA[3]);
        wsB[0] = f2_fma(x1, wa.x, wsB[0]);
        wsB[1] = f2_fma(x1, wa.y, wsB[1]);
        wsB[2] = f2_fma(x1, wb.x, wsB[2]);
        wsB[3] = f2_fma(x1, wb.y, wsB[3]);
      }
    }
#pragma unroll
    for (int i = 0; i < 4; ++i) {
      unsigned long long y = f2_fma(cmp2[i], F2_NEG1, wsA[i]);
      unsigned long long tt = f2_add(acc2[i], y);
      unsigned long long t2 = f2_fma(acc2[i], F2_NEG1, tt);
      cmp2[i] = f2_fma(y, F2_NEG1, t2);
      acc2[i] = tt;
    }
#pragma unroll
    for (int i = 0; i < 4; ++i) {
      unsigned long long y = f2_fma(cmp2[4 + i], F2_NEG1, wsB[i]);
      unsigned long long tt = f2_add(acc2[4 + i], y);
      unsigned long long t2 = f2_fma(acc2[4 + i], F2_NEG1, tt);
      cmp2[4 + i] = f2_fma(y, F2_NEG1, t2);
      acc2[4 + i] = tt;
    }
  }

  const int oh = oh0 + ty;
  const int ow = ow0 + tx * 2;
#pragma unroll
  for (int px = 0; px < 2; ++px) {
#pragma unroll
    for (int i = 0; i < 4; ++i) {
      float lo, hi;
      f2_unpack(acc2[px * 4 + i], lo, hi);
      lo = fmaxf(lo + b[co0 + 2 * i], 0.f);
      hi = fmaxf(hi + b[co0 + 2 * i + 1], 0.f);
      g_h1[(size_t)(co0 + 2 * i) * 65536 + (size_t)oh * 256 + ow + px] = lo;
      g_h1[(size_t)(co0 + 2 * i + 1) * 65536 + (size_t)oh * 256 + ow + px] = hi;
    }
  }
}

// ============= wide conv: 32x16 tile, 2 horizontal px/thread, 8 couts ========
// cp.async double-buffered, one barrier per 4-channel group, 36-term chains +
// one Kahan fold per group (R12-proven). NCHUNKS chunks of 32 channels.
template <int CINFULL, int NCHUNKS, bool FINAL>
__device__ __forceinline__ void conv_wide(const float* __restrict__ in,
                                          const float* __restrict__ wgt,
                                          const float* __restrict__ bias,
                                          float* __restrict__ out, int Hin,
                                          int Win, int Hout, int Wout,
                                          int c_begin, int co0) {
  constexpr int WCH = 32, NCH = 4;
  constexpr int IN_H = 34, ROWP = 68;
  constexpr int IN_W4 = 17;
  constexpr int CHE4 = IN_H * IN_W4;
  constexpr int ELEMS4 = NCH * CHE4;
  constexpr int LD4 = (ELEMS4 + 255) / 256;
  constexpr int G = WCH / NCH;
  constexpr int BUFSZ = NCH * IN_H * ROWP;

  extern __shared__ float smem_dyn[];
  float* s_in = smem_dyn;
  float* s_w = smem_dyn + 2 * BUFSZ;

  const int t = threadIdx.x;
  const int tx = t & 15, ty = t >> 4;
  const int ow0 = blockIdx.x * 32, oh0 = blockIdx.y * 16;
  const int HW = Hin * Win;

  int goff4[LD4], soff4[LD4];
#pragma unroll
  for (int i = 0; i < LD4; ++i) {
    int idx = t + i * 256;
    int ch = idx / CHE4;
    int rem = idx - ch * CHE4;
    int r = rem / IN_W4, c4 = rem - r * IN_W4;
    int ih = oh0 * 2 + r, iw = ow0 * 2 + c4 * 4;
    bool slot = (idx < ELEMS4);
    bool ok = slot && ((unsigned)ih < (unsigned)Hin) &&
              ((unsigned)iw < (unsigned)Win);
    goff4[i] = ok ? (ch * HW + ih * Win + iw) : -1;
    soff4[i] = slot ? ((ch * IN_H + r) * ROWP + c4 * 4) : -1;
  }

  unsigned long long acc2[8], cmp2[8];
#pragma unroll
  for (int i = 0; i < 8; ++i) { acc2[i] = 0ull; cmp2[i] = 0ull; }

  for (int chunk = 0; chunk < NCHUNKS; ++chunk) {
    const int c0 = c_begin + chunk * WCH;
    __syncthreads();
#pragma unroll
    for (int i = 0; i < 9; ++i) {
      int idx = t + i * 256;
      int co = idx / (WCH * 9);
      int rem = idx - co * (WCH * 9);
      int ccg = rem / 9, k = rem - ccg * 9;
      s_w[(ccg * 9 + k) * 8 + co] =
          wgt[(size_t)(co0 + co) * CINFULL * 9 + (size_t)(c0 + ccg) * 9 + k];
    }
    {
      const float* inb = in + (size_t)c0 * HW;
      unsigned bufb = (unsigned)__cvta_generic_to_shared(s_in);
#pragma unroll
      for (int i = 0; i < LD4; ++i)
        if (soff4[i] >= 0)
          cp16(bufb + (unsigned)soff4[i] * 4,
               inb + (goff4[i] >= 0 ? goff4[i] : 0), goff4[i] >= 0 ? 16 : 0);
      cp_commit();
    }
    for (int g = 0; g < G; ++g) {
      cp_wait_all();
      __syncthreads();
      if (g + 1 < G) {
        const float* inb = in + (size_t)(c0 + (g + 1) * NCH) * HW;
        unsigned bufb = (unsigned)__cvta_generic_to_shared(
            s_in + ((g + 1) & 1) * BUFSZ);
#pragma unroll
        for (int i = 0; i < LD4; ++i)
          if (soff4[i] >= 0)
            cp16(bufb + (unsigned)soff4[i] * 4,
                 inb + (goff4[i] >= 0 ? goff4[i] : 0), goff4[i] >= 0 ? 16 : 0);
        cp_commit();
      }
      const float* buf = s_in + (g & 1) * BUFSZ;

      unsigned long long wsA[4] = {0ull, 0ull, 0ull, 0ull};
      unsigned long long wsB[4] = {0ull, 0ull, 0ull, 0ull};
#pragma unroll
      for (int chl = 0; chl < NCH; ++chl) {
#pragma unroll
        for (int kh = 0; kh < 3; ++kh) {
          const int rbase = (chl * IN_H + ty * 2 + kh) * ROWP + tx * 4;
          float4 xr = *(const float4*)&buf[rbase];
          float x4v = buf[rbase + 4];
          float x0s[3] = {xr.x, xr.y, xr.z};
          float x1s[3] = {xr.z, xr.w, x4v};
#pragma unroll
          for (int kw = 0; kw < 3; ++kw) {
            unsigned long long x0 = f2_bcast(x0s[kw]);
            unsigned long long x1 = f2_bcast(x1s[kw]);
            const ulonglong2* wp =
                (const ulonglong2*)&s_w[((g * NCH + chl) * 9 + kh * 3 + kw) *
                                        8];
            ulonglong2 wa = wp[0], wb = wp[1];
            wsA[0] = f2_fma(x0, wa.x, wsA[0]);
            wsA[1] = f2_fma(x0, wa.y, wsA[1]);
            wsA[2] = f2_fma(x0, wb.x, wsA[2]);
            wsA[3] = f2_fma(x0, wb.y, wsA[3]);
            wsB[0] = f2_fma(x1, wa.x, wsB[0]);
            wsB[1] = f2_fma(x1, wa.y, wsB[1]);
            wsB[2] = f2_fma(x1, wb.x, wsB[2]);
            wsB[3] = f2_fma(x1, wb.y, wsB[3]);
          }
        }
      }
#pragma unroll
      for (int i = 0; i < 4; ++i) {
        unsigned long long y = f2_fma(cmp2[i], F2_NEG1, wsA[i]);
        unsigned long long tt = f2_add(acc2[i], y);
        unsigned long long t2 = f2_fma(acc2[i], F2_NEG1, tt);
        cmp2[i] = f2_fma(y, F2_NEG1, t2);
        acc2[i] = tt;
      }
#pragma unroll
      for (int i = 0; i < 4; ++i) {
        unsigned long long y = f2_fma(cmp2[4 + i], F2_NEG1, wsB[i]);
        unsigned long long tt = f2_add(acc2[4 + i], y);
        unsigned long long t2 = f2_fma(acc2[4 + i], F2_NEG1, tt);
        cmp2[4 + i] = f2_fma(y, F2_NEG1, t2);
        acc2[4 + i] = tt;
      }
    }
  }

  const int oh = oh0 + ty;
  const int ow = ow0 + tx * 2;
#pragma unroll
  for (int px = 0; px < 2; ++px) {
#pragma unroll
    for (int i = 0; i < 4; ++i) {
      float lo, hi;
      f2_unpack(acc2[px * 4 + i], lo, hi);
      if (FINAL) {
        lo = fmaxf(lo + bias[co0 + 2 * i], 0.f);
        hi = fmaxf(hi + bias[co0 + 2 * i + 1], 0.f);
      }
      out[(size_t)(co0 + 2 * i) * Hout * Wout + (size_t)oh * Wout + ow + px] =
          lo;
      out[(size_t)(co0 + 2 * i + 1) * Hout * Wout + (size_t)oh * Wout + ow +
          px] = hi;
    }
  }
}

static const int CW_SMEM = (2 * 4 * 34 * 68 + 32 * 9 * 8) * 4;  // 83200 B

__global__ void __launch_bounds__(256, 2) k_conv2(const float* w,
                                                  const float* b) {
  conv_wide<64, 2, true>(g_h1, w, b, g_h2, 256, 256, 128, 128, 0,
                         blockIdx.z * 8);
}
// conv3: UNSPLIT (4 chunks of 32 ch) — writes bias+relu directly, no combine.
__global__ void __launch_bounds__(256, 2) k_conv3(const float* w,
                                                  const float* b) {
  conv_wide<128, 4, true>(g_h2, w, b, g_h3, 128, 128, 64, 64, 0,
                          blockIdx.z * 8);
}
// ex: split-C x4 (z = split*32 + co_blk), fp64 combine kept.
__global__ void __launch_bounds__(256, 2) k_ex(const float* w) {
  const int split = blockIdx.z >> 5;
  const int co0 = (blockIdx.z & 31) * 8;
  conv_wide<256, 2, false>(g_h3, w, nullptr,
                           g_expart + (size_t)split * 256 * 32 * 32, 64, 64,
                           32, 32, split * 64, co0);
}
__global__ void k_combex(const float* __restrict__ b) {
  const int i4 = (blockIdx.x * 256 + threadIdx.x) * 4;
  const int co = i4 >> 10;
  const double bv = (double)b[co];
  float4 p0 = *(const float4*)&g_expart[i4];
  float4 p1 = *(const float4*)&g_expart[262144 + i4];
  float4 p2 = *(const float4*)&g_expart[2 * 262144 + i4];
  float4 p3 = *(const float4*)&g_expart[3 * 262144 + i4];
  float4 o;
  o.x = fmaxf((float)((((double)p0.x + (double)p1.x) + (double)p2.x) +
                      (double)p3.x + bv), 0.f);
  o.y = fmaxf((float)((((double)p0.y + (double)p1.y) + (double)p2.y) +
                      (double)p3.y + bv), 0.f);
  o.z = fmaxf((float)((((double)p0.z + (double)p1.z) + (double)p2.z) +
                      (double)p3.z + bv), 0.f);
  o.w = fmaxf((float)((((double)p0.w + (double)p1.w) + (double)p2.w) +
                      (double)p3.w + bv), 0.f);
  *(float4*)&g_h4[i4] = o;
}

// ---------------- head convs (reg 4ch + cls 21ch), stride1 pad1, split-K -------
__global__ void __launch_bounds__(256) k_head(const float* __restrict__ reg_w,
                                              const float* __restrict__ cls_w) {
  constexpr int IN_T = 34, ROWP = 35, NCH = 4;
  constexpr int ELEMS = NCH * IN_T * IN_T;
  constexpr int LD = (ELEMS + 255) / 256;
  const int split = blockIdx.x, co = blockIdx.y;
  const float* w = (co < 4) ? (reg_w + (size_t)co * 256 * 9)
                            : (cls_w + (size_t)(co - 4) * 256 * 9);
  __shared__ float s_in[NCH * IN_T * ROWP];
  __shared__ float s_w[32 * 9];
  const int t = threadIdx.x;

  int goff[LD], soff[LD];
#pragma unroll
  for (int i = 0; i < LD; ++i) {
    int idx = t + i * 256;
    int ch = idx / (IN_T * IN_T);
    int rem = idx - ch * (IN_T * IN_T);
    int r = rem / IN_T, c = rem - r * IN_T;
    int ih = r - 1, iw = c - 1;
    bool ok = (idx < ELEMS) && ((unsigned)ih < 32u) && ((unsigned)iw < 32u);
    goff[i] = ok ? (ch * 1024 + ih * 32 + iw) : -1;
    soff[i] = (ch * IN_T + r) * ROWP + c;
  }
  for (int idx = t; idx < 32 * 9; idx += 256)
    s_w[idx] = w[(size_t)(split * 32 + idx / 9) * 9 + (idx % 9)];

  float acc[4] = {0.f, 0.f, 0.f, 0.f};
  float cmp[4] = {0.f, 0.f, 0.f, 0.f};

  float rbuf[LD];
  {
    const float* inb = g_h4 + (size_t)split * 32 * 1024;
#pragma unroll
    for (int i = 0; i < LD; ++i) rbuf[i] = (goff[i] >= 0) ? inb[goff[i]] : 0.f;
  }
  for (int g = 0; g < 8; ++g) {
    __syncthreads();
#pragma unroll
    for (int i = 0; i < LD; ++i)
      if (t + i * 256 < ELEMS) s_in[soff[i]] = rbuf[i];
    if (g + 1 < 8) {
      const float* inb = g_h4 + (size_t)(split * 32 + (g + 1) * NCH) * 1024;
#pragma unroll
      for (int i = 0; i < LD; ++i)
        rbuf[i] = (goff[i] >= 0) ? inb[goff[i]] : 0.f;
    }
    __syncthreads();

#pragma unroll
    for (int cc = 0; cc < NCH; ++cc) {
      float wr[9];
#pragma unroll
      for (int k = 0; k < 9; ++k) wr[k] = s_w[(g * NCH + cc) * 9 + k];
#pragma unroll
      for (int px = 0; px < 4; ++px) {
        int p = t + px * 256;
        int oh = p >> 5, ow = p & 31;
        float a = 0.f;
#pragma unroll
        for (int kh = 0; kh < 3; ++kh)
#pragma unroll
          for (int kw = 0; kw < 3; ++kw)
            a = fmaf(s_in[(cc * IN_T + oh + kh) * ROWP + ow + kw],
                     wr[kh * 3 + kw], a);
        float y = a - cmp[px];
        float tt = acc[px] + y;
        cmp[px] = (tt - acc[px]) - y;
        acc[px] = tt;
      }
    }
  }
#pragma unroll
  for (int px = 0; px < 4; ++px)
    g_part[(size_t)(split * 25 + co) * 1024 + t + px * 256] = acc[px];
}

// ---------------- reduce partials (double) + transpose + softmax (double) ------
__global__ void k_prep(const float* __restrict__ reg_b,
                       const float* __restrict__ cls_b) {
  const int a = blockIdx.x * 256 + threadIdx.x;  // anchor 0..1023
#pragma unroll
  for (int j = 0; j < 4; ++j) {
    double s = 0.0;
    for (int sp = 0; sp < 8; ++sp)
      s += (double)g_part[(size_t)(sp * 25 + j) * 1024 + a];
    g_locs[a * 4 + j] = (float)(s + (double)reg_b[j]);
  }
  float conf[NCLS];
  for (int c = 0; c < NCLS; ++c) {
    double s = 0.0;
    for (int sp = 0; sp < 8; ++sp)
      s += (double)g_part[(size_t)(sp * 25 + 4 + c) * 1024 + a];
    conf[c] = (float)(s + (double)cls_b[c]);
    g_confs[a * NCLS + c] = conf[c];
  }
  float m = conf[0];
  int lab = 0;
  for (int c = 1; c < NCLS; ++c)
    if (conf[c] > m) { m = conf[c]; lab = c; }
  double sum = 0.0;
  for (int c = 0; c < NCLS; ++c) sum += exp((double)conf[c] - (double)m);
  g_scores[a] = (float)(1.0 / sum);  // max softmax prob
  g_labels[a] = lab;
}

// ---------------- stable bitonic sort by descending score ----------------
__global__ void k_sort() {
  __shared__ float s[1024];
  __shared__ int si[1024];
  const int t = threadIdx.x;
  s[t] = g_scores[t];
  si[t] = t;
  __syncthreads();
  for (int k = 2; k <= 1024; k <<= 1) {
    for (int j = k >> 1; j > 0; j >>= 1) {
      int ixj = t ^ j;
      if (ixj > t) {
        float sa = s[t], sb = s[ixj];
        int ia = si[t], ib = si[ixj];
        bool aFirst = (sa > sb) || (sa == sb && ia < ib);  // stable desc
        bool dirUp = ((t & k) == 0);
        if (dirUp ? !aFirst : aFirst) {
          s[t] = sb; s[ixj] = sa;
          si[t] = ib; si[ixj] = ia;
        }
      }
      __syncthreads();
    }
  }
  const int idx = si[t];
  g_order[t] = idx;
  g_sscore[t] = s[t];
  g_sbox[t] = make_float4(g_locs[idx * 4 + 0], g_locs[idx * 4 + 1],
                          g_locs[idx * 4 + 2], g_locs[idx * 4 + 3]);
  unsigned vb = __ballot_sync(0xffffffffu, s[t] > 0.04f);
  if ((t & 31) == 0) g_validmask[t >> 5] = vb;
}

// ---------------- pairwise IoU suppression bitmask ----------------
// fp32 fast path; fp64 recompute only when |iou32 - 0.5| < 1e-4 (keeps the
// decision identical to the proven fp64 version wherever there's ambiguity).
__global__ void k_iou() {
  const int i = blockIdx.x, j = threadIdx.x;
  float4 bi = g_sbox[i];
  float4 bj = g_sbox[j];
  float ai = (bi.z - bi.x) * (bi.w - bi.y);
  float aj = (bj.z - bj.x) * (bj.w - bj.y);
  float ltx = fmaxf(bi.x, bj.x), lty = fmaxf(bi.y, bj.y);
  float rbx = fminf(bi.z, bj.z), rby = fminf(bi.w, bj.w);
  float inter = fmaxf(rbx - ltx, 0.f) * fmaxf(rby - lty, 0.f);
  float uni = ai + aj - inter;
  float iou = inter / (uni + 1e-9f);
  bool dec;
  if (fabsf(iou - 0.5f) > 1e-4f) {
    dec = iou > 0.5f;
  } else {  // rare: resolve at fp64 (same math as the proven version)
    double dai = ((double)bi.z - (double)bi.x) * ((double)bi.w - (double)bi.y);
    double daj = ((double)bj.z - (double)bj.x) * ((double)bj.w - (double)bj.y);
    double dlx = fmax((double)bi.x, (double)bj.x);
    double dly = fmax((double)bi.y, (double)bj.y);
    double drx = fmin((double)bi.z, (double)bj.z);
    double dry = fmin((double)bi.w, (double)bj.w);
    double din = fmax(drx - dlx, 0.0) * fmax(dry - dly, 0.0);
    double dio = din / (dai + daj - din + 1e-9);
    dec = dio > 0.5;
  }
  unsigned m = __ballot_sync(0xffffffffu, dec);
  if ((j & 31) == 0) g_sup[i * 32 + (j >> 5)] = m;
}

// ---------------- sequential greedy NMS on bitmask, single warp ----------------
__global__ void k_nms() {
  const int lane = threadIdx.x;  // 32 threads
  unsigned kw = 0;
  const unsigned validw = g_validmask[lane];
  const int CH = 8;
  unsigned buf[CH], nbuf[CH];
#pragma unroll
  for (int q = 0; q < CH; ++q) buf[q] = g_sup[q * 32 + lane];
  for (int c = 0; c < 1024 / CH; ++c) {
    if (c + 1 < 1024 / CH) {
#pragma unroll
      for (int q = 0; q < CH; ++q)
        nbuf[q] = g_sup[((c + 1) * CH + q) * 32 + lane];
    }
#pragma unroll
    for (int q = 0; q < CH; ++q) {
      int i = c * CH + q;
      bool sup = __any_sync(0xffffffffu, (buf[q] & kw) != 0u);
      if (!sup && lane == (i >> 5)) {
        if ((validw >> (i & 31)) & 1u) kw |= (1u << (i & 31));
      }
    }
#pragma unroll
    for (int q = 0; q < CH; ++q) buf[q] = nbuf[q];
  }
  g_keepmask[lane] = kw;
}

// ---------------- masked gather to output ----------------
// layout (float32): boxes[1024*4] | labels[1024] | scores[1024] | confs[1024*21]
__global__ void k_out(float* __restrict__ out) {
  const int p = blockIdx.x * 256 + threadIdx.x;  // 0..1023
  const bool keep = (g_keepmask[p >> 5] >> (p & 31)) & 1u;
  const int idx = g_order[p];
  float4 b = g_sbox[p];
  out[p * 4 + 0] = keep ? b.x : -1.0f;
  out[p * 4 + 1] = keep ? b.y : -1.0f;
  out[p * 4 + 2] = keep ? b.z : -1.0f;
  out[p * 4 + 3] = keep ? b.w : -1.0f;
  out[4096 + p] = keep ? (float)g_labels[idx] : 0.0f;
  out[5120 + p] = keep ? g_sscore[p] : -1.0f;
  for (int c = 0; c < NCLS; ++c)
    out[6144 + p * NCLS + c] = keep ? g_confs[idx * NCLS + c] : -1.0f;
}

// ---------------- launch ----------------
extern "C" void kernel_launch(void* const* d_in, const int* in_sizes, int n_in,
                              void* d_out, int out_size) {
  const float* x = (const float*)d_in[0];
  const float* bb_w1 = (const float*)d_in[1];
  const float* bb_b1 = (const float*)d_in[2];
  const float* bb_w2 = (const float*)d_in[3];
  const float* bb_b2 = (const float*)d_in[4];
  const float* bb_w3 = (const float*)d_in[5];
  const float* bb_b3 = (const float*)d_in[6];
  const float* ex_w = (const float*)d_in[7];
  const float* ex_b = (const float*)d_in[8];
  const float* reg_w = (const float*)d_in[9];
  const float* reg_b = (const float*)d_in[10];
  const float* cls_w = (const float*)d_in[11];
  const float* cls_b = (const float*)d_in[12];

  cudaFuncSetAttribute(k_conv2, cudaFuncAttributeMaxDynamicSharedMemorySize,
                       CW_SMEM);
  cudaFuncSetAttribute(k_conv3, cudaFuncAttributeMaxDynamicSharedMemorySize,
                       CW_SMEM);
  cudaFuncSetAttribute(k_ex, cudaFuncAttributeMaxDynamicSharedMemorySize,
                       CW_SMEM);

  // only batch element 7 affects the output
  const float* x7 = x + (size_t)7 * 3 * 512 * 512;

  k_conv1<<<dim3(8, 16, 8), 256>>>(x7, bb_w1, bb_b1);
  k_conv2<<<dim3(4, 8, 16), 256, CW_SMEM>>>(bb_w2, bb_b2);
  k_conv3<<<dim3(2, 4, 32), 256, CW_SMEM>>>(bb_w3, bb_b3);
  k_ex<<<dim3(1, 2, 128), 256, CW_SMEM>>>(ex_w);
  k_combex<<<256, 256>>>(ex_b);
  k_head<<<dim3(8, 25), 256>>>(reg_w, cls_w);
  k_prep<<<4, 256>>>(reg_b, cls_b);
  k_sort<<<1, 1024>>>();
  k_iou<<<1024, 1024>>>();
  k_nms<<<1, 32>>>();
  k_out<<<4, 256>>>((float*)d_out);
}